// round 12
// baseline (speedup 1.0000x reference)
#include <cuda_runtime.h>
#include <cuda_fp16.h>
#include <math.h>
#include <stdint.h>

#define S_LEN 8192
#define HID 2048
#define QKV3 (3*HID)
#define QKVP 6272          // qkv (6144) + lr rows padded to 128
#define NHEADS 16
#define HDIM 128
#define NFW 4
#define FD 512
#define CHUNK 2048
#define FDFD (FD*FD)

// ---------------- fp32 scratch ----------------
static __device__ float g_qkv [(size_t)S_LEN*QKVP];
static __device__ float g_rq  [(size_t)S_LEN*HID];
static __device__ float g_rk  [(size_t)S_LEN*HID];
static __device__ float g_attn[(size_t)S_LEN*HID];
static __device__ float g_ofst[(size_t)NFW*S_LEN*FD];
static __device__ float g_lr  [(size_t)S_LEN*12];
static __device__ float g_rope[(size_t)S_LEN*128];
static __device__ float g_w0  [(size_t)NFW*FDFD];
static __device__ float g_w1  [(size_t)NFW*FDFD];
static __device__ float g_w2  [(size_t)NFW*FDFD];
static __device__ float g_pq  [(size_t)NFW*CHUNK*1024];   // [gq | hmq]
static __device__ float g_pk  [(size_t)NFW*CHUNK*1024];   // [gk | hmk]
static __device__ float g_dhid[(size_t)NFW*CHUNK*FD];
static __device__ float g_part[(size_t)48*FDFD];
// ---------------- fp16 GEMM operands ----------------
static __device__ __half h_hs  [(size_t)S_LEN*HID];
static __device__ __half h_qkvw[(size_t)QKVP*HID];
static __device__ __half h_opw [(size_t)HID*HID];
static __device__ __half h_x   [(size_t)S_LEN*HID];
static __device__ __half h_fq  [(size_t)NFW*S_LEN*FD];
static __device__ __half h_fk  [(size_t)NFW*S_LEN*FD];
static __device__ __half h_fv  [(size_t)NFW*S_LEN*FD];
static __device__ __half h_gq  [(size_t)NFW*CHUNK*FD];
static __device__ __half h_t0 [(size_t)NFW*CHUNK*FD];
static __device__ __half h_t1 [(size_t)NFW*CHUNK*FD];
static __device__ __half h_t2 [(size_t)NFW*CHUNK*FD];
static __device__ __half h_t3 [(size_t)NFW*CHUNK*FD];
static __device__ __half h_t4 [(size_t)NFW*CHUNK*FD];
static __device__ __half h_w02[(size_t)NFW*1024*FD];
static __device__ __half h_w1 [(size_t)NFW*FDFD];
static __device__ __half h_w1T[(size_t)NFW*FDFD];

// ---------------- helpers ----------------
__device__ __forceinline__ void mma16(float* c, const uint32_t* a, const uint32_t* b)
{
    asm volatile(
        "mma.sync.aligned.m16n8k16.row.col.f32.f16.f16.f32 "
        "{%0,%1,%2,%3}, {%4,%5,%6,%7}, {%8,%9}, {%0,%1,%2,%3};"
        : "+f"(c[0]), "+f"(c[1]), "+f"(c[2]), "+f"(c[3])
        : "r"(a[0]), "r"(a[1]), "r"(a[2]), "r"(a[3]), "r"(b[0]), "r"(b[1]));
}
__device__ __forceinline__ void ldsm4(uint32_t* r, uint32_t addr)
{
    asm volatile("ldmatrix.sync.aligned.m8n8.x4.shared.b16 {%0,%1,%2,%3}, [%4];"
                 : "=r"(r[0]), "=r"(r[1]), "=r"(r[2]), "=r"(r[3]) : "r"(addr));
}
__device__ __forceinline__ uint32_t smem_u32(const void* p)
{
    uint32_t a;
    asm("{ .reg .u64 t; cvta.to.shared.u64 t, %1; cvt.u32.u64 %0, t; }" : "=r"(a) : "l"(p));
    return a;
}
__device__ __forceinline__ void cp16(uint32_t d, const void* g)
{
    asm volatile("cp.async.cg.shared.global [%0], [%1], 16;" :: "r"(d), "l"(g));
}
#define CP_COMMIT() asm volatile("cp.async.commit_group;" ::: "memory")
#define CP_WAIT1()  asm volatile("cp.async.wait_group 1;" ::: "memory")
#define CP_WAIT0()  asm volatile("cp.async.wait_group 0;" ::: "memory")

// ---------------- fp16 tensor GEMM body (round-10 proven) ----------------
#define STGB 32768
#define GSMEM (3*STGB)

__device__ __forceinline__ void gemm_body(
    const __half* __restrict__ A, const __half* __restrict__ B, float* __restrict__ C,
    int Ks, int lda, int ldb, int ldc, __half* smh)
{
    const int m0 = blockIdx.y * 128, n0 = blockIdx.x * 128;
    const int tid = threadIdx.x, warp = tid >> 5, lane = tid & 31;
    const int wm = (warp >> 1) * 32, wn = (warp & 1) * 64;

    float acc[2][8][4];
    #pragma unroll
    for (int i = 0; i < 2; i++)
        #pragma unroll
        for (int j = 0; j < 8; j++)
            #pragma unroll
            for (int l = 0; l < 4; l++) acc[i][j][l] = 0.f;

    const int nst = Ks >> 6;
    const uint32_t smbase = smem_u32(smh);

    const int crow = tid >> 1;
    const int gb = (tid & 1) * 4;
    const __half* gA = A + (size_t)(m0 + crow) * lda + gb * 8;
    const __half* gB = B + (size_t)(n0 + crow) * ldb + gb * 8;
    const uint32_t wbase = (uint32_t)(crow * 128);
    const uint32_t wsw = (uint32_t)(crow & 7);

    #pragma unroll
    for (int s = 0; s < 2; s++) {
        uint32_t sa = smbase + s * STGB;
        #pragma unroll
        for (int i = 0; i < 4; i++) {
            uint32_t wo = wbase + (((uint32_t)(gb + i) ^ wsw) << 4);
            cp16(sa + wo,         gA + (s << 6) + i * 8);
            cp16(sa + 16384 + wo, gB + (s << 6) + i * 8);
        }
        CP_COMMIT();
    }

    const uint32_t sw = (uint32_t)(lane & 7);
    const uint32_t arowb = (uint32_t)((wm + (lane & 15)) * 128);
    const uint32_t browb = (uint32_t)((wn + ((lane >> 4) << 3) + (lane & 7)) * 128);
    const uint32_t agb = (uint32_t)(lane >> 4);
    const uint32_t bgb = (uint32_t)((lane >> 3) & 1);

    int st = 0;
    for (int s = 0; s < nst; s++) {
        if (s + 1 < nst) CP_WAIT1(); else CP_WAIT0();
        __syncthreads();
        if (s + 2 < nst) {
            uint32_t sa = smbase + ((s + 2) % 3) * STGB;
            #pragma unroll
            for (int i = 0; i < 4; i++) {
                uint32_t wo = wbase + (((uint32_t)(gb + i) ^ wsw) << 4);
                cp16(sa + wo,         gA + ((s + 2) << 6) + i * 8);
                cp16(sa + 16384 + wo, gB + ((s + 2) << 6) + i * 8);
            }
        }
        CP_COMMIT();
        const uint32_t sa = smbase + st * STGB;
        const uint32_t sb = sa + 16384;
        #pragma unroll
        for (int kt = 0; kt < 4; kt++) {
            const uint32_t axor = ((2 * kt + agb) ^ sw) << 4;
            const uint32_t bxor = ((2 * kt + bgb) ^ sw) << 4;
            uint32_t af[2][4];
            ldsm4(af[0], sa + arowb + axor);
            ldsm4(af[1], sa + arowb + 2048 + axor);
            #pragma unroll
            for (int p = 0; p < 4; p++) {
                uint32_t bf[4];
                ldsm4(bf, sb + browb + p * 2048 + bxor);
                mma16(acc[0][2 * p],     af[0], &bf[0]);
                mma16(acc[0][2 * p + 1], af[0], &bf[2]);
                mma16(acc[1][2 * p],     af[1], &bf[0]);
                mma16(acc[1][2 * p + 1], af[1], &bf[2]);
            }
        }
        st++; if (st == 3) st = 0;
    }

    const int gr = lane >> 2, gc = lane & 3;
    #pragma unroll
    for (int mt = 0; mt < 2; mt++) {
        #pragma unroll
        for (int nt = 0; nt < 8; nt++) {
            int row = m0 + wm + mt * 16 + gr;
            int col = n0 + wn + nt * 8 + 2 * gc;
            *(float2*)(C + (size_t)row * ldc + col) =
                make_float2(acc[mt][nt][0], acc[mt][nt][1]);
            *(float2*)(C + (size_t)(row + 8) * ldc + col) =
                make_float2(acc[mt][nt][2], acc[mt][nt][3]);
        }
    }
}

__global__ void __launch_bounds__(256, 2) mm_gen(
    const __half* __restrict__ A, const __half* __restrict__ B, float* __restrict__ C,
    int K, int lda, int ldb, int ldc, size_t sA, size_t sB, size_t sC)
{
    extern __shared__ __half smh[];
    int hh = blockIdx.z;
    gemm_body(A + sA * hh, B + sB * hh, C + sC * hh, K, lda, ldb, ldc, smh);
}

__global__ void __launch_bounds__(256, 2) mm_fwd(
    const __half* __restrict__ fq, const __half* __restrict__ fk,
    const __half* __restrict__ w02, float* __restrict__ pq, float* __restrict__ pk)
{
    extern __shared__ __half smh[];
    int z = blockIdx.z, which = z >> 2, hh = z & 3;
    const __half* A = (which ? fk : fq) + (size_t)hh * ((size_t)S_LEN * FD);
    const __half* B = w02 + (size_t)hh * (1024 * FD);
    float* C = (which ? pk : pq) + (size_t)hh * ((size_t)CHUNK * 1024);
    gemm_body(A, B, C, FD, FD, FD, 1024, smh);
}

__global__ void __launch_bounds__(256, 2) mm_upd(
    const __half* __restrict__ t0, const __half* __restrict__ t1,
    const __half* __restrict__ t3, const __half* __restrict__ t4,
    const __half* __restrict__ t2, float* __restrict__ part)
{
    extern __shared__ __half smh[];
    int z = blockIdx.z, mat = z >> 4, rem = z & 15, sl = rem >> 2, hh = rem & 3;
    const size_t sT = (size_t)FD * CHUNK;
    const __half* A = (mat == 0 ? t0 : mat == 1 ? t1 : t3) + (size_t)hh * sT + sl * (CHUNK / 4);
    const __half* B = (mat < 2 ? t4 : t2) + (size_t)hh * sT + sl * (CHUNK / 4);
    float* C = part + (size_t)z * FDFD;
    gemm_body(A, B, C, CHUNK / 4, CHUNK, CHUNK, FD, smh);
}

// ---------------- fused weight update + fp16 refresh ----------------
__global__ void __launch_bounds__(256) wupdate(
    float* __restrict__ w0, float* __restrict__ w1, float* __restrict__ w2,
    const float* __restrict__ part,
    __half* __restrict__ w02h, __half* __restrict__ w1h, __half* __restrict__ w1Th)
{
    __shared__ float t[32][33];
    int z = blockIdx.z, mat = z >> 2, h = z & 3;
    int c0 = blockIdx.x * 32, r0 = blockIdx.y * 32;
    int x = threadIdx.x, y = threadIdx.y;
    float* master = (mat == 0 ? w0 : mat == 1 ? w2 : w1) + (size_t)h * FDFD;
    const float* p = part + ((size_t)(mat * 16 + h)) * FDFD;
    #pragma unroll
    for (int i = 0; i < 4; i++) {
        int r = r0 + y + i * 8, c = c0 + x;
        size_t idx = (size_t)r * FD + c;
        float s = master[idx] + p[idx] + p[idx + (size_t)4 * FDFD]
                + p[idx + (size_t)8 * FDFD] + p[idx + (size_t)12 * FDFD];
        master[idx] = s;
        __half hv = __float2half(s);
        if (mat == 0)      w02h[(size_t)h * 1024 * FD + idx] = hv;
        else if (mat == 1) w02h[(size_t)h * 1024 * FD + (size_t)512 * FD + idx] = hv;
        else { w1h[(size_t)h * FDFD + idx] = hv; t[y + i * 8][x] = s; }
    }
    if (mat == 2) {
        __syncthreads();
        #pragma unroll
        for (int i = 0; i < 4; i++)
            w1Th[(size_t)h * FDFD + (size_t)(c0 + y + i * 8) * FD + r0 + x] =
                __float2half(t[x][y + i * 8]);
    }
}

// ---------------- converts ----------------
__global__ void __launch_bounds__(256) f2h(const float* __restrict__ s, __half* __restrict__ d, size_t n)
{
    size_t i = ((size_t)blockIdx.x * 256 + threadIdx.x) * 8;
    if (i >= n) return;
    float4 a = *(const float4*)(s + i), b = *(const float4*)(s + i + 4);
    __half2 q0 = __floats2half2_rn(a.x, a.y), q1 = __floats2half2_rn(a.z, a.w);
    __half2 q2 = __floats2half2_rn(b.x, b.y), q3 = __floats2half2_rn(b.z, b.w);
    uint4 u;
    u.x = *(uint32_t*)&q0; u.y = *(uint32_t*)&q1; u.z = *(uint32_t*)&q2; u.w = *(uint32_t*)&q3;
    *(uint4*)(d + i) = u;
}

// build padded qkv+lr weight: rows 0..6143 = qkv_w, 6144..6155 = lr_w, rest 0
__global__ void __launch_bounds__(256) qkvw_cvt(const float* __restrict__ qw,
                                                const float* __restrict__ lw,
                                                __half* __restrict__ dst)
{
    size_t i = ((size_t)blockIdx.x * 256 + threadIdx.x) * 8;   // over QKVP*HID
    int row = (int)(i >> 11);
    int col = (int)(i & 2047);
    float4 a = make_float4(0.f,0.f,0.f,0.f), b = a;
    if (row < QKV3) {
        const float* s = qw + (size_t)row * HID + col;
        a = *(const float4*)s; b = *(const float4*)(s + 4);
    } else if (row < QKV3 + 12) {
        const float* s = lw + (size_t)(row - QKV3) * HID + col;
        a = *(const float4*)s; b = *(const float4*)(s + 4);
    }
    __half2 q0 = __floats2half2_rn(a.x, a.y), q1 = __floats2half2_rn(a.z, a.w);
    __half2 q2 = __floats2half2_rn(b.x, b.y), q3 = __floats2half2_rn(b.z, b.w);
    uint4 u;
    u.x = *(uint32_t*)&q0; u.y = *(uint32_t*)&q1; u.z = *(uint32_t*)&q2; u.w = *(uint32_t*)&q3;
    *(uint4*)(dst + i) = u;
}

__global__ void __launch_bounds__(256) f2hw02(const float* __restrict__ w0, const float* __restrict__ w2,
                                              __half* __restrict__ dst)
{
    size_t i = ((size_t)blockIdx.x * 256 + threadIdx.x) * 8;
    int h = (int)(i >> 19);
    int r = (int)((i >> 9) & 1023);
    int c = (int)(i & 511);
    const float* src = (r < 512 ? w0 + ((size_t)h * FD + r) * FD
                                : w2 + ((size_t)h * FD + (r - 512)) * FD) + c;
    float4 a = *(const float4*)src, b = *(const float4*)(src + 4);
    __half2 q0 = __floats2half2_rn(a.x, a.y), q1 = __floats2half2_rn(a.z, a.w);
    __half2 q2 = __floats2half2_rn(b.x, b.y), q3 = __floats2half2_rn(b.z, b.w);
    uint4 u;
    u.x = *(uint32_t*)&q0; u.y = *(uint32_t*)&q1; u.z = *(uint32_t*)&q2; u.w = *(uint32_t*)&q3;
    *(uint4*)(dst + i) = u;
}

__global__ void __launch_bounds__(256) transpose_wh(const float* __restrict__ src, __half* __restrict__ dst)
{
    __shared__ float t[32][33];
    int h = blockIdx.z;
    int i0 = blockIdx.x * 32, j0 = blockIdx.y * 32;
    int x = threadIdx.x, y = threadIdx.y;
    const float* s = src + (size_t)h * FDFD;
    __half* d = dst + (size_t)h * FDFD;
    #pragma unroll
    for (int i = 0; i < 4; i++) t[y + i * 8][x] = s[(size_t)(j0 + y + i * 8) * FD + i0 + x];
    __syncthreads();
    #pragma unroll
    for (int i = 0; i < 4; i++) d[(size_t)(i0 + y + i * 8) * FD + j0 + x] = __float2half(t[x][y + i * 8]);
}

// ---------------- RoPE table (one-time) ----------------
__global__ void __launch_bounds__(256) rope_tab()
{
    int idx = blockIdx.x * 256 + threadIdx.x;   // over S_LEN*64
    int t = idx >> 6, i = idx & 63;
    float freq = (float)exp(-(double)i * (13.122363377404328 / 64.0));
    float sn, cs;
    sincosf((float)t * freq, &sn, &cs);
    g_rope[(size_t)t * 128 + i] = cs;
    g_rope[(size_t)t * 128 + 64 + i] = sn;
}

// ---------------- utils ----------------
__device__ __forceinline__ float blockReduceSum256(float v)
{
    __shared__ float red[8];
    #pragma unroll
    for (int o = 16; o > 0; o >>= 1) v += __shfl_xor_sync(0xffffffffu, v, o);
    if ((threadIdx.x & 31) == 0) red[threadIdx.x >> 5] = v;
    __syncthreads();
    if (threadIdx.x < 32) {
        float x = (threadIdx.x < 8) ? red[threadIdx.x] : 0.f;
        #pragma unroll
        for (int o = 4; o > 0; o >>= 1) x += __shfl_xor_sync(0xffffffffu, x, o);
        if (threadIdx.x == 0) red[0] = x;
    }
    __syncthreads();
    float r = red[0];
    __syncthreads();
    return r;
}
__device__ __forceinline__ float siluf(float x) { return x / (1.f + expf(-x)); }

// ---------------- per-token preprocess (lean) ----------------
__global__ void __launch_bounds__(256) preprocess_kernel(
    const float* __restrict__ qnw, const float* __restrict__ knw,
    const float* __restrict__ qksc, const float* __restrict__ qkof,
    const float* __restrict__ lrb)
{
    __shared__ float sq[HID];
    __shared__ float sk[HID];
    __shared__ float gsum[8];
    int t = blockIdx.x, tid = threadIdx.x;
    int lane = tid & 31;

    if (tid < 8) gsum[tid] = 0.f;

    const float* qrow = g_qkv + (size_t)t * QKVP;
    const float* krow = qrow + HID;
    const float* vrow = qrow + 2 * HID;

    float ssq = 0.f, ssk = 0.f;
    #pragma unroll
    for (int i = 0; i < 8; i++) {
        int d = i * 256 + tid;
        float a = qrow[d]; sq[d] = a; ssq += a * a;
        float b = krow[d]; sk[d] = b; ssk += b * b;
    }
    ssq = blockReduceSum256(ssq);
    ssk = blockReduceSum256(ssk);
    float rsq = rsqrtf(ssq * (1.f / HID) + 1e-6f);
    float rsk = rsqrtf(ssk * (1.f / HID) + 1e-6f);
    #pragma unroll
    for (int i = 0; i < 8; i++) {
        int d = i * 256 + tid;
        sq[d] = sq[d] * rsq * qnw[d];
        sk[d] = sk[d] * rsk * knw[d];
    }
    __syncthreads();
    // RoPE from precomputed table
    const float* rp = g_rope + (size_t)t * 128;
    #pragma unroll
    for (int j = 0; j < 4; j++) {
        int idx = j * 256 + tid;
        int hh = idx >> 6, i = idx & 63;
        float cs = rp[i], sn = rp[64 + i];
        int d1 = hh * HDIM + i, d2 = d1 + 64;
        float q1 = sq[d1], q2 = sq[d2], k1 = sk[d1], k2 = sk[d2];
        size_t base = (size_t)t * HID;
        g_rq[base + d1] = q1 * cs - q2 * sn;
        g_rq[base + d2] = q2 * cs + q1 * sn;
        g_rk[base + d1] = k1 * cs - k2 * sn;
        g_rk[base + d2] = k2 * cs + k1 * sn;
    }
    __syncthreads();
    // fast-weight inputs; gsum via warp-shuffle (iteration i -> group i>>1)
    #pragma unroll
    for (int i = 0; i < 8; i++) {
        int d = i * 256 + tid;
        float xq = sq[d] * qksc[2 * d]     + qkof[2 * d];
        float xk = sk[d] * qksc[2 * d + 1] + qkof[2 * d + 1];
        float a = siluf(xq), b = siluf(xk);
        sq[d] = a; sk[d] = b;
        float va = a * a, vb = b * b;
        #pragma unroll
        for (int o = 16; o > 0; o >>= 1) {
            va += __shfl_xor_sync(0xffffffffu, va, o);
            vb += __shfl_xor_sync(0xffffffffu, vb, o);
        }
        if (lane == 0) {
            atomicAdd(&gsum[i >> 1], va);
            atomicAdd(&gsum[4 + (i >> 1)], vb);
        }
        int g = d >> 9;
        h_fv[((size_t)g * S_LEN + t) * FD + (d & 511)] = __float2half(siluf(vrow[d]));
    }
    __syncthreads();
    #pragma unroll
    for (int i = 0; i < 8; i++) {
        int d = i * 256 + tid;
        int g = d >> 9;
        float nq = fmaxf(sqrtf(gsum[g]),     1e-12f);
        float nk = fmaxf(sqrtf(gsum[4 + g]), 1e-12f);
        size_t o = ((size_t)g * S_LEN + t) * FD + (d & 511);
        h_fq[o] = __float2half(sq[d] / nq);
        h_fk[o] = __float2half(sk[d] / nk);
    }
    // mamba LR from GEMM appendix columns
    if (tid < 12) {
        float z = qrow[3 * HID + tid] + lrb[tid] - 6.90725523731f;
        float sp = (z > 0.f) ? z + log1pf(expf(-z)) : log1pf(expf(z));
        g_lr[(size_t)t * 12 + tid] = sp;
    }
}

// ---------------- sliding-window attention ----------------
__global__ void __launch_bounds__(256) attn_kernel()
{
    extern __shared__ float sh[];
    float* sQ = sh;
    float* sK = sh + 4096;
    float* sV = sh + 8192;
    float* sP = sh + 12288;
    int head = blockIdx.y;
    int q0 = blockIdx.x * 32;
    int tid = threadIdx.x;
    int row = tid >> 3, sub = tid & 7;
    const float qs = 0.08838834764831845f;

    for (int i = tid; i < 32 * 32; i += 256) {
        int r = i >> 5, c4 = (i & 31) << 2;
        float4 v = *(const float4*)(g_rq + (size_t)(q0 + r) * HID + head * HDIM + c4);
        sQ[r*128+c4+0] = v.x*qs; sQ[r*128+c4+1] = v.y*qs;
        sQ[r*128+c4+2] = v.z*qs; sQ[r*128+c4+3] = v.w*qs;
    }

    float oacc[16];
    #pragma unroll
    for (int j = 0; j < 16; j++) oacc[j] = 0.f;
    float m = -1e30f, l = 0.f;
    int qpos = q0 + row;

    for (int it = 0; it < 9; it++) {
        int kb = q0 - 256 + it * 32;
        if (kb + 32 <= 0) continue;
        __syncthreads();
        for (int i = tid; i < 32 * 32; i += 256) {
            int r = i >> 5, c4 = (i & 31) << 2;
            int kpos = kb + r;
            float4 kv = make_float4(0.f,0.f,0.f,0.f), vv = kv;
            if (kpos >= 0) {
                kv = *(const float4*)(g_rk  + (size_t)kpos * HID  + head * HDIM + c4);
                vv = *(const float4*)(g_qkv + (size_t)kpos * QKVP + 2 * HID + head * HDIM + c4);
            }
            sK[r*128+c4+0]=kv.x; sK[r*128+c4+1]=kv.y; sK[r*128+c4+2]=kv.z; sK[r*128+c4+3]=kv.w;
            sV[r*128+c4+0]=vv.x; sV[r*128+c4+1]=vv.y; sV[r*128+c4+2]=vv.z; sV[r*128+c4+3]=vv.w;
        }
        __syncthreads();
        float s[4];
        bool ok[4];
        #pragma unroll
        for (int j = 0; j < 4; j++) {
            int kpos = kb + sub * 4 + j;
            ok[j] = (kpos >= 0) && (kpos <= qpos) && (kpos >= qpos - 255);
            s[j] = 0.f;
        }
        const float4* qp = (const float4*)(sQ + row * 128);
        #pragma unroll 8
        for (int d4 = 0; d4 < 32; d4++) {
            float4 a = qp[d4];
            #pragma unroll
            for (int j = 0; j < 4; j++) {
                float4 b = ((const float4*)(sK + (sub * 4 + j) * 128))[d4];
                s[j] += a.x*b.x + a.y*b.y + a.z*b.z + a.w*b.w;
            }
        }
        float tmax = -1e30f;
        #pragma unroll
        for (int j = 0; j < 4; j++) { if (!ok[j]) s[j] = -1e30f; tmax = fmaxf(tmax, s[j]); }
        #pragma unroll
        for (int o = 4; o > 0; o >>= 1) tmax = fmaxf(tmax, __shfl_xor_sync(0xffffffffu, tmax, o, 8));
        float mnew = fmaxf(m, tmax);
        float scale = expf(m - mnew);
        float p[4], ps = 0.f;
        #pragma unroll
        for (int j = 0; j < 4; j++) { p[j] = ok[j] ? expf(s[j] - mnew) : 0.f; ps += p[j]; }
        #pragma unroll
        for (int o = 4; o > 0; o >>= 1) ps += __shfl_xor_sync(0xffffffffu, ps, o, 8);
        l = l * scale + ps;
        m = mnew;
        #pragma unroll
        for (int j = 0; j < 16; j++) oacc[j] *= scale;
        #pragma unroll
        for (int j = 0; j < 4; j++) sP[row * 32 + sub * 4 + j] = p[j];
        __syncwarp();
        #pragma unroll 4
        for (int k = 0; k < 32; k++) {
            float pk = sP[row * 32 + k];
            const float4* vp = (const float4*)(sV + k * 128 + sub * 16);
            float4 v0 = vp[0], v1 = vp[1], v2 = vp[2], v3 = vp[3];
            oacc[0]  += pk*v0.x; oacc[1]  += pk*v0.y; oacc[2]  += pk*v0.z; oacc[3]  += pk*v0.w;
            oacc[4]  += pk*v1.x; oacc[5]  += pk*v1.y; oacc[6]  += pk*v1.z; oacc[7]  += pk*v1.w;
            oacc[8]  += pk*v2.x; oacc[9]  += pk*v2.y; oacc[10] += pk*v2.z; oacc[11] += pk*v2.w;
            oacc[12] += pk*v3.x; oacc[13] += pk*v3.y; oacc[14] += pk*v3.z; oacc[15] += pk*v3.w;
        }
    }
    float inv = 1.f / l;
    #pragma unroll
    for (int j = 0; j < 16; j++)
        g_attn[(size_t)qpos * HID + head * HDIM + sub * 16 + j] = oacc[j] * inv;
}

// ---------------- TTT elementwise + transposes ----------------
__global__ void __launch_bounds__(256) ttt_elem_t(int c0)
{
    __shared__ float t0[32][33], t1[32][33], t2[32][33], t3[32][33], t4[32][33];
    int h = blockIdx.z;
    int cb = blockIdx.x * 32, db = blockIdx.y * 32;
    int x = threadIdx.x, y = threadIdx.y;
    size_t base  = (size_t)h * CHUNK * FD;
    size_t baseP = (size_t)h * CHUNK * 1024;
    #pragma unroll
    for (int i = 0; i < 4; i++) {
        int cy = y + i * 8;
        int c = cb + cy, d = db + x;
        size_t idx  = base  + (size_t)c * FD + d;
        size_t idxP = baseP + (size_t)c * 1024 + d;
        int t = c0 + c;
        float lr0 = g_lr[(size_t)t * 12 + h];
        float lr1 = g_lr[(size_t)t * 12 + 4 + h];
        float lr2 = g_lr[(size_t)t * 12 + 8 + h];
        float gq = g_pq[idxP], hmq = g_pq[idxP + 512];
        h_gq[idx] = __float2half(siluf(gq) * hmq);
        float gk = g_pk[idxP], hmk = g_pk[idxP + 512], dh = g_dhid[idx];
        float sg = 1.f / (1.f + expf(-gk));
        float silug = gk * sg;
        t0[cy][x] = dh * hmk * (sg * (1.f + gk * (1.f - sg))) * lr0;
        t1[cy][x] = dh * silug * lr2;
        t2[cy][x] = silug * hmk;
        t3[cy][x] = __half2float(h_fv[((size_t)h * S_LEN + t) * FD + d]) * lr1;
        t4[cy][x] = __half2float(h_fk[((size_t)h * S_LEN + t) * FD + d]);
    }
    __syncthreads();
    size_t tb = ((size_t)h * FD + db) * CHUNK + cb;
    #pragma unroll
    for (int i = 0; i < 4; i++) {
        int dy = y + i * 8;
        size_t o = tb + (size_t)dy * CHUNK + x;
        h_t0[o] = __float2half(t0[x][dy]);
        h_t1[o] = __float2half(t1[x][dy]);
        h_t2[o] = __float2half(t2[x][dy]);
        h_t3[o] = __float2half(t3[x][dy]);
        h_t4[o] = __float2half(t4[x][dy]);
    }
}

// ---------------- rms_norm(o_fast) + attn add -> fp16 x ----------------
__global__ void __launch_bounds__(256) normadd_kernel(const float* __restrict__ tnw)
{
    __shared__ float ss[4];
    int t = blockIdx.x, tid = threadIdx.x;
    if (tid < 4) ss[tid] = 0.f;
    __syncthreads();
    float v[8];
    #pragma unroll
    for (int i = 0; i < 8; i++) {
        int d = i * 256 + tid;
        int h = d >> 9;
        float x = g_ofst[((size_t)h * S_LEN + t) * FD + (d & 511)];
        v[i] = x;
        float s = x * x;
        #pragma unroll
        for (int o = 16; o > 0; o >>= 1) s += __shfl_xor_sync(0xffffffffu, s, o);
        if ((tid & 31) == 0) atomicAdd(&ss[h], s);
    }
    __syncthreads();
    #pragma unroll
    for (int i = 0; i < 8; i++) {
        int d = i * 256 + tid;
        int h = d >> 9;
        float rn = rsqrtf(ss[h] * (1.f / FD) + 1e-6f);
        h_x[(size_t)t * HID + d] =
            __float2half(g_attn[(size_t)t * HID + d] + v[i] * rn * tnw[d & 511]);
    }
}

// ---------------- host ----------------
template<typename T>
static T* symaddr(const void* s)
{
    void* p = nullptr;
    cudaGetSymbolAddress(&p, s);
    return (T*)p;
}

extern "C" void kernel_launch(void* const* d_in, const int* in_sizes, int n_in,
                              void* d_out, int out_size)
{
    const float* hs    = (const float*)d_in[0];
    const float* qkv_w = (const float*)d_in[1];
    const float* qnw   = (const float*)d_in[2];
    const float* knw   = (const float*)d_in[3];
    const float* qksc  = (const float*)d_in[4];
    const float* qkof  = (const float*)d_in[5];
    const float* lrw   = (const float*)d_in[6];
    const float* lrb   = (const float*)d_in[7];
    const float* w0    = (const float*)d_in[8];
    const float* w1    = (const float*)d_in[9];
    const float* w2    = (const float*)d_in[10];
    const float* tnw   = (const float*)d_in[11];
    const float* opw   = (const float*)d_in[12];
    float* out = (float*)d_out;

    float*  p_qkv  = symaddr<float>(g_qkv);
    float*  p_ofst = symaddr<float>(g_ofst);
    float*  p_w0   = symaddr<float>(g_w0);
    float*  p_w1   = symaddr<float>(g_w1);
    float*  p_w2   = symaddr<float>(g_w2);
    float*  p_pq   = symaddr<float>(g_pq);
    float*  p_pk   = symaddr<float>(g_pk);
    float*  p_dhid = symaddr<float>(g_dhid);
    float*  p_part = symaddr<float>(g_part);
    __half* ph_hs  = symaddr<__half>(h_hs);
    __half* ph_qw  = symaddr<__half>(h_qkvw);
    __half* ph_ow  = symaddr<__half>(h_opw);
    __half* ph_x   = symaddr<__half>(h_x);
    __half* ph_fq  = symaddr<__half>(h_fq);
    __half* ph_fk  = symaddr<__half>(h_fk);
    __half* ph_fv  = symaddr<__half>(h_fv);
    __half* ph_gq  = symaddr<__half>(h_gq);
    __half* ph_t0  = symaddr<__half>(h_t0);
    __half* ph_t1  = symaddr<__half>(h_t1);
    __half* ph_t2  = symaddr<__half>(h_t2);
    __half* ph_t3  = symaddr<__half>(h_t3);
    __half* ph_t4  = symaddr<__half>(h_t4);
    __half* ph_w02 = symaddr<__half>(h_w02);
    __half* ph_w1  = symaddr<__half>(h_w1);
    __half* ph_w1T = symaddr<__half>(h_w1T);

    const size_t WB = sizeof(float) * NFW * FDFD;
    const size_t WE = (size_t)NFW * FDFD;
    const size_t sH = (size_t)S_LEN * FD;
    const size_t sC = (size_t)CHUNK * FD;
    const size_t sW = (size_t)FDFD;

    cudaFuncSetAttribute(mm_gen, cudaFuncAttributeMaxDynamicSharedMemorySize, GSMEM);
    cudaFuncSetAttribute(mm_fwd, cudaFuncAttributeMaxDynamicSharedMemorySize, GSMEM);
    cudaFuncSetAttribute(mm_upd, cudaFuncAttributeMaxDynamicSharedMemorySize, GSMEM);
    cudaFuncSetAttribute(attn_kernel, cudaFuncAttributeMaxDynamicSharedMemorySize, 53248);

    cudaMemcpyAsync(p_w0, w0, WB, cudaMemcpyDeviceToDevice, 0);
    cudaMemcpyAsync(p_w1, w1, WB, cudaMemcpyDeviceToDevice, 0);
    cudaMemcpyAsync(p_w2, w2, WB, cudaMemcpyDeviceToDevice, 0);

    rope_tab<<<(S_LEN*64)/256, 256>>>();                                          // 0
    f2h<<<(S_LEN*HID)/2048, 256>>>(hs, ph_hs, (size_t)S_LEN*HID);                 // 1
    qkvw_cvt<<<(QKVP*HID)/2048, 256>>>(qkv_w, lrw, ph_qw);                        // 2
    // 3: qkv+lr = hs @ [qkv_w;lr_w]^T
    mm_gen<<<dim3(QKVP/128, S_LEN/128, 1), 256, GSMEM>>>(
        ph_hs, ph_qw, p_qkv, HID, HID, HID, QKVP, 0, 0, 0);
    preprocess_kernel<<<S_LEN, 256>>>(qnw, knw, qksc, qkof, lrb);                 // 4
    attn_kernel<<<dim3(S_LEN/32, NHEADS), 256, 53248>>>();                        // 5
    f2hw02<<<(NFW*1024*FD)/2048, 256>>>(p_w0, p_w2, ph_w02);                      // 6
    f2h<<<WE/2048, 256>>>(p_w1, ph_w1, WE);                                       // 7
    transpose_wh<<<dim3(16, 16, 4), dim3(32, 8)>>>(p_w1, ph_w1T);                 // 8
    f2h<<<(HID*HID)/2048, 256>>>(opw, ph_ow, (size_t)HID*HID);                    // 9

    // TTT scan
    for (int c = 0; c < 4; c++) {
        size_t co = (size_t)c * CHUNK * FD;
        int c0 = c * CHUNK;
        mm_fwd<<<dim3(8, 16, 8), 256, GSMEM>>>(ph_fq + co, ph_fk + co, ph_w02, p_pq, p_pk);
        mm_gen<<<dim3(4, 16, 4), 256, GSMEM>>>(ph_fv + co, ph_w1T, p_dhid,
            FD, FD, FD, FD, sH, sW, sC);
        ttt_elem_t<<<dim3(CHUNK/32, FD/32, NFW), dim3(32, 8)>>>(c0);
        mm_gen<<<dim3(4, 16, 4), 256, GSMEM>>>(ph_gq, ph_w1, p_ofst + co,
            FD, FD, FD, FD, sC, sW, sH);
        mm_upd<<<dim3(4, 4, 48), 256, GSMEM>>>(ph_t0, ph_t1, ph_t3, ph_t4, ph_t2, p_part);
        if (c < 3)
            wupdate<<<dim3(16, 16, 12), dim3(32, 8)>>>(
                p_w0, p_w1, p_w2, p_part, ph_w02, ph_w1, ph_w1T);
    }

    normadd_kernel<<<S_LEN, 256>>>(tnw);

    mm_gen<<<dim3(HID/128, S_LEN/128, 1), 256, GSMEM>>>(
        ph_x, ph_ow, out, HID, HID, HID, HID, 0, 0, 0);
}

// round 13
// speedup vs baseline: 3.3245x; 3.3245x over previous
#include <cuda_runtime.h>
#include <cuda_fp16.h>
#include <math.h>
#include <stdint.h>

#define S_LEN 8192
#define HID 2048
#define QKV3 (3*HID)
#define NHEADS 16
#define HDIM 128
#define NFW 4
#define FD 512
#define CHUNK 2048
#define FDFD (FD*FD)

// ---------------- fp32 scratch ----------------
static __device__ float g_qkv [(size_t)S_LEN*QKV3];
static __device__ float g_rq  [(size_t)S_LEN*HID];
static __device__ float g_rk  [(size_t)S_LEN*HID];
static __device__ float g_attn[(size_t)S_LEN*HID];
static __device__ float g_fv  [(size_t)NFW*S_LEN*FD];
static __device__ float g_ofst[(size_t)NFW*S_LEN*FD];
static __device__ float g_lr  [(size_t)S_LEN*12];
static __device__ float g_rope[(size_t)S_LEN*128];
static __device__ float g_w0  [(size_t)NFW*FDFD];
static __device__ float g_w1  [(size_t)NFW*FDFD];
static __device__ float g_w2  [(size_t)NFW*FDFD];
static __device__ float g_pq  [(size_t)NFW*CHUNK*1024];   // [gq | hmq]
static __device__ float g_pk  [(size_t)NFW*CHUNK*1024];   // [gk | hmk]
static __device__ float g_dhid[(size_t)NFW*CHUNK*FD];
static __device__ float g_part[(size_t)48*FDFD];          // split-K partials
// ---------------- fp16 GEMM operands ----------------
static __device__ __half h_hs  [(size_t)S_LEN*HID];
static __device__ __half h_qkvw[(size_t)QKV3*HID];
static __device__ __half h_opw [(size_t)HID*HID];
static __device__ __half h_x   [(size_t)S_LEN*HID];
static __device__ __half h_fq  [(size_t)NFW*S_LEN*FD];
static __device__ __half h_fk  [(size_t)NFW*S_LEN*FD];
static __device__ __half h_fv  [(size_t)NFW*S_LEN*FD];
static __device__ __half h_gq  [(size_t)NFW*CHUNK*FD];
static __device__ __half h_t0 [(size_t)NFW*CHUNK*FD];
static __device__ __half h_t1 [(size_t)NFW*CHUNK*FD];
static __device__ __half h_t2 [(size_t)NFW*CHUNK*FD];
static __device__ __half h_t3 [(size_t)NFW*CHUNK*FD];
static __device__ __half h_t4 [(size_t)NFW*CHUNK*FD];
static __device__ __half h_w02[(size_t)NFW*1024*FD];      // [w0 rows ; w2 rows]
static __device__ __half h_w1 [(size_t)NFW*FDFD];
static __device__ __half h_w1T[(size_t)NFW*FDFD];

// ---------------- helpers ----------------
__device__ __forceinline__ void mma16(float* c, const uint32_t* a, const uint32_t* b)
{
    asm volatile(
        "mma.sync.aligned.m16n8k16.row.col.f32.f16.f16.f32 "
        "{%0,%1,%2,%3}, {%4,%5,%6,%7}, {%8,%9}, {%0,%1,%2,%3};"
        : "+f"(c[0]), "+f"(c[1]), "+f"(c[2]), "+f"(c[3])
        : "r"(a[0]), "r"(a[1]), "r"(a[2]), "r"(a[3]), "r"(b[0]), "r"(b[1]));
}
__device__ __forceinline__ void ldsm4(uint32_t* r, uint32_t addr)
{
    asm volatile("ldmatrix.sync.aligned.m8n8.x4.shared.b16 {%0,%1,%2,%3}, [%4];"
                 : "=r"(r[0]), "=r"(r[1]), "=r"(r[2]), "=r"(r[3]) : "r"(addr));
}
__device__ __forceinline__ uint32_t smem_u32(const void* p)
{
    uint32_t a;
    asm("{ .reg .u64 t; cvta.to.shared.u64 t, %1; cvt.u32.u64 %0, t; }" : "=r"(a) : "l"(p));
    return a;
}
__device__ __forceinline__ void cp16(uint32_t d, const void* g)
{
    asm volatile("cp.async.cg.shared.global [%0], [%1], 16;" :: "r"(d), "l"(g));
}
#define CP_COMMIT() asm volatile("cp.async.commit_group;" ::: "memory")
#define CP_WAIT1()  asm volatile("cp.async.wait_group 1;" ::: "memory")
#define CP_WAIT0()  asm volatile("cp.async.wait_group 0;" ::: "memory")

// ---------------- fp16 tensor GEMM body (round-10 proven) ----------------
#define STGB 32768
#define GSMEM (3*STGB)

__device__ __forceinline__ void gemm_body(
    const __half* __restrict__ A, const __half* __restrict__ B, float* __restrict__ C,
    int Ks, int lda, int ldb, int ldc, __half* smh)
{
    const int m0 = blockIdx.y * 128, n0 = blockIdx.x * 128;
    const int tid = threadIdx.x, warp = tid >> 5, lane = tid & 31;
    const int wm = (warp >> 1) * 32, wn = (warp & 1) * 64;

    float acc[2][8][4];
    #pragma unroll
    for (int i = 0; i < 2; i++)
        #pragma unroll
        for (int j = 0; j < 8; j++)
            #pragma unroll
            for (int l = 0; l < 4; l++) acc[i][j][l] = 0.f;

    const int nst = Ks >> 6;
    const uint32_t smbase = smem_u32(smh);

    const int crow = tid >> 1;
    const int gb = (tid & 1) * 4;
    const __half* gA = A + (size_t)(m0 + crow) * lda + gb * 8;
    const __half* gB = B + (size_t)(n0 + crow) * ldb + gb * 8;
    const uint32_t wbase = (uint32_t)(crow * 128);
    const uint32_t wsw = (uint32_t)(crow & 7);

    #pragma unroll
    for (int s = 0; s < 2; s++) {
        uint32_t sa = smbase + s * STGB;
        #pragma unroll
        for (int i = 0; i < 4; i++) {
            uint32_t wo = wbase + (((uint32_t)(gb + i) ^ wsw) << 4);
            cp16(sa + wo,         gA + (s << 6) + i * 8);
            cp16(sa + 16384 + wo, gB + (s << 6) + i * 8);
        }
        CP_COMMIT();
    }

    const uint32_t sw = (uint32_t)(lane & 7);
    const uint32_t arowb = (uint32_t)((wm + (lane & 15)) * 128);
    const uint32_t browb = (uint32_t)((wn + ((lane >> 4) << 3) + (lane & 7)) * 128);
    const uint32_t agb = (uint32_t)(lane >> 4);
    const uint32_t bgb = (uint32_t)((lane >> 3) & 1);

    int st = 0;
    for (int s = 0; s < nst; s++) {
        if (s + 1 < nst) CP_WAIT1(); else CP_WAIT0();
        __syncthreads();
        if (s + 2 < nst) {
            uint32_t sa = smbase + ((s + 2) % 3) * STGB;
            #pragma unroll
            for (int i = 0; i < 4; i++) {
                uint32_t wo = wbase + (((uint32_t)(gb + i) ^ wsw) << 4);
                cp16(sa + wo,         gA + ((s + 2) << 6) + i * 8);
                cp16(sa + 16384 + wo, gB + ((s + 2) << 6) + i * 8);
            }
        }
        CP_COMMIT();
        const uint32_t sa = smbase + st * STGB;
        const uint32_t sb = sa + 16384;
        #pragma unroll
        for (int kt = 0; kt < 4; kt++) {
            const uint32_t axor = ((2 * kt + agb) ^ sw) << 4;
            const uint32_t bxor = ((2 * kt + bgb) ^ sw) << 4;
            uint32_t af[2][4];
            ldsm4(af[0], sa + arowb + axor);
            ldsm4(af[1], sa + arowb + 2048 + axor);
            #pragma unroll
            for (int p = 0; p < 4; p++) {
                uint32_t bf[4];
                ldsm4(bf, sb + browb + p * 2048 + bxor);
                mma16(acc[0][2 * p],     af[0], &bf[0]);
                mma16(acc[0][2 * p + 1], af[0], &bf[2]);
                mma16(acc[1][2 * p],     af[1], &bf[0]);
                mma16(acc[1][2 * p + 1], af[1], &bf[2]);
            }
        }
        st++; if (st == 3) st = 0;
    }

    const int gr = lane >> 2, gc = lane & 3;
    #pragma unroll
    for (int mt = 0; mt < 2; mt++) {
        #pragma unroll
        for (int nt = 0; nt < 8; nt++) {
            int row = m0 + wm + mt * 16 + gr;
            int col = n0 + wn + nt * 8 + 2 * gc;
            *(float2*)(C + (size_t)row * ldc + col) =
                make_float2(acc[mt][nt][0], acc[mt][nt][1]);
            *(float2*)(C + (size_t)(row + 8) * ldc + col) =
                make_float2(acc[mt][nt][2], acc[mt][nt][3]);
        }
    }
}

__global__ void __launch_bounds__(256, 2) mm_gen(
    const __half* __restrict__ A, const __half* __restrict__ B, float* __restrict__ C,
    int K, int lda, int ldb, int ldc, size_t sA, size_t sB, size_t sC)
{
    extern __shared__ __half smh[];
    int hh = blockIdx.z;
    gemm_body(A + sA * hh, B + sB * hh, C + sC * hh, K, lda, ldb, ldc, smh);
}

__global__ void __launch_bounds__(256, 2) mm_fwd(
    const __half* __restrict__ fq, const __half* __restrict__ fk,
    const __half* __restrict__ w02, float* __restrict__ pq, float* __restrict__ pk)
{
    extern __shared__ __half smh[];
    int z = blockIdx.z, which = z >> 2, hh = z & 3;
    const __half* A = (which ? fk : fq) + (size_t)hh * ((size_t)S_LEN * FD);
    const __half* B = w02 + (size_t)hh * (1024 * FD);
    float* C = (which ? pk : pq) + (size_t)hh * ((size_t)CHUNK * 1024);
    gemm_body(A, B, C, FD, FD, FD, 1024, smh);
}

__global__ void __launch_bounds__(256, 2) mm_upd(
    const __half* __restrict__ t0, const __half* __restrict__ t1,
    const __half* __restrict__ t3, const __half* __restrict__ t4,
    const __half* __restrict__ t2, float* __restrict__ part)
{
    extern __shared__ __half smh[];
    int z = blockIdx.z, mat = z >> 4, rem = z & 15, sl = rem >> 2, hh = rem & 3;
    const size_t sT = (size_t)FD * CHUNK;
    const __half* A = (mat == 0 ? t0 : mat == 1 ? t1 : t3) + (size_t)hh * sT + sl * (CHUNK / 4);
    const __half* B = (mat < 2 ? t4 : t2) + (size_t)hh * sT + sl * (CHUNK / 4);
    float* C = part + (size_t)z * FDFD;
    gemm_body(A, B, C, CHUNK / 4, CHUNK, CHUNK, FD, smh);
}

// ---------------- fused weight update + fp16 refresh ----------------
__global__ void __launch_bounds__(256) wupdate(
    float* __restrict__ w0, float* __restrict__ w1, float* __restrict__ w2,
    const float* __restrict__ part,
    __half* __restrict__ w02h, __half* __restrict__ w1h, __half* __restrict__ w1Th)
{
    __shared__ float t[32][33];
    int z = blockIdx.z, mat = z >> 2, h = z & 3;
    int c0 = blockIdx.x * 32, r0 = blockIdx.y * 32;
    int x = threadIdx.x, y = threadIdx.y;
    float* master = (mat == 0 ? w0 : mat == 1 ? w2 : w1) + (size_t)h * FDFD;
    const float* p = part + ((size_t)(mat * 16 + h)) * FDFD;
    #pragma unroll
    for (int i = 0; i < 4; i++) {
        int r = r0 + y + i * 8, c = c0 + x;
        size_t idx = (size_t)r * FD + c;
        float s = master[idx] + p[idx] + p[idx + (size_t)4 * FDFD]
                + p[idx + (size_t)8 * FDFD] + p[idx + (size_t)12 * FDFD];
        master[idx] = s;
        __half hv = __float2half(s);
        if (mat == 0)      w02h[(size_t)h * 1024 * FD + idx] = hv;
        else if (mat == 1) w02h[(size_t)h * 1024 * FD + (size_t)512 * FD + idx] = hv;
        else { w1h[(size_t)h * FDFD + idx] = hv; t[y + i * 8][x] = s; }
    }
    if (mat == 2) {
        __syncthreads();
        #pragma unroll
        for (int i = 0; i < 4; i++)
            w1Th[(size_t)h * FDFD + (size_t)(c0 + y + i * 8) * FD + r0 + x] =
                __float2half(t[x][y + i * 8]);
    }
}

// ---------------- converts ----------------
__global__ void __launch_bounds__(256) f2h(const float* __restrict__ s, __half* __restrict__ d, size_t n)
{
    size_t i = ((size_t)blockIdx.x * 256 + threadIdx.x) * 8;
    if (i >= n) return;
    float4 a = *(const float4*)(s + i), b = *(const float4*)(s + i + 4);
    __half2 q0 = __floats2half2_rn(a.x, a.y), q1 = __floats2half2_rn(a.z, a.w);
    __half2 q2 = __floats2half2_rn(b.x, b.y), q3 = __floats2half2_rn(b.z, b.w);
    uint4 u;
    u.x = *(uint32_t*)&q0; u.y = *(uint32_t*)&q1; u.z = *(uint32_t*)&q2; u.w = *(uint32_t*)&q3;
    *(uint4*)(d + i) = u;
}

__global__ void __launch_bounds__(256) f2hw02(const float* __restrict__ w0, const float* __restrict__ w2,
                                              __half* __restrict__ dst)
{
    size_t i = ((size_t)blockIdx.x * 256 + threadIdx.x) * 8;
    int h = (int)(i >> 19);
    int r = (int)((i >> 9) & 1023);
    int c = (int)(i & 511);
    const float* src = (r < 512 ? w0 + ((size_t)h * FD + r) * FD
                                : w2 + ((size_t)h * FD + (r - 512)) * FD) + c;
    float4 a = *(const float4*)src, b = *(const float4*)(src + 4);
    __half2 q0 = __floats2half2_rn(a.x, a.y), q1 = __floats2half2_rn(a.z, a.w);
    __half2 q2 = __floats2half2_rn(b.x, b.y), q3 = __floats2half2_rn(b.z, b.w);
    uint4 u;
    u.x = *(uint32_t*)&q0; u.y = *(uint32_t*)&q1; u.z = *(uint32_t*)&q2; u.w = *(uint32_t*)&q3;
    *(uint4*)(dst + i) = u;
}

__global__ void __launch_bounds__(256) transpose_wh(const float* __restrict__ src, __half* __restrict__ dst)
{
    __shared__ float t[32][33];
    int h = blockIdx.z;
    int i0 = blockIdx.x * 32, j0 = blockIdx.y * 32;
    int x = threadIdx.x, y = threadIdx.y;
    const float* s = src + (size_t)h * FDFD;
    __half* d = dst + (size_t)h * FDFD;
    #pragma unroll
    for (int i = 0; i < 4; i++) t[y + i * 8][x] = s[(size_t)(j0 + y + i * 8) * FD + i0 + x];
    __syncthreads();
    #pragma unroll
    for (int i = 0; i < 4; i++) d[(size_t)(i0 + y + i * 8) * FD + j0 + x] = __float2half(t[x][y + i * 8]);
}

// ---------------- RoPE table (one-time) ----------------
__global__ void __launch_bounds__(256) rope_tab()
{
    int idx = blockIdx.x * 256 + threadIdx.x;   // over S_LEN*64
    int t = idx >> 6, i = idx & 63;
    float freq = (float)exp(-(double)i * (13.122363377404328 / 64.0));
    float sn, cs;
    sincosf((float)t * freq, &sn, &cs);
    g_rope[(size_t)t * 128 + i] = cs;
    g_rope[(size_t)t * 128 + 64 + i] = sn;
}

// ---------------- utils ----------------
__device__ __forceinline__ float blockReduceSum256(float v)
{
    __shared__ float red[8];
    #pragma unroll
    for (int o = 16; o > 0; o >>= 1) v += __shfl_xor_sync(0xffffffffu, v, o);
    if ((threadIdx.x & 31) == 0) red[threadIdx.x >> 5] = v;
    __syncthreads();
    if (threadIdx.x < 32) {
        float x = (threadIdx.x < 8) ? red[threadIdx.x] : 0.f;
        #pragma unroll
        for (int o = 4; o > 0; o >>= 1) x += __shfl_xor_sync(0xffffffffu, x, o);
        if (threadIdx.x == 0) red[0] = x;
    }
    __syncthreads();
    float r = red[0];
    __syncthreads();
    return r;
}
__device__ __forceinline__ float siluf(float x) { return x / (1.f + expf(-x)); }

// ---------------- per-token preprocess (R10 + rope table) ----------------
__global__ void __launch_bounds__(256) preprocess_kernel(
    const float* __restrict__ hs, const float* __restrict__ qnw,
    const float* __restrict__ knw, const float* __restrict__ qksc,
    const float* __restrict__ qkof, const float* __restrict__ lrw,
    const float* __restrict__ lrb)
{
    __shared__ float sq[HID];
    __shared__ float sk[HID];
    __shared__ float gsum[8];
    __shared__ float lsum[12];
    int t = blockIdx.x, tid = threadIdx.x;

    if (tid < 8) gsum[tid] = 0.f;
    if (tid >= 64 && tid < 76) lsum[tid - 64] = 0.f;

    const float* qrow = g_qkv + (size_t)t * QKV3;
    const float* krow = qrow + HID;
    const float* vrow = qrow + 2 * HID;

    float ssq = 0.f, ssk = 0.f;
    for (int d = tid; d < HID; d += 256) {
        float a = qrow[d]; sq[d] = a; ssq += a * a;
        float b = krow[d]; sk[d] = b; ssk += b * b;
    }
    ssq = blockReduceSum256(ssq);
    ssk = blockReduceSum256(ssk);
    float rsq = rsqrtf(ssq * (1.f / HID) + 1e-6f);
    float rsk = rsqrtf(ssk * (1.f / HID) + 1e-6f);
    for (int d = tid; d < HID; d += 256) {
        sq[d] = sq[d] * rsq * qnw[d];
        sk[d] = sk[d] * rsk * knw[d];
    }
    __syncthreads();
    const float* rp = g_rope + (size_t)t * 128;
    for (int idx = tid; idx < NHEADS * 64; idx += 256) {
        int hh = idx >> 6, i = idx & 63;
        float cs = rp[i], sn = rp[64 + i];
        int d1 = hh * HDIM + i, d2 = d1 + 64;
        float q1 = sq[d1], q2 = sq[d2], k1 = sk[d1], k2 = sk[d2];
        size_t base = (size_t)t * HID;
        g_rq[base + d1] = q1 * cs - q2 * sn;
        g_rq[base + d2] = q2 * cs + q1 * sn;
        g_rk[base + d1] = k1 * cs - k2 * sn;
        g_rk[base + d2] = k2 * cs + k1 * sn;
    }
    __syncthreads();
    for (int d = tid; d < HID; d += 256) {
        float xq = sq[d] * qksc[2 * d]     + qkof[2 * d];
        float xk = sk[d] * qksc[2 * d + 1] + qkof[2 * d + 1];
        float a = siluf(xq), b = siluf(xk);
        sq[d] = a; sk[d] = b;
        int g = d >> 9;
        atomicAdd(&gsum[g],     a * a);
        atomicAdd(&gsum[4 + g], b * b);
        float sv = siluf(vrow[d]);
        size_t o = ((size_t)g * S_LEN + t) * FD + (d & 511);
        g_fv[o] = sv;
        h_fv[o] = __float2half(sv);
    }
    __syncthreads();
    for (int d = tid; d < HID; d += 256) {
        int g = d >> 9;
        float nq = fmaxf(sqrtf(gsum[g]),     1e-12f);
        float nk = fmaxf(sqrtf(gsum[4 + g]), 1e-12f);
        size_t o = ((size_t)g * S_LEN + t) * FD + (d & 511);
        h_fq[o] = __float2half(sq[d] / nq);
        h_fk[o] = __float2half(sk[d] / nk);
    }
    float p[12];
    #pragma unroll
    for (int j = 0; j < 12; j++) p[j] = 0.f;
    const float* hrow = hs + (size_t)t * HID;
    for (int d = tid; d < HID; d += 256) {
        float hv = hrow[d];
        #pragma unroll
        for (int j = 0; j < 12; j++) p[j] += hv * lrw[(size_t)j * HID + d];
    }
    #pragma unroll
    for (int j = 0; j < 12; j++) {
        float v = p[j];
        #pragma unroll
        for (int o = 16; o > 0; o >>= 1) v += __shfl_xor_sync(0xffffffffu, v, o);
        if ((tid & 31) == 0) atomicAdd(&lsum[j], v);
    }
    __syncthreads();
    if (tid < 12) {
        float z = lsum[tid] + lrb[tid] - 6.90725523731f;
        float sp = (z > 0.f) ? z + log1pf(expf(-z)) : log1pf(expf(z));
        g_lr[(size_t)t * 12 + tid] = sp;
    }
}

// ---------------- sliding-window attention (bank-conflict-free) ----------------
// sQ/sK/sV rows padded to 132 floats; k-lanes map k = sub + 8j; output dims
// d = sub*4 + 32*jj. All LDS.128 verified conflict-free mod 32 banks.
#define AR 132
#define ASM_FLOATS (3*32*AR + 32*36)    // 13824
__global__ void __launch_bounds__(256) attn_kernel()
{
    extern __shared__ float sh[];
    float* sQ = sh;                 // 32 x 132
    float* sK = sh + 32 * AR;       // 32 x 132
    float* sV = sh + 64 * AR;       // 32 x 132
    float* sP = sh + 96 * AR;       // 32 x 36
    int head = blockIdx.y;
    int q0 = blockIdx.x * 32;
    int tid = threadIdx.x;
    int row = tid >> 3, sub = tid & 7;
    const float qs = 0.08838834764831845f;

    for (int i = tid; i < 32 * 32; i += 256) {
        int r = i >> 5, c4 = (i & 31) << 2;
        float4 v = *(const float4*)(g_rq + (size_t)(q0 + r) * HID + head * HDIM + c4);
        v.x *= qs; v.y *= qs; v.z *= qs; v.w *= qs;
        *(float4*)(sQ + r * AR + c4) = v;
    }

    float oacc[16];
    #pragma unroll
    for (int j = 0; j < 16; j++) oacc[j] = 0.f;
    float m = -1e30f, l = 0.f;
    int qpos = q0 + row;

    for (int it = 0; it < 9; it++) {
        int kb = q0 - 256 + it * 32;
        if (kb + 32 <= 0) continue;
        __syncthreads();
        for (int i = tid; i < 32 * 32; i += 256) {
            int r = i >> 5, c4 = (i & 31) << 2;
            int kpos = kb + r;
            float4 kv = make_float4(0.f,0.f,0.f,0.f), vv = kv;
            if (kpos >= 0) {
                kv = *(const float4*)(g_rk  + (size_t)kpos * HID  + head * HDIM + c4);
                vv = *(const float4*)(g_qkv + (size_t)kpos * QKV3 + 2 * HID + head * HDIM + c4);
            }
            *(float4*)(sK + r * AR + c4) = kv;
            *(float4*)(sV + r * AR + c4) = vv;
        }
        __syncthreads();
        float s[4];
        bool ok[4];
        #pragma unroll
        for (int j = 0; j < 4; j++) {
            int kpos = kb + sub + 8 * j;
            ok[j] = (kpos >= 0) && (kpos <= qpos) && (kpos >= qpos - 255);
            s[j] = 0.f;
        }
        const float4* qp = (const float4*)(sQ + row * AR);
        #pragma unroll 8
        for (int d4 = 0; d4 < 32; d4++) {
            float4 a = qp[d4];
            #pragma unroll
            for (int j = 0; j < 4; j++) {
                float4 b = *(const float4*)(sK + (sub + 8 * j) * AR + d4 * 4);
                s[j] += a.x*b.x + a.y*b.y + a.z*b.z + a.w*b.w;
            }
        }
        float tmax = -1e30f;
        #pragma unroll
        for (int j = 0; j < 4; j++) { if (!ok[j]) s[j] = -1e30f; tmax = fmaxf(tmax, s[j]); }
        #pragma unroll
        for (int o = 4; o > 0; o >>= 1) tmax = fmaxf(tmax, __shfl_xor_sync(0xffffffffu, tmax, o, 8));
        float mnew = fmaxf(m, tmax);
        float scale = expf(m - mnew);
        float p[4], ps = 0.f;
        #pragma unroll
        for (int j = 0; j < 4; j++) { p[j] = ok[j] ? expf(s[j] - mnew) : 0.f; ps += p[j]; }
        #pragma unroll
        for (int o = 4; o > 0; o >>= 1) ps += __shfl_xor_sync(0xffffffffu, ps, o, 8);
        l = l * scale + ps;
        m = mnew;
        #pragma unroll
        for (int j = 0; j < 16; j++) oacc[j] *= scale;
        #pragma unroll
        for (int j = 0; j < 4; j++) sP[row * 36 + sub + 8 * j] = p[j];
        __syncwarp();
        #pragma unroll 4
        for (int k = 0; k < 32; k++) {
            float pk = sP[row * 36 + k];
            #pragma unroll
            for (int jj = 0; jj < 4; jj++) {
                float4 v = *(const float4*)(sV + k * AR + sub * 4 + 32 * jj);
                oacc[jj*4+0] += pk*v.x; oacc[jj*4+1] += pk*v.y;
                oacc[jj*4+2] += pk*v.z; oacc[jj*4+3] += pk*v.w;
            }
        }
    }
    float inv = 1.f / l;
    #pragma unroll
    for (int jj = 0; jj < 4; jj++) {
        float4 v;
        v.x = oacc[jj*4+0]*inv; v.y = oacc[jj*4+1]*inv;
        v.z = oacc[jj*4+2]*inv; v.w = oacc[jj*4+3]*inv;
        *(float4*)(g_attn + (size_t)qpos * HID + head * HDIM + sub * 4 + 32 * jj) = v;
    }
}

// ---------------- TTT elementwise + transposes ----------------
__global__ void __launch_bounds__(256) ttt_elem_t(int c0)
{
    __shared__ float t0[32][33], t1[32][33], t2[32][33], t3[32][33], t4[32][33];
    int h = blockIdx.z;
    int cb = blockIdx.x * 32, db = blockIdx.y * 32;
    int x = threadIdx.x, y = threadIdx.y;
    size_t base  = (size_t)h * CHUNK * FD;
    size_t baseP = (size_t)h * CHUNK * 1024;
    #pragma unroll
    for (int i = 0; i < 4; i++) {
        int cy = y + i * 8;
        int c = cb + cy, d = db + x;
        size_t idx  = base  + (size_t)c * FD + d;
        size_t idxP = baseP + (size_t)c * 1024 + d;
        int t = c0 + c;
        float lr0 = g_lr[(size_t)t * 12 + h];
        float lr1 = g_lr[(size_t)t * 12 + 4 + h];
        float lr2 = g_lr[(size_t)t * 12 + 8 + h];
        float gq = g_pq[idxP], hmq = g_pq[idxP + 512];
        h_gq[idx] = __float2half(siluf(gq) * hmq);
        float gk = g_pk[idxP], hmk = g_pk[idxP + 512], dh = g_dhid[idx];
        float sg = 1.f / (1.f + expf(-gk));
        float silug = gk * sg;
        t0[cy][x] = dh * hmk * (sg * (1.f + gk * (1.f - sg))) * lr0;
        t1[cy][x] = dh * silug * lr2;
        t2[cy][x] = silug * hmk;
        t3[cy][x] = g_fv[((size_t)h * S_LEN + t) * FD + d] * lr1;
        t4[cy][x] = __half2float(h_fk[((size_t)h * S_LEN + t) * FD + d]);
    }
    __syncthreads();
    size_t tb = ((size_t)h * FD + db) * CHUNK + cb;
    #pragma unroll
    for (int i = 0; i < 4; i++) {
        int dy = y + i * 8;
        size_t o = tb + (size_t)dy * CHUNK + x;
        h_t0[o] = __float2half(t0[x][dy]);
        h_t1[o] = __float2half(t1[x][dy]);
        h_t2[o] = __float2half(t2[x][dy]);
        h_t3[o] = __float2half(t3[x][dy]);
        h_t4[o] = __float2half(t4[x][dy]);
    }
}

// ---------------- rms_norm(o_fast) + attn add -> fp16 x ----------------
__global__ void __launch_bounds__(256) normadd_kernel(const float* __restrict__ tnw)
{
    __shared__ float ss[4];
    int t = blockIdx.x, tid = threadIdx.x;
    if (tid < 4) ss[tid] = 0.f;
    __syncthreads();
    float v[8];
    #pragma unroll
    for (int i = 0; i < 8; i++) {
        int d = i * 256 + tid;
        int h = d >> 9;
        float x = g_ofst[((size_t)h * S_LEN + t) * FD + (d & 511)];
        v[i] = x;
        float s = x * x;
        #pragma unroll
        for (int o = 16; o > 0; o >>= 1) s += __shfl_xor_sync(0xffffffffu, s, o);
        if ((tid & 31) == 0) atomicAdd(&ss[h], s);
    }
    __syncthreads();
    #pragma unroll
    for (int i = 0; i < 8; i++) {
        int d = i * 256 + tid;
        int h = d >> 9;
        float rn = rsqrtf(ss[h] * (1.f / FD) + 1e-6f);
        h_x[(size_t)t * HID + d] =
            __float2half(g_attn[(size_t)t * HID + d] + v[i] * rn * tnw[d & 511]);
    }
}

// ---------------- host ----------------
template<typename T>
static T* symaddr(const void* s)
{
    void* p = nullptr;
    cudaGetSymbolAddress(&p, s);
    return (T*)p;
}

extern "C" void kernel_launch(void* const* d_in, const int* in_sizes, int n_in,
                              void* d_out, int out_size)
{
    const float* hs    = (const float*)d_in[0];
    const float* qkv_w = (const float*)d_in[1];
    const float* qnw   = (const float*)d_in[2];
    const float* knw   = (const float*)d_in[3];
    const float* qksc  = (const float*)d_in[4];
    const float* qkof  = (const float*)d_in[5];
    const float* lrw   = (const float*)d_in[6];
    const float* lrb   = (const float*)d_in[7];
    const float* w0    = (const float*)d_in[8];
    const float* w1    = (const float*)d_in[9];
    const float* w2    = (const float*)d_in[10];
    const float* tnw   = (const float*)d_in[11];
    const float* opw   = (const float*)d_in[12];
    float* out = (float*)d_out;

    float*  p_qkv  = symaddr<float>(g_qkv);
    float*  p_ofst = symaddr<float>(g_ofst);
    float*  p_w0   = symaddr<float>(g_w0);
    float*  p_w1   = symaddr<float>(g_w1);
    float*  p_w2   = symaddr<float>(g_w2);
    float*  p_pq   = symaddr<float>(g_pq);
    float*  p_pk   = symaddr<float>(g_pk);
    float*  p_dhid = symaddr<float>(g_dhid);
    float*  p_part = symaddr<float>(g_part);
    __half* ph_hs  = symaddr<__half>(h_hs);
    __half* ph_qw  = symaddr<__half>(h_qkvw);
    __half* ph_ow  = symaddr<__half>(h_opw);
    __half* ph_x   = symaddr<__half>(h_x);
    __half* ph_fq  = symaddr<__half>(h_fq);
    __half* ph_fk  = symaddr<__half>(h_fk);
    __half* ph_fv  = symaddr<__half>(h_fv);
    __half* ph_gq  = symaddr<__half>(h_gq);
    __half* ph_t0  = symaddr<__half>(h_t0);
    __half* ph_t1  = symaddr<__half>(h_t1);
    __half* ph_t2  = symaddr<__half>(h_t2);
    __half* ph_t3  = symaddr<__half>(h_t3);
    __half* ph_t4  = symaddr<__half>(h_t4);
    __half* ph_w02 = symaddr<__half>(h_w02);
    __half* ph_w1  = symaddr<__half>(h_w1);
    __half* ph_w1T = symaddr<__half>(h_w1T);

    const size_t WB = sizeof(float) * NFW * FDFD;
    const size_t WE = (size_t)NFW * FDFD;
    const size_t sH = (size_t)S_LEN * FD;
    const size_t sC = (size_t)CHUNK * FD;
    const size_t sW = (size_t)FDFD;

    cudaFuncSetAttribute(mm_gen, cudaFuncAttributeMaxDynamicSharedMemorySize, GSMEM);
    cudaFuncSetAttribute(mm_fwd, cudaFuncAttributeMaxDynamicSharedMemorySize, GSMEM);
    cudaFuncSetAttribute(mm_upd, cudaFuncAttributeMaxDynamicSharedMemorySize, GSMEM);
    cudaFuncSetAttribute(attn_kernel, cudaFuncAttributeMaxDynamicSharedMemorySize, ASM_FLOATS * 4);

    cudaMemcpyAsync(p_w0, w0, WB, cudaMemcpyDeviceToDevice, 0);
    cudaMemcpyAsync(p_w1, w1, WB, cudaMemcpyDeviceToDevice, 0);
    cudaMemcpyAsync(p_w2, w2, WB, cudaMemcpyDeviceToDevice, 0);

    rope_tab<<<(S_LEN*64)/256, 256>>>();                                          // 0
    f2h<<<(S_LEN*HID)/2048, 256>>>(hs, ph_hs, (size_t)S_LEN*HID);                 // 1
    f2h<<<(QKV3*HID)/2048, 256>>>(qkv_w, ph_qw, (size_t)QKV3*HID);                // 2
    mm_gen<<<dim3(QKV3/128, S_LEN/128, 1), 256, GSMEM>>>(
        ph_hs, ph_qw, p_qkv, HID, HID, HID, QKV3, 0, 0, 0);                       // 3
    preprocess_kernel<<<S_LEN, 256>>>(hs, qnw, knw, qksc, qkof, lrw, lrb);        // 4
    attn_kernel<<<dim3(S_LEN/32, NHEADS), 256, ASM_FLOATS * 4>>>();               // 5 (PROFILED)
    f2hw02<<<(NFW*1024*FD)/2048, 256>>>(p_w0, p_w2, ph_w02);                      // 6
    f2h<<<WE/2048, 256>>>(p_w1, ph_w1, WE);                                       // 7
    transpose_wh<<<dim3(16, 16, 4), dim3(32, 8)>>>(p_w1, ph_w1T);                 // 8
    f2h<<<(HID*HID)/2048, 256>>>(opw, ph_ow, (size_t)HID*HID);                    // 9

    // TTT scan
    for (int c = 0; c < 4; c++) {
        size_t co = (size_t)c * CHUNK * FD;
        int c0 = c * CHUNK;
        mm_fwd<<<dim3(8, 16, 8), 256, GSMEM>>>(ph_fq + co, ph_fk + co, ph_w02, p_pq, p_pk);
        mm_gen<<<dim3(4, 16, 4), 256, GSMEM>>>(ph_fv + co, ph_w1T, p_dhid,
            FD, FD, FD, FD, sH, sW, sC);
        ttt_elem_t<<<dim3(CHUNK/32, FD/32, NFW), dim3(32, 8)>>>(c0);
        mm_gen<<<dim3(4, 16, 4), 256, GSMEM>>>(ph_gq, ph_w1, p_ofst + co,
            FD, FD, FD, FD, sC, sW, sH);
        mm_upd<<<dim3(4, 4, 48), 256, GSMEM>>>(ph_t0, ph_t1, ph_t3, ph_t4, ph_t2, p_part);
        if (c < 3)
            wupdate<<<dim3(16, 16, 12), dim3(32, 8)>>>(
                p_w0, p_w1, p_w2, p_part, ph_w02, ph_w1, ph_w1T);
    }

    normadd_kernel<<<S_LEN, 256>>>(tnw);

    mm_gen<<<dim3(HID/128, S_LEN/128, 1), 256, GSMEM>>>(
        ph_x, ph_ow, out, HID, HID, HID, HID, 0, 0, 0);
}

// round 14
// speedup vs baseline: 3.3369x; 1.0037x over previous
#include <cuda_runtime.h>
#include <cuda_fp16.h>
#include <math.h>
#include <stdint.h>

#define S_LEN 8192
#define HID 2048
#define QKV3 (3*HID)
#define NHEADS 16
#define HDIM 128
#define NFW 4
#define FD 512
#define CHUNK 2048
#define FDFD (FD*FD)

// ---------------- fp32 scratch ----------------
static __device__ float g_qkv [(size_t)S_LEN*QKV3];
static __device__ float g_rq  [(size_t)S_LEN*HID];
static __device__ float g_rk  [(size_t)S_LEN*HID];
static __device__ float g_attn[(size_t)S_LEN*HID];
static __device__ float g_fv  [(size_t)NFW*S_LEN*FD];
static __device__ float g_ofst[(size_t)NFW*S_LEN*FD];
static __device__ float g_lr  [(size_t)S_LEN*12];
static __device__ float g_lrraw[(size_t)S_LEN*128];
static __device__ float g_rope[(size_t)S_LEN*128];
static __device__ float g_w0  [(size_t)NFW*FDFD];
static __device__ float g_w1  [(size_t)NFW*FDFD];
static __device__ float g_w2  [(size_t)NFW*FDFD];
static __device__ float g_pq  [(size_t)NFW*CHUNK*1024];   // [gq | hmq]
static __device__ float g_pk  [(size_t)NFW*CHUNK*1024];   // [gk | hmk]
static __device__ float g_dhid[(size_t)NFW*CHUNK*FD];
static __device__ float g_part[(size_t)48*FDFD];          // split-K partials
// ---------------- fp16 GEMM operands ----------------
static __device__ __half h_hs  [(size_t)S_LEN*HID];
static __device__ __half h_qkvw[(size_t)QKV3*HID];
static __device__ __half h_lrw [(size_t)128*HID];
static __device__ __half h_opw [(size_t)HID*HID];
static __device__ __half h_x   [(size_t)S_LEN*HID];
static __device__ __half h_fq  [(size_t)NFW*S_LEN*FD];
static __device__ __half h_fk  [(size_t)NFW*S_LEN*FD];
static __device__ __half h_fv  [(size_t)NFW*S_LEN*FD];
static __device__ __half h_gq  [(size_t)NFW*CHUNK*FD];
static __device__ __half h_t0 [(size_t)NFW*CHUNK*FD];
static __device__ __half h_t1 [(size_t)NFW*CHUNK*FD];
static __device__ __half h_t2 [(size_t)NFW*CHUNK*FD];
static __device__ __half h_t3 [(size_t)NFW*CHUNK*FD];
static __device__ __half h_t4 [(size_t)NFW*CHUNK*FD];
static __device__ __half h_w02[(size_t)NFW*1024*FD];      // [w0 rows ; w2 rows]
static __device__ __half h_w1 [(size_t)NFW*FDFD];
static __device__ __half h_w1T[(size_t)NFW*FDFD];

// ---------------- helpers ----------------
__device__ __forceinline__ void mma16(float* c, const uint32_t* a, const uint32_t* b)
{
    asm volatile(
        "mma.sync.aligned.m16n8k16.row.col.f32.f16.f16.f32 "
        "{%0,%1,%2,%3}, {%4,%5,%6,%7}, {%8,%9}, {%0,%1,%2,%3};"
        : "+f"(c[0]), "+f"(c[1]), "+f"(c[2]), "+f"(c[3])
        : "r"(a[0]), "r"(a[1]), "r"(a[2]), "r"(a[3]), "r"(b[0]), "r"(b[1]));
}
__device__ __forceinline__ void ldsm4(uint32_t* r, uint32_t addr)
{
    asm volatile("ldmatrix.sync.aligned.m8n8.x4.shared.b16 {%0,%1,%2,%3}, [%4];"
                 : "=r"(r[0]), "=r"(r[1]), "=r"(r[2]), "=r"(r[3]) : "r"(addr));
}
__device__ __forceinline__ uint32_t smem_u32(const void* p)
{
    uint32_t a;
    asm("{ .reg .u64 t; cvta.to.shared.u64 t, %1; cvt.u32.u64 %0, t; }" : "=r"(a) : "l"(p));
    return a;
}
__device__ __forceinline__ void cp16(uint32_t d, const void* g)
{
    asm volatile("cp.async.cg.shared.global [%0], [%1], 16;" :: "r"(d), "l"(g));
}
#define CP_COMMIT() asm volatile("cp.async.commit_group;" ::: "memory")
#define CP_WAIT1()  asm volatile("cp.async.wait_group 1;" ::: "memory")
#define CP_WAIT0()  asm volatile("cp.async.wait_group 0;" ::: "memory")

// ---------------- fp16 tensor GEMM body (round-10 proven) ----------------
#define STGB 32768
#define GSMEM (3*STGB)

__device__ __forceinline__ void gemm_body(
    const __half* __restrict__ A, const __half* __restrict__ B, float* __restrict__ C,
    int Ks, int lda, int ldb, int ldc, __half* smh)
{
    const int m0 = blockIdx.y * 128, n0 = blockIdx.x * 128;
    const int tid = threadIdx.x, warp = tid >> 5, lane = tid & 31;
    const int wm = (warp >> 1) * 32, wn = (warp & 1) * 64;

    float acc[2][8][4];
    #pragma unroll
    for (int i = 0; i < 2; i++)
        #pragma unroll
        for (int j = 0; j < 8; j++)
            #pragma unroll
            for (int l = 0; l < 4; l++) acc[i][j][l] = 0.f;

    const int nst = Ks >> 6;
    const uint32_t smbase = smem_u32(smh);

    const int crow = tid >> 1;
    const int gb = (tid & 1) * 4;
    const __half* gA = A + (size_t)(m0 + crow) * lda + gb * 8;
    const __half* gB = B + (size_t)(n0 + crow) * ldb + gb * 8;
    const uint32_t wbase = (uint32_t)(crow * 128);
    const uint32_t wsw = (uint32_t)(crow & 7);

    #pragma unroll
    for (int s = 0; s < 2; s++) {
        uint32_t sa = smbase + s * STGB;
        #pragma unroll
        for (int i = 0; i < 4; i++) {
            uint32_t wo = wbase + (((uint32_t)(gb + i) ^ wsw) << 4);
            cp16(sa + wo,         gA + (s << 6) + i * 8);
            cp16(sa + 16384 + wo, gB + (s << 6) + i * 8);
        }
        CP_COMMIT();
    }

    const uint32_t sw = (uint32_t)(lane & 7);
    const uint32_t arowb = (uint32_t)((wm + (lane & 15)) * 128);
    const uint32_t browb = (uint32_t)((wn + ((lane >> 4) << 3) + (lane & 7)) * 128);
    const uint32_t agb = (uint32_t)(lane >> 4);
    const uint32_t bgb = (uint32_t)((lane >> 3) & 1);

    int st = 0;
    for (int s = 0; s < nst; s++) {
        if (s + 1 < nst) CP_WAIT1(); else CP_WAIT0();
        __syncthreads();
        if (s + 2 < nst) {
            uint32_t sa = smbase + ((s + 2) % 3) * STGB;
            #pragma unroll
            for (int i = 0; i < 4; i++) {
                uint32_t wo = wbase + (((uint32_t)(gb + i) ^ wsw) << 4);
                cp16(sa + wo,         gA + ((s + 2) << 6) + i * 8);
                cp16(sa + 16384 + wo, gB + ((s + 2) << 6) + i * 8);
            }
        }
        CP_COMMIT();
        const uint32_t sa = smbase + st * STGB;
        const uint32_t sb = sa + 16384;
        #pragma unroll
        for (int kt = 0; kt < 4; kt++) {
            const uint32_t axor = ((2 * kt + agb) ^ sw) << 4;
            const uint32_t bxor = ((2 * kt + bgb) ^ sw) << 4;
            uint32_t af[2][4];
            ldsm4(af[0], sa + arowb + axor);
            ldsm4(af[1], sa + arowb + 2048 + axor);
            #pragma unroll
            for (int p = 0; p < 4; p++) {
                uint32_t bf[4];
                ldsm4(bf, sb + browb + p * 2048 + bxor);
                mma16(acc[0][2 * p],     af[0], &bf[0]);
                mma16(acc[0][2 * p + 1], af[0], &bf[2]);
                mma16(acc[1][2 * p],     af[1], &bf[0]);
                mma16(acc[1][2 * p + 1], af[1], &bf[2]);
            }
        }
        st++; if (st == 3) st = 0;
    }

    const int gr = lane >> 2, gc = lane & 3;
    #pragma unroll
    for (int mt = 0; mt < 2; mt++) {
        #pragma unroll
        for (int nt = 0; nt < 8; nt++) {
            int row = m0 + wm + mt * 16 + gr;
            int col = n0 + wn + nt * 8 + 2 * gc;
            *(float2*)(C + (size_t)row * ldc + col) =
                make_float2(acc[mt][nt][0], acc[mt][nt][1]);
            *(float2*)(C + (size_t)(row + 8) * ldc + col) =
                make_float2(acc[mt][nt][2], acc[mt][nt][3]);
        }
    }
}

__global__ void __launch_bounds__(256, 2) mm_gen(
    const __half* __restrict__ A, const __half* __restrict__ B, float* __restrict__ C,
    int K, int lda, int ldb, int ldc, size_t sA, size_t sB, size_t sC)
{
    extern __shared__ __half smh[];
    int hh = blockIdx.z;
    gemm_body(A + sA * hh, B + sB * hh, C + sC * hh, K, lda, ldb, ldc, smh);
}

__global__ void __launch_bounds__(256, 2) mm_fwd(
    const __half* __restrict__ fq, const __half* __restrict__ fk,
    const __half* __restrict__ w02, float* __restrict__ pq, float* __restrict__ pk)
{
    extern __shared__ __half smh[];
    int z = blockIdx.z, which = z >> 2, hh = z & 3;
    const __half* A = (which ? fk : fq) + (size_t)hh * ((size_t)S_LEN * FD);
    const __half* B = w02 + (size_t)hh * (1024 * FD);
    float* C = (which ? pk : pq) + (size_t)hh * ((size_t)CHUNK * 1024);
    gemm_body(A, B, C, FD, FD, FD, 1024, smh);
}

__global__ void __launch_bounds__(256, 2) mm_upd(
    const __half* __restrict__ t0, const __half* __restrict__ t1,
    const __half* __restrict__ t3, const __half* __restrict__ t4,
    const __half* __restrict__ t2, float* __restrict__ part)
{
    extern __shared__ __half smh[];
    int z = blockIdx.z, mat = z >> 4, rem = z & 15, sl = rem >> 2, hh = rem & 3;
    const size_t sT = (size_t)FD * CHUNK;
    const __half* A = (mat == 0 ? t0 : mat == 1 ? t1 : t3) + (size_t)hh * sT + sl * (CHUNK / 4);
    const __half* B = (mat < 2 ? t4 : t2) + (size_t)hh * sT + sl * (CHUNK / 4);
    float* C = part + (size_t)z * FDFD;
    gemm_body(A, B, C, CHUNK / 4, CHUNK, CHUNK, FD, smh);
}

// ---------------- fused weight update + fp16 refresh ----------------
__global__ void __launch_bounds__(256) wupdate(
    float* __restrict__ w0, float* __restrict__ w1, float* __restrict__ w2,
    const float* __restrict__ part,
    __half* __restrict__ w02h, __half* __restrict__ w1h, __half* __restrict__ w1Th)
{
    __shared__ float t[32][33];
    int z = blockIdx.z, mat = z >> 2, h = z & 3;
    int c0 = blockIdx.x * 32, r0 = blockIdx.y * 32;
    int x = threadIdx.x, y = threadIdx.y;
    float* master = (mat == 0 ? w0 : mat == 1 ? w2 : w1) + (size_t)h * FDFD;
    const float* p = part + ((size_t)(mat * 16 + h)) * FDFD;
    #pragma unroll
    for (int i = 0; i < 4; i++) {
        int r = r0 + y + i * 8, c = c0 + x;
        size_t idx = (size_t)r * FD + c;
        float s = master[idx] + p[idx] + p[idx + (size_t)4 * FDFD]
                + p[idx + (size_t)8 * FDFD] + p[idx + (size_t)12 * FDFD];
        master[idx] = s;
        __half hv = __float2half(s);
        if (mat == 0)      w02h[(size_t)h * 1024 * FD + idx] = hv;
        else if (mat == 1) w02h[(size_t)h * 1024 * FD + (size_t)512 * FD + idx] = hv;
        else { w1h[(size_t)h * FDFD + idx] = hv; t[y + i * 8][x] = s; }
    }
    if (mat == 2) {
        __syncthreads();
        #pragma unroll
        for (int i = 0; i < 4; i++)
            w1Th[(size_t)h * FDFD + (size_t)(c0 + y + i * 8) * FD + r0 + x] =
                __float2half(t[x][y + i * 8]);
    }
}

// ---------------- converts ----------------
__global__ void __launch_bounds__(256) f2h(const float* __restrict__ s, __half* __restrict__ d, size_t n)
{
    size_t i = ((size_t)blockIdx.x * 256 + threadIdx.x) * 8;
    if (i >= n) return;
    float4 a = *(const float4*)(s + i), b = *(const float4*)(s + i + 4);
    __half2 q0 = __floats2half2_rn(a.x, a.y), q1 = __floats2half2_rn(a.z, a.w);
    __half2 q2 = __floats2half2_rn(b.x, b.y), q3 = __floats2half2_rn(b.z, b.w);
    uint4 u;
    u.x = *(uint32_t*)&q0; u.y = *(uint32_t*)&q1; u.z = *(uint32_t*)&q2; u.w = *(uint32_t*)&q3;
    *(uint4*)(d + i) = u;
}

// lr_w (12 x 2048) -> h_lrw (128 x 2048), zero-padded
__global__ void __launch_bounds__(256) lrw_cvt(const float* __restrict__ lw, __half* __restrict__ dst)
{
    size_t i = ((size_t)blockIdx.x * 256 + threadIdx.x) * 8;   // over 128*HID
    int row = (int)(i >> 11);
    int col = (int)(i & 2047);
    float4 a = make_float4(0.f,0.f,0.f,0.f), b = a;
    if (row < 12) {
        const float* s = lw + (size_t)row * HID + col;
        a = *(const float4*)s; b = *(const float4*)(s + 4);
    }
    __half2 q0 = __floats2half2_rn(a.x, a.y), q1 = __floats2half2_rn(a.z, a.w);
    __half2 q2 = __floats2half2_rn(b.x, b.y), q3 = __floats2half2_rn(b.z, b.w);
    uint4 u;
    u.x = *(uint32_t*)&q0; u.y = *(uint32_t*)&q1; u.z = *(uint32_t*)&q2; u.w = *(uint32_t*)&q3;
    *(uint4*)(dst + i) = u;
}

__global__ void __launch_bounds__(256) f2hw02(const float* __restrict__ w0, const float* __restrict__ w2,
                                              __half* __restrict__ dst)
{
    size_t i = ((size_t)blockIdx.x * 256 + threadIdx.x) * 8;
    int h = (int)(i >> 19);
    int r = (int)((i >> 9) & 1023);
    int c = (int)(i & 511);
    const float* src = (r < 512 ? w0 + ((size_t)h * FD + r) * FD
                                : w2 + ((size_t)h * FD + (r - 512)) * FD) + c;
    float4 a = *(const float4*)src, b = *(const float4*)(src + 4);
    __half2 q0 = __floats2half2_rn(a.x, a.y), q1 = __floats2half2_rn(a.z, a.w);
    __half2 q2 = __floats2half2_rn(b.x, b.y), q3 = __floats2half2_rn(b.z, b.w);
    uint4 u;
    u.x = *(uint32_t*)&q0; u.y = *(uint32_t*)&q1; u.z = *(uint32_t*)&q2; u.w = *(uint32_t*)&q3;
    *(uint4*)(dst + i) = u;
}

__global__ void __launch_bounds__(256) transpose_wh(const float* __restrict__ src, __half* __restrict__ dst)
{
    __shared__ float t[32][33];
    int h = blockIdx.z;
    int i0 = blockIdx.x * 32, j0 = blockIdx.y * 32;
    int x = threadIdx.x, y = threadIdx.y;
    const float* s = src + (size_t)h * FDFD;
    __half* d = dst + (size_t)h * FDFD;
    #pragma unroll
    for (int i = 0; i < 4; i++) t[y + i * 8][x] = s[(size_t)(j0 + y + i * 8) * FD + i0 + x];
    __syncthreads();
    #pragma unroll
    for (int i = 0; i < 4; i++) d[(size_t)(i0 + y + i * 8) * FD + j0 + x] = __float2half(t[x][y + i * 8]);
}

// ---------------- RoPE table (one-time) ----------------
__global__ void __launch_bounds__(256) rope_tab()
{
    int idx = blockIdx.x * 256 + threadIdx.x;   // over S_LEN*64
    int t = idx >> 6, i = idx & 63;
    float freq = (float)exp(-(double)i * (13.122363377404328 / 64.0));
    float sn, cs;
    sincosf((float)t * freq, &sn, &cs);
    g_rope[(size_t)t * 128 + i] = cs;
    g_rope[(size_t)t * 128 + 64 + i] = sn;
}

// ---------------- utils ----------------
__device__ __forceinline__ float blockReduceSum256(float v)
{
    __shared__ float red[8];
    #pragma unroll
    for (int o = 16; o > 0; o >>= 1) v += __shfl_xor_sync(0xffffffffu, v, o);
    if ((threadIdx.x & 31) == 0) red[threadIdx.x >> 5] = v;
    __syncthreads();
    if (threadIdx.x < 32) {
        float x = (threadIdx.x < 8) ? red[threadIdx.x] : 0.f;
        #pragma unroll
        for (int o = 4; o > 0; o >>= 1) x += __shfl_xor_sync(0xffffffffu, x, o);
        if (threadIdx.x == 0) red[0] = x;
    }
    __syncthreads();
    float r = red[0];
    __syncthreads();
    return r;
}
__device__ __forceinline__ float siluf(float x) { return x / (1.f + expf(-x)); }

// ---------------- per-token preprocess (LR from GEMM) ----------------
__global__ void __launch_bounds__(256) preprocess_kernel(
    const float* __restrict__ qnw, const float* __restrict__ knw,
    const float* __restrict__ qksc, const float* __restrict__ qkof,
    const float* __restrict__ lrb)
{
    __shared__ float sq[HID];
    __shared__ float sk[HID];
    __shared__ float gsum[8];
    int t = blockIdx.x, tid = threadIdx.x;

    if (tid < 8) gsum[tid] = 0.f;

    const float* qrow = g_qkv + (size_t)t * QKV3;
    const float* krow = qrow + HID;
    const float* vrow = qrow + 2 * HID;

    float ssq = 0.f, ssk = 0.f;
    for (int d = tid; d < HID; d += 256) {
        float a = qrow[d]; sq[d] = a; ssq += a * a;
        float b = krow[d]; sk[d] = b; ssk += b * b;
    }
    ssq = blockReduceSum256(ssq);
    ssk = blockReduceSum256(ssk);
    float rsq = rsqrtf(ssq * (1.f / HID) + 1e-6f);
    float rsk = rsqrtf(ssk * (1.f / HID) + 1e-6f);
    for (int d = tid; d < HID; d += 256) {
        sq[d] = sq[d] * rsq * qnw[d];
        sk[d] = sk[d] * rsk * knw[d];
    }
    __syncthreads();
    const float* rp = g_rope + (size_t)t * 128;
    for (int idx = tid; idx < NHEADS * 64; idx += 256) {
        int hh = idx >> 6, i = idx & 63;
        float cs = rp[i], sn = rp[64 + i];
        int d1 = hh * HDIM + i, d2 = d1 + 64;
        float q1 = sq[d1], q2 = sq[d2], k1 = sk[d1], k2 = sk[d2];
        size_t base = (size_t)t * HID;
        g_rq[base + d1] = q1 * cs - q2 * sn;
        g_rq[base + d2] = q2 * cs + q1 * sn;
        g_rk[base + d1] = k1 * cs - k2 * sn;
        g_rk[base + d2] = k2 * cs + k1 * sn;
    }
    __syncthreads();
    for (int d = tid; d < HID; d += 256) {
        float xq = sq[d] * qksc[2 * d]     + qkof[2 * d];
        float xk = sk[d] * qksc[2 * d + 1] + qkof[2 * d + 1];
        float a = siluf(xq), b = siluf(xk);
        sq[d] = a; sk[d] = b;
        int g = d >> 9;
        atomicAdd(&gsum[g],     a * a);
        atomicAdd(&gsum[4 + g], b * b);
        float sv = siluf(vrow[d]);
        size_t o = ((size_t)g * S_LEN + t) * FD + (d & 511);
        g_fv[o] = sv;
        h_fv[o] = __float2half(sv);
    }
    __syncthreads();
    for (int d = tid; d < HID; d += 256) {
        int g = d >> 9;
        float nq = fmaxf(sqrtf(gsum[g]),     1e-12f);
        float nk = fmaxf(sqrtf(gsum[4 + g]), 1e-12f);
        size_t o = ((size_t)g * S_LEN + t) * FD + (d & 511);
        h_fq[o] = __float2half(sq[d] / nq);
        h_fk[o] = __float2half(sk[d] / nk);
    }
    // mamba LR from dedicated GEMM output
    if (tid < 12) {
        float z = g_lrraw[(size_t)t * 128 + tid] + lrb[tid] - 6.90725523731f;
        float sp = (z > 0.f) ? z + log1pf(expf(-z)) : log1pf(expf(z));
        g_lr[(size_t)t * 12 + tid] = sp;
    }
}

// ---------------- sliding-window attention (bank-conflict-free) ----------------
#define AR 132
#define ASM_FLOATS (3*32*AR + 32*36)    // 13824
__global__ void __launch_bounds__(256) attn_kernel()
{
    extern __shared__ float sh[];
    float* sQ = sh;                 // 32 x 132
    float* sK = sh + 32 * AR;       // 32 x 132
    float* sV = sh + 64 * AR;       // 32 x 132
    float* sP = sh + 96 * AR;       // 32 x 36
    int head = blockIdx.y;
    int q0 = blockIdx.x * 32;
    int tid = threadIdx.x;
    int row = tid >> 3, sub = tid & 7;
    const float qs = 0.08838834764831845f;

    for (int i = tid; i < 32 * 32; i += 256) {
        int r = i >> 5, c4 = (i & 31) << 2;
        float4 v = *(const float4*)(g_rq + (size_t)(q0 + r) * HID + head * HDIM + c4);
        v.x *= qs; v.y *= qs; v.z *= qs; v.w *= qs;
        *(float4*)(sQ + r * AR + c4) = v;
    }

    float oacc[16];
    #pragma unroll
    for (int j = 0; j < 16; j++) oacc[j] = 0.f;
    float m = -1e30f, l = 0.f;
    int qpos = q0 + row;

    for (int it = 0; it < 9; it++) {
        int kb = q0 - 256 + it * 32;
        if (kb + 32 <= 0) continue;
        __syncthreads();
        for (int i = tid; i < 32 * 32; i += 256) {
            int r = i >> 5, c4 = (i & 31) << 2;
            int kpos = kb + r;
            float4 kv = make_float4(0.f,0.f,0.f,0.f), vv = kv;
            if (kpos >= 0) {
                kv = *(const float4*)(g_rk  + (size_t)kpos * HID  + head * HDIM + c4);
                vv = *(const float4*)(g_qkv + (size_t)kpos * QKV3 + 2 * HID + head * HDIM + c4);
            }
            *(float4*)(sK + r * AR + c4) = kv;
            *(float4*)(sV + r * AR + c4) = vv;
        }
        __syncthreads();
        float s[4];
        bool ok[4];
        #pragma unroll
        for (int j = 0; j < 4; j++) {
            int kpos = kb + sub + 8 * j;
            ok[j] = (kpos >= 0) && (kpos <= qpos) && (kpos >= qpos - 255);
            s[j] = 0.f;
        }
        const float4* qp = (const float4*)(sQ + row * AR);
        #pragma unroll 8
        for (int d4 = 0; d4 < 32; d4++) {
            float4 a = qp[d4];
            #pragma unroll
            for (int j = 0; j < 4; j++) {
                float4 b = *(const float4*)(sK + (sub + 8 * j) * AR + d4 * 4);
                s[j] += a.x*b.x + a.y*b.y + a.z*b.z + a.w*b.w;
            }
        }
        float tmax = -1e30f;
        #pragma unroll
        for (int j = 0; j < 4; j++) { if (!ok[j]) s[j] = -1e30f; tmax = fmaxf(tmax, s[j]); }
        #pragma unroll
        for (int o = 4; o > 0; o >>= 1) tmax = fmaxf(tmax, __shfl_xor_sync(0xffffffffu, tmax, o, 8));
        float mnew = fmaxf(m, tmax);
        float scale = expf(m - mnew);
        float p[4], ps = 0.f;
        #pragma unroll
        for (int j = 0; j < 4; j++) { p[j] = ok[j] ? expf(s[j] - mnew) : 0.f; ps += p[j]; }
        #pragma unroll
        for (int o = 4; o > 0; o >>= 1) ps += __shfl_xor_sync(0xffffffffu, ps, o, 8);
        l = l * scale + ps;
        m = mnew;
        #pragma unroll
        for (int j = 0; j < 16; j++) oacc[j] *= scale;
        #pragma unroll
        for (int j = 0; j < 4; j++) sP[row * 36 + sub + 8 * j] = p[j];
        __syncwarp();
        #pragma unroll 4
        for (int k = 0; k < 32; k++) {
            float pk = sP[row * 36 + k];
            #pragma unroll
            for (int jj = 0; jj < 4; jj++) {
                float4 v = *(const float4*)(sV + k * AR + sub * 4 + 32 * jj);
                oacc[jj*4+0] += pk*v.x; oacc[jj*4+1] += pk*v.y;
                oacc[jj*4+2] += pk*v.z; oacc[jj*4+3] += pk*v.w;
            }
        }
    }
    float inv = 1.f / l;
    #pragma unroll
    for (int jj = 0; jj < 4; jj++) {
        float4 v;
        v.x = oacc[jj*4+0]*inv; v.y = oacc[jj*4+1]*inv;
        v.z = oacc[jj*4+2]*inv; v.w = oacc[jj*4+3]*inv;
        *(float4*)(g_attn + (size_t)qpos * HID + head * HDIM + sub * 4 + 32 * jj) = v;
    }
}

// ---------------- TTT elementwise + transposes ----------------
__global__ void __launch_bounds__(256) ttt_elem_t(int c0)
{
    __shared__ float t0[32][33], t1[32][33], t2[32][33], t3[32][33], t4[32][33];
    int h = blockIdx.z;
    int cb = blockIdx.x * 32, db = blockIdx.y * 32;
    int x = threadIdx.x, y = threadIdx.y;
    size_t base  = (size_t)h * CHUNK * FD;
    size_t baseP = (size_t)h * CHUNK * 1024;
    #pragma unroll
    for (int i = 0; i < 4; i++) {
        int cy = y + i * 8;
        int c = cb + cy, d = db + x;
        size_t idx  = base  + (size_t)c * FD + d;
        size_t idxP = baseP + (size_t)c * 1024 + d;
        int t = c0 + c;
        float lr0 = g_lr[(size_t)t * 12 + h];
        float lr1 = g_lr[(size_t)t * 12 + 4 + h];
        float lr2 = g_lr[(size_t)t * 12 + 8 + h];
        float gq = g_pq[idxP], hmq = g_pq[idxP + 512];
        h_gq[idx] = __float2half(siluf(gq) * hmq);
        float gk = g_pk[idxP], hmk = g_pk[idxP + 512], dh = g_dhid[idx];
        float sg = 1.f / (1.f + expf(-gk));
        float silug = gk * sg;
        t0[cy][x] = dh * hmk * (sg * (1.f + gk * (1.f - sg))) * lr0;
        t1[cy][x] = dh * silug * lr2;
        t2[cy][x] = silug * hmk;
        t3[cy][x] = g_fv[((size_t)h * S_LEN + t) * FD + d] * lr1;
        t4[cy][x] = __half2float(h_fk[((size_t)h * S_LEN + t) * FD + d]);
    }
    __syncthreads();
    size_t tb = ((size_t)h * FD + db) * CHUNK + cb;
    #pragma unroll
    for (int i = 0; i < 4; i++) {
        int dy = y + i * 8;
        size_t o = tb + (size_t)dy * CHUNK + x;
        h_t0[o] = __float2half(t0[x][dy]);
        h_t1[o] = __float2half(t1[x][dy]);
        h_t2[o] = __float2half(t2[x][dy]);
        h_t3[o] = __float2half(t3[x][dy]);
        h_t4[o] = __float2half(t4[x][dy]);
    }
}

// ---------------- rms_norm(o_fast) + attn add -> fp16 x ----------------
__global__ void __launch_bounds__(256) normadd_kernel(const float* __restrict__ tnw)
{
    __shared__ float ss[4];
    int t = blockIdx.x, tid = threadIdx.x;
    if (tid < 4) ss[tid] = 0.f;
    __syncthreads();
    float v[8];
    #pragma unroll
    for (int i = 0; i < 8; i++) {
        int d = i * 256 + tid;
        int h = d >> 9;
        float x = g_ofst[((size_t)h * S_LEN + t) * FD + (d & 511)];
        v[i] = x;
        float s = x * x;
        #pragma unroll
        for (int o = 16; o > 0; o >>= 1) s += __shfl_xor_sync(0xffffffffu, s, o);
        if ((tid & 31) == 0) atomicAdd(&ss[h], s);
    }
    __syncthreads();
    #pragma unroll
    for (int i = 0; i < 8; i++) {
        int d = i * 256 + tid;
        int h = d >> 9;
        float rn = rsqrtf(ss[h] * (1.f / FD) + 1e-6f);
        h_x[(size_t)t * HID + d] =
            __float2half(g_attn[(size_t)t * HID + d] + v[i] * rn * tnw[d & 511]);
    }
}

// ---------------- host ----------------
template<typename T>
static T* symaddr(const void* s)
{
    void* p = nullptr;
    cudaGetSymbolAddress(&p, s);
    return (T*)p;
}

extern "C" void kernel_launch(void* const* d_in, const int* in_sizes, int n_in,
                              void* d_out, int out_size)
{
    const float* hs    = (const float*)d_in[0];
    const float* qkv_w = (const float*)d_in[1];
    const float* qnw   = (const float*)d_in[2];
    const float* knw   = (const float*)d_in[3];
    const float* qksc  = (const float*)d_in[4];
    const float* qkof  = (const float*)d_in[5];
    const float* lrw   = (const float*)d_in[6];
    const float* lrb   = (const float*)d_in[7];
    const float* w0    = (const float*)d_in[8];
    const float* w1    = (const float*)d_in[9];
    const float* w2    = (const float*)d_in[10];
    const float* tnw   = (const float*)d_in[11];
    const float* opw   = (const float*)d_in[12];
    float* out = (float*)d_out;

    float*  p_qkv  = symaddr<float>(g_qkv);
    float*  p_lrr  = symaddr<float>(g_lrraw);
    float*  p_ofst = symaddr<float>(g_ofst);
    float*  p_w0   = symaddr<float>(g_w0);
    float*  p_w1   = symaddr<float>(g_w1);
    float*  p_w2   = symaddr<float>(g_w2);
    float*  p_pq   = symaddr<float>(g_pq);
    float*  p_pk   = symaddr<float>(g_pk);
    float*  p_dhid = symaddr<float>(g_dhid);
    float*  p_part = symaddr<float>(g_part);
    __half* ph_hs  = symaddr<__half>(h_hs);
    __half* ph_qw  = symaddr<__half>(h_qkvw);
    __half* ph_lw  = symaddr<__half>(h_lrw);
    __half* ph_ow  = symaddr<__half>(h_opw);
    __half* ph_x   = symaddr<__half>(h_x);
    __half* ph_fq  = symaddr<__half>(h_fq);
    __half* ph_fk  = symaddr<__half>(h_fk);
    __half* ph_fv  = symaddr<__half>(h_fv);
    __half* ph_gq  = symaddr<__half>(h_gq);
    __half* ph_t0  = symaddr<__half>(h_t0);
    __half* ph_t1  = symaddr<__half>(h_t1);
    __half* ph_t2  = symaddr<__half>(h_t2);
    __half* ph_t3  = symaddr<__half>(h_t3);
    __half* ph_t4  = symaddr<__half>(h_t4);
    __half* ph_w02 = symaddr<__half>(h_w02);
    __half* ph_w1  = symaddr<__half>(h_w1);
    __half* ph_w1T = symaddr<__half>(h_w1T);

    const size_t WB = sizeof(float) * NFW * FDFD;
    const size_t WE = (size_t)NFW * FDFD;
    const size_t sH = (size_t)S_LEN * FD;
    const size_t sC = (size_t)CHUNK * FD;
    const size_t sW = (size_t)FDFD;

    cudaFuncSetAttribute(mm_gen, cudaFuncAttributeMaxDynamicSharedMemorySize, GSMEM);
    cudaFuncSetAttribute(mm_fwd, cudaFuncAttributeMaxDynamicSharedMemorySize, GSMEM);
    cudaFuncSetAttribute(mm_upd, cudaFuncAttributeMaxDynamicSharedMemorySize, GSMEM);
    cudaFuncSetAttribute(attn_kernel, cudaFuncAttributeMaxDynamicSharedMemorySize, ASM_FLOATS * 4);

    cudaMemcpyAsync(p_w0, w0, WB, cudaMemcpyDeviceToDevice, 0);
    cudaMemcpyAsync(p_w1, w1, WB, cudaMemcpyDeviceToDevice, 0);
    cudaMemcpyAsync(p_w2, w2, WB, cudaMemcpyDeviceToDevice, 0);

    rope_tab<<<(S_LEN*64)/256, 256>>>();                                          // 0
    f2h<<<(S_LEN*HID)/2048, 256>>>(hs, ph_hs, (size_t)S_LEN*HID);                 // 1
    f2h<<<(QKV3*HID)/2048, 256>>>(qkv_w, ph_qw, (size_t)QKV3*HID);                // 2
    lrw_cvt<<<(128*HID)/2048, 256>>>(lrw, ph_lw);                                 // 3
    mm_gen<<<dim3(QKV3/128, S_LEN/128, 1), 256, GSMEM>>>(
        ph_hs, ph_qw, p_qkv, HID, HID, HID, QKV3, 0, 0, 0);                       // 4
    mm_gen<<<dim3(1, S_LEN/128, 1), 256, GSMEM>>>(
        ph_hs, ph_lw, p_lrr, HID, HID, HID, 128, 0, 0, 0);                        // 5
    preprocess_kernel<<<S_LEN, 256>>>(qnw, knw, qksc, qkof, lrb);                 // 6
    attn_kernel<<<dim3(S_LEN/32, NHEADS), 256, ASM_FLOATS * 4>>>();               // 7
    f2hw02<<<(NFW*1024*FD)/2048, 256>>>(p_w0, p_w2, ph_w02);                      // 8
    f2h<<<WE/2048, 256>>>(p_w1, ph_w1, WE);                                       // 9
    transpose_wh<<<dim3(16, 16, 4), dim3(32, 8)>>>(p_w1, ph_w1T);                 // 10
    f2h<<<(HID*HID)/2048, 256>>>(opw, ph_ow, (size_t)HID*HID);                    // 11

    // TTT scan
    for (int c = 0; c < 4; c++) {
        size_t co = (size_t)c * CHUNK * FD;
        int c0 = c * CHUNK;
        mm_fwd<<<dim3(8, 16, 8), 256, GSMEM>>>(ph_fq + co, ph_fk + co, ph_w02, p_pq, p_pk);
        mm_gen<<<dim3(4, 16, 4), 256, GSMEM>>>(ph_fv + co, ph_w1T, p_dhid,
            FD, FD, FD, FD, sH, sW, sC);
        ttt_elem_t<<<dim3(CHUNK/32, FD/32, NFW), dim3(32, 8)>>>(c0);
        mm_gen<<<dim3(4, 16, 4), 256, GSMEM>>>(ph_gq, ph_w1, p_ofst + co,
            FD, FD, FD, FD, sC, sW, sH);
        mm_upd<<<dim3(4, 4, 48), 256, GSMEM>>>(ph_t0, ph_t1, ph_t3, ph_t4, ph_t2, p_part);
        if (c < 3)
            wupdate<<<dim3(16, 16, 12), dim3(32, 8)>>>(
                p_w0, p_w1, p_w2, p_part, ph_w02, ph_w1, ph_w1T);
    }

    normadd_kernel<<<S_LEN, 256>>>(tnw);

    mm_gen<<<dim3(HID/128, S_LEN/128, 1), 256, GSMEM>>>(
        ph_x, ph_ow, out, HID, HID, HID, HID, 0, 0, 0);
}

// round 15
// speedup vs baseline: 3.3525x; 1.0047x over previous
#include <cuda_runtime.h>
#include <cuda_fp16.h>
#include <math.h>
#include <stdint.h>

#define S_LEN 8192
#define HID 2048
#define QKV3 (3*HID)
#define NHEADS 16
#define HDIM 128
#define NFW 4
#define FD 512
#define CHUNK 2048
#define FDFD (FD*FD)

// ---------------- fp32 scratch ----------------
static __device__ float g_qkv [(size_t)S_LEN*QKV3];
static __device__ float g_rq  [(size_t)S_LEN*HID];
static __device__ float g_rk  [(size_t)S_LEN*HID];
static __device__ float g_attn[(size_t)S_LEN*HID];
static __device__ float g_fv  [(size_t)NFW*S_LEN*FD];
static __device__ float g_ofst[(size_t)NFW*S_LEN*FD];
static __device__ float g_lr  [(size_t)S_LEN*12];
static __device__ float g_lrraw[(size_t)S_LEN*128];
static __device__ float g_rope[(size_t)S_LEN*128];
static __device__ float g_w0  [(size_t)NFW*FDFD];
static __device__ float g_w1  [(size_t)NFW*FDFD];
static __device__ float g_w2  [(size_t)NFW*FDFD];
static __device__ float g_pq  [(size_t)NFW*CHUNK*1024];   // [gq | hmq]
static __device__ float g_pk  [(size_t)NFW*CHUNK*1024];   // [gk | hmk]
static __device__ float g_dhid[(size_t)NFW*CHUNK*FD];
static __device__ float g_part[(size_t)48*FDFD];          // split-K partials
// ---------------- fp16 GEMM operands ----------------
static __device__ __half h_hs  [(size_t)S_LEN*HID];
static __device__ __half h_qkvw[(size_t)QKV3*HID];
static __device__ __half h_lrw [(size_t)128*HID];
static __device__ __half h_opw [(size_t)HID*HID];
static __device__ __half h_x   [(size_t)S_LEN*HID];
static __device__ __half h_fq  [(size_t)NFW*S_LEN*FD];
static __device__ __half h_fk  [(size_t)NFW*S_LEN*FD];
static __device__ __half h_fv  [(size_t)NFW*S_LEN*FD];
static __device__ __half h_gq  [(size_t)NFW*CHUNK*FD];
static __device__ __half h_t0 [(size_t)NFW*CHUNK*FD];
static __device__ __half h_t1 [(size_t)NFW*CHUNK*FD];
static __device__ __half h_t2 [(size_t)NFW*CHUNK*FD];
static __device__ __half h_t3 [(size_t)NFW*CHUNK*FD];
static __device__ __half h_t4 [(size_t)NFW*CHUNK*FD];
static __device__ __half h_w02[(size_t)NFW*1024*FD];      // [w0 rows ; w2 rows]
static __device__ __half h_w1 [(size_t)NFW*FDFD];
static __device__ __half h_w1T[(size_t)NFW*FDFD];

// ---------------- helpers ----------------
__device__ __forceinline__ void mma16(float* c, const uint32_t* a, const uint32_t* b)
{
    asm volatile(
        "mma.sync.aligned.m16n8k16.row.col.f32.f16.f16.f32 "
        "{%0,%1,%2,%3}, {%4,%5,%6,%7}, {%8,%9}, {%0,%1,%2,%3};"
        : "+f"(c[0]), "+f"(c[1]), "+f"(c[2]), "+f"(c[3])
        : "r"(a[0]), "r"(a[1]), "r"(a[2]), "r"(a[3]), "r"(b[0]), "r"(b[1]));
}
__device__ __forceinline__ void ldsm4(uint32_t* r, uint32_t addr)
{
    asm volatile("ldmatrix.sync.aligned.m8n8.x4.shared.b16 {%0,%1,%2,%3}, [%4];"
                 : "=r"(r[0]), "=r"(r[1]), "=r"(r[2]), "=r"(r[3]) : "r"(addr));
}
__device__ __forceinline__ uint32_t smem_u32(const void* p)
{
    uint32_t a;
    asm("{ .reg .u64 t; cvta.to.shared.u64 t, %1; cvt.u32.u64 %0, t; }" : "=r"(a) : "l"(p));
    return a;
}
__device__ __forceinline__ void cp16(uint32_t d, const void* g)
{
    asm volatile("cp.async.cg.shared.global [%0], [%1], 16;" :: "r"(d), "l"(g));
}
#define CP_COMMIT() asm volatile("cp.async.commit_group;" ::: "memory")
#define CP_WAIT1()  asm volatile("cp.async.wait_group 1;" ::: "memory")
#define CP_WAIT0()  asm volatile("cp.async.wait_group 0;" ::: "memory")

// ---------------- fp16 tensor GEMM body (parameterized tile origin) ----------------
#define STGB 32768
#define GSMEM (3*STGB)

__device__ __forceinline__ void gemm_body(
    const __half* __restrict__ A, const __half* __restrict__ B, float* __restrict__ C,
    int m0, int n0, int Ks, int lda, int ldb, int ldc, __half* smh)
{
    const int tid = threadIdx.x, warp = tid >> 5, lane = tid & 31;
    const int wm = (warp >> 1) * 32, wn = (warp & 1) * 64;

    float acc[2][8][4];
    #pragma unroll
    for (int i = 0; i < 2; i++)
        #pragma unroll
        for (int j = 0; j < 8; j++)
            #pragma unroll
            for (int l = 0; l < 4; l++) acc[i][j][l] = 0.f;

    const int nst = Ks >> 6;
    const uint32_t smbase = smem_u32(smh);

    const int crow = tid >> 1;
    const int gb = (tid & 1) * 4;
    const __half* gA = A + (size_t)(m0 + crow) * lda + gb * 8;
    const __half* gB = B + (size_t)(n0 + crow) * ldb + gb * 8;
    const uint32_t wbase = (uint32_t)(crow * 128);
    const uint32_t wsw = (uint32_t)(crow & 7);

    #pragma unroll
    for (int s = 0; s < 2; s++) {
        uint32_t sa = smbase + s * STGB;
        #pragma unroll
        for (int i = 0; i < 4; i++) {
            uint32_t wo = wbase + (((uint32_t)(gb + i) ^ wsw) << 4);
            cp16(sa + wo,         gA + (s << 6) + i * 8);
            cp16(sa + 16384 + wo, gB + (s << 6) + i * 8);
        }
        CP_COMMIT();
    }

    const uint32_t sw = (uint32_t)(lane & 7);
    const uint32_t arowb = (uint32_t)((wm + (lane & 15)) * 128);
    const uint32_t browb = (uint32_t)((wn + ((lane >> 4) << 3) + (lane & 7)) * 128);
    const uint32_t agb = (uint32_t)(lane >> 4);
    const uint32_t bgb = (uint32_t)((lane >> 3) & 1);

    int st = 0;
    for (int s = 0; s < nst; s++) {
        if (s + 1 < nst) CP_WAIT1(); else CP_WAIT0();
        __syncthreads();
        if (s + 2 < nst) {
            uint32_t sa = smbase + ((s + 2) % 3) * STGB;
            #pragma unroll
            for (int i = 0; i < 4; i++) {
                uint32_t wo = wbase + (((uint32_t)(gb + i) ^ wsw) << 4);
                cp16(sa + wo,         gA + ((s + 2) << 6) + i * 8);
                cp16(sa + 16384 + wo, gB + ((s + 2) << 6) + i * 8);
            }
        }
        CP_COMMIT();
        const uint32_t sa = smbase + st * STGB;
        const uint32_t sb = sa + 16384;
        #pragma unroll
        for (int kt = 0; kt < 4; kt++) {
            const uint32_t axor = ((2 * kt + agb) ^ sw) << 4;
            const uint32_t bxor = ((2 * kt + bgb) ^ sw) << 4;
            uint32_t af[2][4];
            ldsm4(af[0], sa + arowb + axor);
            ldsm4(af[1], sa + arowb + 2048 + axor);
            #pragma unroll
            for (int p = 0; p < 4; p++) {
                uint32_t bf[4];
                ldsm4(bf, sb + browb + p * 2048 + bxor);
                mma16(acc[0][2 * p],     af[0], &bf[0]);
                mma16(acc[0][2 * p + 1], af[0], &bf[2]);
                mma16(acc[1][2 * p],     af[1], &bf[0]);
                mma16(acc[1][2 * p + 1], af[1], &bf[2]);
            }
        }
        st++; if (st == 3) st = 0;
    }

    const int gr = lane >> 2, gc = lane & 3;
    #pragma unroll
    for (int mt = 0; mt < 2; mt++) {
        #pragma unroll
        for (int nt = 0; nt < 8; nt++) {
            int row = m0 + wm + mt * 16 + gr;
            int col = n0 + wn + nt * 8 + 2 * gc;
            *(float2*)(C + (size_t)row * ldc + col) =
                make_float2(acc[mt][nt][0], acc[mt][nt][1]);
            *(float2*)(C + (size_t)(row + 8) * ldc + col) =
                make_float2(acc[mt][nt][2], acc[mt][nt][3]);
        }
    }
}

__global__ void __launch_bounds__(256, 2) mm_gen(
    const __half* __restrict__ A, const __half* __restrict__ B, float* __restrict__ C,
    int K, int lda, int ldb, int ldc, size_t sA, size_t sB, size_t sC)
{
    extern __shared__ __half smh[];
    int hh = blockIdx.z;
    gemm_body(A + sA * hh, B + sB * hh, C + sC * hh,
              blockIdx.y * 128, blockIdx.x * 128, K, lda, ldb, ldc, smh);
}

// fused forward: 1280 blocks. t<1024: pq/pk fwd; t>=1024: dhid.
__global__ void __launch_bounds__(256, 2) mm_fwd2(
    const __half* __restrict__ fq, const __half* __restrict__ fk,
    const __half* __restrict__ fv, const __half* __restrict__ w02,
    const __half* __restrict__ w1T,
    float* __restrict__ pq, float* __restrict__ pk, float* __restrict__ dhid)
{
    extern __shared__ __half smh[];
    int t = blockIdx.x;
    if (t < 1024) {
        int z = t >> 7, rem = t & 127, by = rem >> 3, bx = rem & 7;
        int which = z >> 2, hh = z & 3;
        const __half* A = (which ? fk : fq) + (size_t)hh * ((size_t)S_LEN * FD);
        const __half* B = w02 + (size_t)hh * (1024 * FD);
        float* C = (which ? pk : pq) + (size_t)hh * ((size_t)CHUNK * 1024);
        gemm_body(A, B, C, by * 128, bx * 128, FD, FD, FD, 1024, smh);
    } else {
        int u = t - 1024, z = u >> 6, rem = u & 63, by = rem >> 2, bx = rem & 3;
        const __half* A = fv + (size_t)z * ((size_t)S_LEN * FD);
        const __half* B = w1T + (size_t)z * FDFD;
        float* C = dhid + (size_t)z * ((size_t)CHUNK * FD);
        gemm_body(A, B, C, by * 128, bx * 128, FD, FD, FD, FD, smh);
    }
}

// fused updates + ofst: 1024 blocks. t<768: partials; t>=768: ofst (gq @ old w1).
__global__ void __launch_bounds__(256, 2) mm_upd2(
    const __half* __restrict__ t0, const __half* __restrict__ t1,
    const __half* __restrict__ t3, const __half* __restrict__ t4,
    const __half* __restrict__ t2, const __half* __restrict__ gq,
    const __half* __restrict__ w1, float* __restrict__ part, float* __restrict__ ofst)
{
    extern __shared__ __half smh[];
    int t = blockIdx.x;
    if (t < 768) {
        int z = t >> 4, rem = t & 15, by = rem >> 2, bx = rem & 3;
        int mat = z >> 4, r = z & 15, sl = r >> 2, hh = r & 3;
        const size_t sT = (size_t)FD * CHUNK;
        const __half* A = (mat == 0 ? t0 : mat == 1 ? t1 : t3)
                          + (size_t)hh * sT + sl * (CHUNK / 4);
        const __half* B = (mat < 2 ? t4 : t2)
                          + (size_t)hh * sT + sl * (CHUNK / 4);
        float* C = part + (size_t)z * FDFD;
        gemm_body(A, B, C, by * 128, bx * 128, CHUNK / 4, CHUNK, CHUNK, FD, smh);
    } else {
        int u = t - 768, z = u >> 6, rem = u & 63, by = rem >> 2, bx = rem & 3;
        const __half* A = gq + (size_t)z * ((size_t)CHUNK * FD);
        const __half* B = w1 + (size_t)z * FDFD;
        float* C = ofst + (size_t)z * ((size_t)S_LEN * FD);
        gemm_body(A, B, C, by * 128, bx * 128, FD, FD, FD, FD, smh);
    }
}

// ---------------- fused weight update + fp16 refresh ----------------
__global__ void __launch_bounds__(256) wupdate(
    float* __restrict__ w0, float* __restrict__ w1, float* __restrict__ w2,
    const float* __restrict__ part,
    __half* __restrict__ w02h, __half* __restrict__ w1h, __half* __restrict__ w1Th)
{
    __shared__ float t[32][33];
    int z = blockIdx.z, mat = z >> 2, h = z & 3;
    int c0 = blockIdx.x * 32, r0 = blockIdx.y * 32;
    int x = threadIdx.x, y = threadIdx.y;
    float* master = (mat == 0 ? w0 : mat == 1 ? w2 : w1) + (size_t)h * FDFD;
    const float* p = part + ((size_t)(mat * 16 + h)) * FDFD;
    #pragma unroll
    for (int i = 0; i < 4; i++) {
        int r = r0 + y + i * 8, c = c0 + x;
        size_t idx = (size_t)r * FD + c;
        float s = master[idx] + p[idx] + p[idx + (size_t)4 * FDFD]
                + p[idx + (size_t)8 * FDFD] + p[idx + (size_t)12 * FDFD];
        master[idx] = s;
        __half hv = __float2half(s);
        if (mat == 0)      w02h[(size_t)h * 1024 * FD + idx] = hv;
        else if (mat == 1) w02h[(size_t)h * 1024 * FD + (size_t)512 * FD + idx] = hv;
        else { w1h[(size_t)h * FDFD + idx] = hv; t[y + i * 8][x] = s; }
    }
    if (mat == 2) {
        __syncthreads();
        #pragma unroll
        for (int i = 0; i < 4; i++)
            w1Th[(size_t)h * FDFD + (size_t)(c0 + y + i * 8) * FD + r0 + x] =
                __float2half(t[x][y + i * 8]);
    }
}

// ---------------- converts ----------------
__global__ void __launch_bounds__(256) f2h(const float* __restrict__ s, __half* __restrict__ d, size_t n)
{
    size_t i = ((size_t)blockIdx.x * 256 + threadIdx.x) * 8;
    if (i >= n) return;
    float4 a = *(const float4*)(s + i), b = *(const float4*)(s + i + 4);
    __half2 q0 = __floats2half2_rn(a.x, a.y), q1 = __floats2half2_rn(a.z, a.w);
    __half2 q2 = __floats2half2_rn(b.x, b.y), q3 = __floats2half2_rn(b.z, b.w);
    uint4 u;
    u.x = *(uint32_t*)&q0; u.y = *(uint32_t*)&q1; u.z = *(uint32_t*)&q2; u.w = *(uint32_t*)&q3;
    *(uint4*)(d + i) = u;
}

__global__ void __launch_bounds__(256) lrw_cvt(const float* __restrict__ lw, __half* __restrict__ dst)
{
    size_t i = ((size_t)blockIdx.x * 256 + threadIdx.x) * 8;
    int row = (int)(i >> 11);
    int col = (int)(i & 2047);
    float4 a = make_float4(0.f,0.f,0.f,0.f), b = a;
    if (row < 12) {
        const float* s = lw + (size_t)row * HID + col;
        a = *(const float4*)s; b = *(const float4*)(s + 4);
    }
    __half2 q0 = __floats2half2_rn(a.x, a.y), q1 = __floats2half2_rn(a.z, a.w);
    __half2 q2 = __floats2half2_rn(b.x, b.y), q3 = __floats2half2_rn(b.z, b.w);
    uint4 u;
    u.x = *(uint32_t*)&q0; u.y = *(uint32_t*)&q1; u.z = *(uint32_t*)&q2; u.w = *(uint32_t*)&q3;
    *(uint4*)(dst + i) = u;
}

__global__ void __launch_bounds__(256) f2hw02(const float* __restrict__ w0, const float* __restrict__ w2,
                                              __half* __restrict__ dst)
{
    size_t i = ((size_t)blockIdx.x * 256 + threadIdx.x) * 8;
    int h = (int)(i >> 19);
    int r = (int)((i >> 9) & 1023);
    int c = (int)(i & 511);
    const float* src = (r < 512 ? w0 + ((size_t)h * FD + r) * FD
                                : w2 + ((size_t)h * FD + (r - 512)) * FD) + c;
    float4 a = *(const float4*)src, b = *(const float4*)(src + 4);
    __half2 q0 = __floats2half2_rn(a.x, a.y), q1 = __floats2half2_rn(a.z, a.w);
    __half2 q2 = __floats2half2_rn(b.x, b.y), q3 = __floats2half2_rn(b.z, b.w);
    uint4 u;
    u.x = *(uint32_t*)&q0; u.y = *(uint32_t*)&q1; u.z = *(uint32_t*)&q2; u.w = *(uint32_t*)&q3;
    *(uint4*)(dst + i) = u;
}

__global__ void __launch_bounds__(256) transpose_wh(const float* __restrict__ src, __half* __restrict__ dst)
{
    __shared__ float t[32][33];
    int h = blockIdx.z;
    int i0 = blockIdx.x * 32, j0 = blockIdx.y * 32;
    int x = threadIdx.x, y = threadIdx.y;
    const float* s = src + (size_t)h * FDFD;
    __half* d = dst + (size_t)h * FDFD;
    #pragma unroll
    for (int i = 0; i < 4; i++) t[y + i * 8][x] = s[(size_t)(j0 + y + i * 8) * FD + i0 + x];
    __syncthreads();
    #pragma unroll
    for (int i = 0; i < 4; i++) d[(size_t)(i0 + y + i * 8) * FD + j0 + x] = __float2half(t[x][y + i * 8]);
}

// ---------------- RoPE table (one-time) ----------------
__global__ void __launch_bounds__(256) rope_tab()
{
    int idx = blockIdx.x * 256 + threadIdx.x;
    int t = idx >> 6, i = idx & 63;
    float freq = (float)exp(-(double)i * (13.122363377404328 / 64.0));
    float sn, cs;
    sincosf((float)t * freq, &sn, &cs);
    g_rope[(size_t)t * 128 + i] = cs;
    g_rope[(size_t)t * 128 + 64 + i] = sn;
}

// ---------------- utils ----------------
__device__ __forceinline__ float blockReduceSum256(float v)
{
    __shared__ float red[8];
    #pragma unroll
    for (int o = 16; o > 0; o >>= 1) v += __shfl_xor_sync(0xffffffffu, v, o);
    if ((threadIdx.x & 31) == 0) red[threadIdx.x >> 5] = v;
    __syncthreads();
    if (threadIdx.x < 32) {
        float x = (threadIdx.x < 8) ? red[threadIdx.x] : 0.f;
        #pragma unroll
        for (int o = 4; o > 0; o >>= 1) x += __shfl_xor_sync(0xffffffffu, x, o);
        if (threadIdx.x == 0) red[0] = x;
    }
    __syncthreads();
    float r = red[0];
    __syncthreads();
    return r;
}
__device__ __forceinline__ float siluf(float x) { return x / (1.f + expf(-x)); }

// ---------------- per-token preprocess ----------------
__global__ void __launch_bounds__(256) preprocess_kernel(
    const float* __restrict__ qnw, const float* __restrict__ knw,
    const float* __restrict__ qksc, const float* __restrict__ qkof,
    const float* __restrict__ lrb)
{
    __shared__ float sq[HID];
    __shared__ float sk[HID];
    __shared__ float gsum[8];
    int t = blockIdx.x, tid = threadIdx.x;

    if (tid < 8) gsum[tid] = 0.f;

    const float* qrow = g_qkv + (size_t)t * QKV3;
    const float* krow = qrow + HID;
    const float* vrow = qrow + 2 * HID;

    float ssq = 0.f, ssk = 0.f;
    for (int d = tid; d < HID; d += 256) {
        float a = qrow[d]; sq[d] = a; ssq += a * a;
        float b = krow[d]; sk[d] = b; ssk += b * b;
    }
    ssq = blockReduceSum256(ssq);
    ssk = blockReduceSum256(ssk);
    float rsq = rsqrtf(ssq * (1.f / HID) + 1e-6f);
    float rsk = rsqrtf(ssk * (1.f / HID) + 1e-6f);
    for (int d = tid; d < HID; d += 256) {
        sq[d] = sq[d] * rsq * qnw[d];
        sk[d] = sk[d] * rsk * knw[d];
    }
    __syncthreads();
    const float* rp = g_rope + (size_t)t * 128;
    for (int idx = tid; idx < NHEADS * 64; idx += 256) {
        int hh = idx >> 6, i = idx & 63;
        float cs = rp[i], sn = rp[64 + i];
        int d1 = hh * HDIM + i, d2 = d1 + 64;
        float q1 = sq[d1], q2 = sq[d2], k1 = sk[d1], k2 = sk[d2];
        size_t base = (size_t)t * HID;
        g_rq[base + d1] = q1 * cs - q2 * sn;
        g_rq[base + d2] = q2 * cs + q1 * sn;
        g_rk[base + d1] = k1 * cs - k2 * sn;
        g_rk[base + d2] = k2 * cs + k1 * sn;
    }
    __syncthreads();
    for (int d = tid; d < HID; d += 256) {
        float xq = sq[d] * qksc[2 * d]     + qkof[2 * d];
        float xk = sk[d] * qksc[2 * d + 1] + qkof[2 * d + 1];
        float a = siluf(xq), b = siluf(xk);
        sq[d] = a; sk[d] = b;
        int g = d >> 9;
        atomicAdd(&gsum[g],     a * a);
        atomicAdd(&gsum[4 + g], b * b);
        float sv = siluf(vrow[d]);
        size_t o = ((size_t)g * S_LEN + t) * FD + (d & 511);
        g_fv[o] = sv;
        h_fv[o] = __float2half(sv);
    }
    __syncthreads();
    for (int d = tid; d < HID; d += 256) {
        int g = d >> 9;
        float nq = fmaxf(sqrtf(gsum[g]),     1e-12f);
        float nk = fmaxf(sqrtf(gsum[4 + g]), 1e-12f);
        size_t o = ((size_t)g * S_LEN + t) * FD + (d & 511);
        h_fq[o] = __float2half(sq[d] / nq);
        h_fk[o] = __float2half(sk[d] / nk);
    }
    if (tid < 12) {
        float z = g_lrraw[(size_t)t * 128 + tid] + lrb[tid] - 6.90725523731f;
        float sp = (z > 0.f) ? z + log1pf(expf(-z)) : log1pf(expf(z));
        g_lr[(size_t)t * 12 + tid] = sp;
    }
}

// ---------------- sliding-window attention (bank-conflict-free) ----------------
#define AR 132
#define ASM_FLOATS (3*32*AR + 32*36)    // 13824
__global__ void __launch_bounds__(256) attn_kernel()
{
    extern __shared__ float sh[];
    float* sQ = sh;
    float* sK = sh + 32 * AR;
    float* sV = sh + 64 * AR;
    float* sP = sh + 96 * AR;
    int head = blockIdx.y;
    int q0 = blockIdx.x * 32;
    int tid = threadIdx.x;
    int row = tid >> 3, sub = tid & 7;
    const float qs = 0.08838834764831845f;

    for (int i = tid; i < 32 * 32; i += 256) {
        int r = i >> 5, c4 = (i & 31) << 2;
        float4 v = *(const float4*)(g_rq + (size_t)(q0 + r) * HID + head * HDIM + c4);
        v.x *= qs; v.y *= qs; v.z *= qs; v.w *= qs;
        *(float4*)(sQ + r * AR + c4) = v;
    }

    float oacc[16];
    #pragma unroll
    for (int j = 0; j < 16; j++) oacc[j] = 0.f;
    float m = -1e30f, l = 0.f;
    int qpos = q0 + row;

    for (int it = 0; it < 9; it++) {
        int kb = q0 - 256 + it * 32;
        if (kb + 32 <= 0) continue;
        __syncthreads();
        for (int i = tid; i < 32 * 32; i += 256) {
            int r = i >> 5, c4 = (i & 31) << 2;
            int kpos = kb + r;
            float4 kv = make_float4(0.f,0.f,0.f,0.f), vv = kv;
            if (kpos >= 0) {
                kv = *(const float4*)(g_rk  + (size_t)kpos * HID  + head * HDIM + c4);
                vv = *(const float4*)(g_qkv + (size_t)kpos * QKV3 + 2 * HID + head * HDIM + c4);
            }
            *(float4*)(sK + r * AR + c4) = kv;
            *(float4*)(sV + r * AR + c4) = vv;
        }
        __syncthreads();
        float s[4];
        bool ok[4];
        #pragma unroll
        for (int j = 0; j < 4; j++) {
            int kpos = kb + sub + 8 * j;
            ok[j] = (kpos >= 0) && (kpos <= qpos) && (kpos >= qpos - 255);
            s[j] = 0.f;
        }
        const float4* qp = (const float4*)(sQ + row * AR);
        #pragma unroll 8
        for (int d4 = 0; d4 < 32; d4++) {
            float4 a = qp[d4];
            #pragma unroll
            for (int j = 0; j < 4; j++) {
                float4 b = *(const float4*)(sK + (sub + 8 * j) * AR + d4 * 4);
                s[j] += a.x*b.x + a.y*b.y + a.z*b.z + a.w*b.w;
            }
        }
        float tmax = -1e30f;
        #pragma unroll
        for (int j = 0; j < 4; j++) { if (!ok[j]) s[j] = -1e30f; tmax = fmaxf(tmax, s[j]); }
        #pragma unroll
        for (int o = 4; o > 0; o >>= 1) tmax = fmaxf(tmax, __shfl_xor_sync(0xffffffffu, tmax, o, 8));
        float mnew = fmaxf(m, tmax);
        float scale = expf(m - mnew);
        float p[4], ps = 0.f;
        #pragma unroll
        for (int j = 0; j < 4; j++) { p[j] = ok[j] ? expf(s[j] - mnew) : 0.f; ps += p[j]; }
        #pragma unroll
        for (int o = 4; o > 0; o >>= 1) ps += __shfl_xor_sync(0xffffffffu, ps, o, 8);
        l = l * scale + ps;
        m = mnew;
        #pragma unroll
        for (int j = 0; j < 16; j++) oacc[j] *= scale;
        #pragma unroll
        for (int j = 0; j < 4; j++) sP[row * 36 + sub + 8 * j] = p[j];
        __syncwarp();
        #pragma unroll 4
        for (int k = 0; k < 32; k++) {
            float pk = sP[row * 36 + k];
            #pragma unroll
            for (int jj = 0; jj < 4; jj++) {
                float4 v = *(const float4*)(sV + k * AR + sub * 4 + 32 * jj);
                oacc[jj*4+0] += pk*v.x; oacc[jj*4+1] += pk*v.y;
                oacc[jj*4+2] += pk*v.z; oacc[jj*4+3] += pk*v.w;
            }
        }
    }
    float inv = 1.f / l;
    #pragma unroll
    for (int jj = 0; jj < 4; jj++) {
        float4 v;
        v.x = oacc[jj*4+0]*inv; v.y = oacc[jj*4+1]*inv;
        v.z = oacc[jj*4+2]*inv; v.w = oacc[jj*4+3]*inv;
        *(float4*)(g_attn + (size_t)qpos * HID + head * HDIM + sub * 4 + 32 * jj) = v;
    }
}

// ---------------- TTT elementwise + transposes ----------------
__global__ void __launch_bounds__(256) ttt_elem_t(int c0)
{
    __shared__ float t0[32][33], t1[32][33], t2[32][33], t3[32][33], t4[32][33];
    int h = blockIdx.z;
    int cb = blockIdx.x * 32, db = blockIdx.y * 32;
    int x = threadIdx.x, y = threadIdx.y;
    size_t base  = (size_t)h * CHUNK * FD;
    size_t baseP = (size_t)h * CHUNK * 1024;
    #pragma unroll
    for (int i = 0; i < 4; i++) {
        int cy = y + i * 8;
        int c = cb + cy, d = db + x;
        size_t idx  = base  + (size_t)c * FD + d;
        size_t idxP = baseP + (size_t)c * 1024 + d;
        int t = c0 + c;
        float lr0 = g_lr[(size_t)t * 12 + h];
        float lr1 = g_lr[(size_t)t * 12 + 4 + h];
        float lr2 = g_lr[(size_t)t * 12 + 8 + h];
        float gq = g_pq[idxP], hmq = g_pq[idxP + 512];
        h_gq[idx] = __float2half(siluf(gq) * hmq);
        float gk = g_pk[idxP], hmk = g_pk[idxP + 512], dh = g_dhid[idx];
        float sg = 1.f / (1.f + expf(-gk));
        float silug = gk * sg;
        t0[cy][x] = dh * hmk * (sg * (1.f + gk * (1.f - sg))) * lr0;
        t1[cy][x] = dh * silug * lr2;
        t2[cy][x] = silug * hmk;
        t3[cy][x] = g_fv[((size_t)h * S_LEN + t) * FD + d] * lr1;
        t4[cy][x] = __half2float(h_fk[((size_t)h * S_LEN + t) * FD + d]);
    }
    __syncthreads();
    size_t tb = ((size_t)h * FD + db) * CHUNK + cb;
    #pragma unroll
    for (int i = 0; i < 4; i++) {
        int dy = y + i * 8;
        size_t o = tb + (size_t)dy * CHUNK + x;
        h_t0[o] = __float2half(t0[x][dy]);
        h_t1[o] = __float2half(t1[x][dy]);
        h_t2[o] = __float2half(t2[x][dy]);
        h_t3[o] = __float2half(t3[x][dy]);
        h_t4[o] = __float2half(t4[x][dy]);
    }
}

// ---------------- rms_norm(o_fast) + attn add -> fp16 x ----------------
__global__ void __launch_bounds__(256) normadd_kernel(const float* __restrict__ tnw)
{
    __shared__ float ss[4];
    int t = blockIdx.x, tid = threadIdx.x;
    if (tid < 4) ss[tid] = 0.f;
    __syncthreads();
    float v[8];
    #pragma unroll
    for (int i = 0; i < 8; i++) {
        int d = i * 256 + tid;
        int h = d >> 9;
        float x = g_ofst[((size_t)h * S_LEN + t) * FD + (d & 511)];
        v[i] = x;
        float s = x * x;
        #pragma unroll
        for (int o = 16; o > 0; o >>= 1) s += __shfl_xor_sync(0xffffffffu, s, o);
        if ((tid & 31) == 0) atomicAdd(&ss[h], s);
    }
    __syncthreads();
    #pragma unroll
    for (int i = 0; i < 8; i++) {
        int d = i * 256 + tid;
        int h = d >> 9;
        float rn = rsqrtf(ss[h] * (1.f / FD) + 1e-6f);
        h_x[(size_t)t * HID + d] =
            __float2half(g_attn[(size_t)t * HID + d] + v[i] * rn * tnw[d & 511]);
    }
}

// ---------------- host ----------------
template<typename T>
static T* symaddr(const void* s)
{
    void* p = nullptr;
    cudaGetSymbolAddress(&p, s);
    return (T*)p;
}

extern "C" void kernel_launch(void* const* d_in, const int* in_sizes, int n_in,
                              void* d_out, int out_size)
{
    const float* hs    = (const float*)d_in[0];
    const float* qkv_w = (const float*)d_in[1];
    const float* qnw   = (const float*)d_in[2];
    const float* knw   = (const float*)d_in[3];
    const float* qksc  = (const float*)d_in[4];
    const float* qkof  = (const float*)d_in[5];
    const float* lrw   = (const float*)d_in[6];
    const float* lrb   = (const float*)d_in[7];
    const float* w0    = (const float*)d_in[8];
    const float* w1    = (const float*)d_in[9];
    const float* w2    = (const float*)d_in[10];
    const float* tnw   = (const float*)d_in[11];
    const float* opw   = (const float*)d_in[12];
    float* out = (float*)d_out;

    float*  p_qkv  = symaddr<float>(g_qkv);
    float*  p_lrr  = symaddr<float>(g_lrraw);
    float*  p_ofst = symaddr<float>(g_ofst);
    float*  p_w0   = symaddr<float>(g_w0);
    float*  p_w1   = symaddr<float>(g_w1);
    float*  p_w2   = symaddr<float>(g_w2);
    float*  p_pq   = symaddr<float>(g_pq);
    float*  p_pk   = symaddr<float>(g_pk);
    float*  p_dhid = symaddr<float>(g_dhid);
    float*  p_part = symaddr<float>(g_part);
    __half* ph_hs  = symaddr<__half>(h_hs);
    __half* ph_qw  = symaddr<__half>(h_qkvw);
    __half* ph_lw  = symaddr<__half>(h_lrw);
    __half* ph_ow  = symaddr<__half>(h_opw);
    __half* ph_x   = symaddr<__half>(h_x);
    __half* ph_fq  = symaddr<__half>(h_fq);
    __half* ph_fk  = symaddr<__half>(h_fk);
    __half* ph_fv  = symaddr<__half>(h_fv);
    __half* ph_gq  = symaddr<__half>(h_gq);
    __half* ph_t0  = symaddr<__half>(h_t0);
    __half* ph_t1  = symaddr<__half>(h_t1);
    __half* ph_t2  = symaddr<__half>(h_t2);
    __half* ph_t3  = symaddr<__half>(h_t3);
    __half* ph_t4  = symaddr<__half>(h_t4);
    __half* ph_w02 = symaddr<__half>(h_w02);
    __half* ph_w1  = symaddr<__half>(h_w1);
    __half* ph_w1T = symaddr<__half>(h_w1T);

    const size_t WB = sizeof(float) * NFW * FDFD;
    const size_t WE = (size_t)NFW * FDFD;

    cudaFuncSetAttribute(mm_gen,  cudaFuncAttributeMaxDynamicSharedMemorySize, GSMEM);
    cudaFuncSetAttribute(mm_fwd2, cudaFuncAttributeMaxDynamicSharedMemorySize, GSMEM);
    cudaFuncSetAttribute(mm_upd2, cudaFuncAttributeMaxDynamicSharedMemorySize, GSMEM);
    cudaFuncSetAttribute(attn_kernel, cudaFuncAttributeMaxDynamicSharedMemorySize, ASM_FLOATS * 4);

    cudaMemcpyAsync(p_w0, w0, WB, cudaMemcpyDeviceToDevice, 0);
    cudaMemcpyAsync(p_w1, w1, WB, cudaMemcpyDeviceToDevice, 0);
    cudaMemcpyAsync(p_w2, w2, WB, cudaMemcpyDeviceToDevice, 0);

    rope_tab<<<(S_LEN*64)/256, 256>>>();                                          // 0
    f2h<<<(S_LEN*HID)/2048, 256>>>(hs, ph_hs, (size_t)S_LEN*HID);                 // 1
    f2h<<<(QKV3*HID)/2048, 256>>>(qkv_w, ph_qw, (size_t)QKV3*HID);                // 2
    lrw_cvt<<<(128*HID)/2048, 256>>>(lrw, ph_lw);                                 // 3
    mm_gen<<<dim3(QKV3/128, S_LEN/128, 1), 256, GSMEM>>>(
        ph_hs, ph_qw, p_qkv, HID, HID, HID, QKV3, 0, 0, 0);                       // 4
    mm_gen<<<dim3(1, S_LEN/128, 1), 256, GSMEM>>>(
        ph_hs, ph_lw, p_lrr, HID, HID, HID, 128, 0, 0, 0);                        // 5
    preprocess_kernel<<<S_LEN, 256>>>(qnw, knw, qksc, qkof, lrb);                 // 6
    attn_kernel<<<dim3(S_LEN/32, NHEADS), 256, ASM_FLOATS * 4>>>();               // 7
    f2hw02<<<(NFW*1024*FD)/2048, 256>>>(p_w0, p_w2, ph_w02);                      // 8
    f2h<<<WE/2048, 256>>>(p_w1, ph_w1, WE);                                       // 9
    transpose_wh<<<dim3(16, 16, 4), dim3(32, 8)>>>(p_w1, ph_w1T);                 // 10
    f2h<<<(HID*HID)/2048, 256>>>(opw, ph_ow, (size_t)HID*HID);                    // 11

    // TTT scan (4 launches/chunk)
    for (int c = 0; c < 4; c++) {
        size_t co = (size_t)c * CHUNK * FD;
        int c0 = c * CHUNK;
        mm_fwd2<<<1280, 256, GSMEM>>>(ph_fq + co, ph_fk + co, ph_fv + co,
                                      ph_w02, ph_w1T, p_pq, p_pk, p_dhid);
        ttt_elem_t<<<dim3(CHUNK/32, FD/32, NFW), dim3(32, 8)>>>(c0);
        mm_upd2<<<1024, 256, GSMEM>>>(ph_t0, ph_t1, ph_t3, ph_t4, ph_t2,
                                      ph_gq, ph_w1, p_part, p_ofst + co);
        if (c < 3)
            wupdate<<<dim3(16, 16, 12), dim3(32, 8)>>>(
                p_w0, p_w1, p_w2, p_part, ph_w02, ph_w1, ph_w1T);
    }

    normadd_kernel<<<S_LEN, 256>>>(tnw);

    mm_gen<<<dim3(HID/128, S_LEN/128, 1), 256, GSMEM>>>(
        ph_x, ph_ow, out, HID, HID, HID, HID, 0, 0, 0);
}

// round 16
// speedup vs baseline: 3.3571x; 1.0014x over previous
#include <cuda_runtime.h>
#include <cuda_fp16.h>
#include <math.h>
#include <stdint.h>

#define S_LEN 8192
#define HID 2048
#define QKV3 (3*HID)
#define NHEADS 16
#define HDIM 128
#define NFW 4
#define FD 512
#define CHUNK 2048
#define FDFD (FD*FD)

// ---------------- fp32 scratch ----------------
static __device__ float g_qkv [(size_t)S_LEN*QKV3];
static __device__ float g_rq  [(size_t)S_LEN*HID];
static __device__ float g_rk  [(size_t)S_LEN*HID];
static __device__ float g_attn[(size_t)S_LEN*HID];
static __device__ float g_fv  [(size_t)NFW*S_LEN*FD];
static __device__ float g_ofst[(size_t)NFW*S_LEN*FD];
static __device__ float g_lr  [(size_t)S_LEN*12];
static __device__ float g_lrraw[(size_t)S_LEN*128];
static __device__ float g_rope[(size_t)S_LEN*128];
static __device__ float g_w0  [(size_t)NFW*FDFD];
static __device__ float g_w1  [(size_t)NFW*FDFD];
static __device__ float g_w2  [(size_t)NFW*FDFD];
static __device__ float g_pq  [(size_t)NFW*CHUNK*1024];   // [gq | hmq]
static __device__ float g_pk  [(size_t)NFW*CHUNK*1024];   // [gk | hmk]
static __device__ float g_dhid[(size_t)NFW*CHUNK*FD];
static __device__ float g_part[(size_t)48*FDFD];          // split-K partials
// ---------------- fp16 GEMM operands ----------------
static __device__ __half h_hs  [(size_t)S_LEN*HID];
static __device__ __half h_qkvw[(size_t)QKV3*HID];
static __device__ __half h_lrw [(size_t)128*HID];
static __device__ __half h_opw [(size_t)HID*HID];
static __device__ __half h_x   [(size_t)S_LEN*HID];
static __device__ __half h_fq  [(size_t)NFW*S_LEN*FD];
static __device__ __half h_fk  [(size_t)NFW*S_LEN*FD];
static __device__ __half h_fv  [(size_t)NFW*S_LEN*FD];
static __device__ __half h_gq  [(size_t)NFW*CHUNK*FD];
static __device__ __half h_t0 [(size_t)NFW*CHUNK*FD];
static __device__ __half h_t1 [(size_t)NFW*CHUNK*FD];
static __device__ __half h_t2 [(size_t)NFW*CHUNK*FD];
static __device__ __half h_t3 [(size_t)NFW*CHUNK*FD];
static __device__ __half h_t4 [(size_t)NFW*CHUNK*FD];
static __device__ __half h_w02[(size_t)NFW*1024*FD];      // [w0 rows ; w2 rows]
static __device__ __half h_w1 [(size_t)NFW*FDFD];
static __device__ __half h_w1T[(size_t)NFW*FDFD];

// ---------------- helpers ----------------
__device__ __forceinline__ void mma16(float* c, const uint32_t* a, const uint32_t* b)
{
    asm volatile(
        "mma.sync.aligned.m16n8k16.row.col.f32.f16.f16.f32 "
        "{%0,%1,%2,%3}, {%4,%5,%6,%7}, {%8,%9}, {%0,%1,%2,%3};"
        : "+f"(c[0]), "+f"(c[1]), "+f"(c[2]), "+f"(c[3])
        : "r"(a[0]), "r"(a[1]), "r"(a[2]), "r"(a[3]), "r"(b[0]), "r"(b[1]));
}
__device__ __forceinline__ void ldsm4(uint32_t* r, uint32_t addr)
{
    asm volatile("ldmatrix.sync.aligned.m8n8.x4.shared.b16 {%0,%1,%2,%3}, [%4];"
                 : "=r"(r[0]), "=r"(r[1]), "=r"(r[2]), "=r"(r[3]) : "r"(addr));
}
__device__ __forceinline__ uint32_t smem_u32(const void* p)
{
    uint32_t a;
    asm("{ .reg .u64 t; cvta.to.shared.u64 t, %1; cvt.u32.u64 %0, t; }" : "=r"(a) : "l"(p));
    return a;
}
__device__ __forceinline__ void cp16(uint32_t d, const void* g)
{
    asm volatile("cp.async.cg.shared.global [%0], [%1], 16;" :: "r"(d), "l"(g));
}
#define CP_COMMIT() asm volatile("cp.async.commit_group;" ::: "memory")
#define CP_WAIT1()  asm volatile("cp.async.wait_group 1;" ::: "memory")
#define CP_WAIT0()  asm volatile("cp.async.wait_group 0;" ::: "memory")

// ---------------- fp16 tensor GEMM body (parameterized tile origin) ----------------
#define STGB 32768
#define GSMEM (3*STGB)

__device__ __forceinline__ void gemm_body(
    const __half* __restrict__ A, const __half* __restrict__ B, float* __restrict__ C,
    int m0, int n0, int Ks, int lda, int ldb, int ldc, __half* smh)
{
    const int tid = threadIdx.x, warp = tid >> 5, lane = tid & 31;
    const int wm = (warp >> 1) * 32, wn = (warp & 1) * 64;

    float acc[2][8][4];
    #pragma unroll
    for (int i = 0; i < 2; i++)
        #pragma unroll
        for (int j = 0; j < 8; j++)
            #pragma unroll
            for (int l = 0; l < 4; l++) acc[i][j][l] = 0.f;

    const int nst = Ks >> 6;
    const uint32_t smbase = smem_u32(smh);

    const int crow = tid >> 1;
    const int gb = (tid & 1) * 4;
    const __half* gA = A + (size_t)(m0 + crow) * lda + gb * 8;
    const __half* gB = B + (size_t)(n0 + crow) * ldb + gb * 8;
    const uint32_t wbase = (uint32_t)(crow * 128);
    const uint32_t wsw = (uint32_t)(crow & 7);

    #pragma unroll
    for (int s = 0; s < 2; s++) {
        uint32_t sa = smbase + s * STGB;
        #pragma unroll
        for (int i = 0; i < 4; i++) {
            uint32_t wo = wbase + (((uint32_t)(gb + i) ^ wsw) << 4);
            cp16(sa + wo,         gA + (s << 6) + i * 8);
            cp16(sa + 16384 + wo, gB + (s << 6) + i * 8);
        }
        CP_COMMIT();
    }

    const uint32_t sw = (uint32_t)(lane & 7);
    const uint32_t arowb = (uint32_t)((wm + (lane & 15)) * 128);
    const uint32_t browb = (uint32_t)((wn + ((lane >> 4) << 3) + (lane & 7)) * 128);
    const uint32_t agb = (uint32_t)(lane >> 4);
    const uint32_t bgb = (uint32_t)((lane >> 3) & 1);

    int st = 0;
    for (int s = 0; s < nst; s++) {
        if (s + 1 < nst) CP_WAIT1(); else CP_WAIT0();
        __syncthreads();
        if (s + 2 < nst) {
            uint32_t sa = smbase + ((s + 2) % 3) * STGB;
            #pragma unroll
            for (int i = 0; i < 4; i++) {
                uint32_t wo = wbase + (((uint32_t)(gb + i) ^ wsw) << 4);
                cp16(sa + wo,         gA + ((s + 2) << 6) + i * 8);
                cp16(sa + 16384 + wo, gB + ((s + 2) << 6) + i * 8);
            }
        }
        CP_COMMIT();
        const uint32_t sa = smbase + st * STGB;
        const uint32_t sb = sa + 16384;
        #pragma unroll
        for (int kt = 0; kt < 4; kt++) {
            const uint32_t axor = ((2 * kt + agb) ^ sw) << 4;
            const uint32_t bxor = ((2 * kt + bgb) ^ sw) << 4;
            uint32_t af[2][4];
            ldsm4(af[0], sa + arowb + axor);
            ldsm4(af[1], sa + arowb + 2048 + axor);
            #pragma unroll
            for (int p = 0; p < 4; p++) {
                uint32_t bf[4];
                ldsm4(bf, sb + browb + p * 2048 + bxor);
                mma16(acc[0][2 * p],     af[0], &bf[0]);
                mma16(acc[0][2 * p + 1], af[0], &bf[2]);
                mma16(acc[1][2 * p],     af[1], &bf[0]);
                mma16(acc[1][2 * p + 1], af[1], &bf[2]);
            }
        }
        st++; if (st == 3) st = 0;
    }

    const int gr = lane >> 2, gc = lane & 3;
    #pragma unroll
    for (int mt = 0; mt < 2; mt++) {
        #pragma unroll
        for (int nt = 0; nt < 8; nt++) {
            int row = m0 + wm + mt * 16 + gr;
            int col = n0 + wn + nt * 8 + 2 * gc;
            *(float2*)(C + (size_t)row * ldc + col) =
                make_float2(acc[mt][nt][0], acc[mt][nt][1]);
            *(float2*)(C + (size_t)(row + 8) * ldc + col) =
                make_float2(acc[mt][nt][2], acc[mt][nt][3]);
        }
    }
}

__global__ void __launch_bounds__(256, 2) mm_gen(
    const __half* __restrict__ A, const __half* __restrict__ B, float* __restrict__ C,
    int K, int lda, int ldb, int ldc, size_t sA, size_t sB, size_t sC)
{
    extern __shared__ __half smh[];
    int hh = blockIdx.z;
    gemm_body(A + sA * hh, B + sB * hh, C + sC * hh,
              blockIdx.y * 128, blockIdx.x * 128, K, lda, ldb, ldc, smh);
}

// fused forward: 1280 blocks. t<1024: pq/pk fwd; t>=1024: dhid.
__global__ void __launch_bounds__(256, 2) mm_fwd2(
    const __half* __restrict__ fq, const __half* __restrict__ fk,
    const __half* __restrict__ fv, const __half* __restrict__ w02,
    const __half* __restrict__ w1T,
    float* __restrict__ pq, float* __restrict__ pk, float* __restrict__ dhid)
{
    extern __shared__ __half smh[];
    int t = blockIdx.x;
    if (t < 1024) {
        int z = t >> 7, rem = t & 127, by = rem >> 3, bx = rem & 7;
        int which = z >> 2, hh = z & 3;
        const __half* A = (which ? fk : fq) + (size_t)hh * ((size_t)S_LEN * FD);
        const __half* B = w02 + (size_t)hh * (1024 * FD);
        float* C = (which ? pk : pq) + (size_t)hh * ((size_t)CHUNK * 1024);
        gemm_body(A, B, C, by * 128, bx * 128, FD, FD, FD, 1024, smh);
    } else {
        int u = t - 1024, z = u >> 6, rem = u & 63, by = rem >> 2, bx = rem & 3;
        const __half* A = fv + (size_t)z * ((size_t)S_LEN * FD);
        const __half* B = w1T + (size_t)z * FDFD;
        float* C = dhid + (size_t)z * ((size_t)CHUNK * FD);
        gemm_body(A, B, C, by * 128, bx * 128, FD, FD, FD, FD, smh);
    }
}

// fused updates + ofst: 1024 blocks. t<768: partials; t>=768: ofst (gq @ old w1).
__global__ void __launch_bounds__(256, 2) mm_upd2(
    const __half* __restrict__ t0, const __half* __restrict__ t1,
    const __half* __restrict__ t3, const __half* __restrict__ t4,
    const __half* __restrict__ t2, const __half* __restrict__ gq,
    const __half* __restrict__ w1, float* __restrict__ part, float* __restrict__ ofst)
{
    extern __shared__ __half smh[];
    int t = blockIdx.x;
    if (t < 768) {
        int z = t >> 4, rem = t & 15, by = rem >> 2, bx = rem & 3;
        int mat = z >> 4, r = z & 15, sl = r >> 2, hh = r & 3;
        const size_t sT = (size_t)FD * CHUNK;
        const __half* A = (mat == 0 ? t0 : mat == 1 ? t1 : t3)
                          + (size_t)hh * sT + sl * (CHUNK / 4);
        const __half* B = (mat < 2 ? t4 : t2)
                          + (size_t)hh * sT + sl * (CHUNK / 4);
        float* C = part + (size_t)z * FDFD;
        gemm_body(A, B, C, by * 128, bx * 128, CHUNK / 4, CHUNK, CHUNK, FD, smh);
    } else {
        int u = t - 768, z = u >> 6, rem = u & 63, by = rem >> 2, bx = rem & 3;
        const __half* A = gq + (size_t)z * ((size_t)CHUNK * FD);
        const __half* B = w1 + (size_t)z * FDFD;
        float* C = ofst + (size_t)z * ((size_t)S_LEN * FD);
        gemm_body(A, B, C, by * 128, bx * 128, FD, FD, FD, FD, smh);
    }
}

// ---------------- fused weight update + fp16 refresh ----------------
__global__ void __launch_bounds__(256) wupdate(
    float* __restrict__ w0, float* __restrict__ w1, float* __restrict__ w2,
    const float* __restrict__ part,
    __half* __restrict__ w02h, __half* __restrict__ w1h, __half* __restrict__ w1Th)
{
    __shared__ float t[32][33];
    int z = blockIdx.z, mat = z >> 2, h = z & 3;
    int c0 = blockIdx.x * 32, r0 = blockIdx.y * 32;
    int x = threadIdx.x, y = threadIdx.y;
    float* master = (mat == 0 ? w0 : mat == 1 ? w2 : w1) + (size_t)h * FDFD;
    const float* p = part + ((size_t)(mat * 16 + h)) * FDFD;
    #pragma unroll
    for (int i = 0; i < 4; i++) {
        int r = r0 + y + i * 8, c = c0 + x;
        size_t idx = (size_t)r * FD + c;
        float s = master[idx] + p[idx] + p[idx + (size_t)4 * FDFD]
                + p[idx + (size_t)8 * FDFD] + p[idx + (size_t)12 * FDFD];
        master[idx] = s;
        __half hv = __float2half(s);
        if (mat == 0)      w02h[(size_t)h * 1024 * FD + idx] = hv;
        else if (mat == 1) w02h[(size_t)h * 1024 * FD + (size_t)512 * FD + idx] = hv;
        else { w1h[(size_t)h * FDFD + idx] = hv; t[y + i * 8][x] = s; }
    }
    if (mat == 2) {
        __syncthreads();
        #pragma unroll
        for (int i = 0; i < 4; i++)
            w1Th[(size_t)h * FDFD + (size_t)(c0 + y + i * 8) * FD + r0 + x] =
                __float2half(t[x][y + i * 8]);
    }
}

// ---------------- converts ----------------
__global__ void __launch_bounds__(256) f2h(const float* __restrict__ s, __half* __restrict__ d, size_t n)
{
    size_t i = ((size_t)blockIdx.x * 256 + threadIdx.x) * 8;
    if (i >= n) return;
    float4 a = *(const float4*)(s + i), b = *(const float4*)(s + i + 4);
    __half2 q0 = __floats2half2_rn(a.x, a.y), q1 = __floats2half2_rn(a.z, a.w);
    __half2 q2 = __floats2half2_rn(b.x, b.y), q3 = __floats2half2_rn(b.z, b.w);
    uint4 u;
    u.x = *(uint32_t*)&q0; u.y = *(uint32_t*)&q1; u.z = *(uint32_t*)&q2; u.w = *(uint32_t*)&q3;
    *(uint4*)(d + i) = u;
}

__global__ void __launch_bounds__(256) lrw_cvt(const float* __restrict__ lw, __half* __restrict__ dst)
{
    size_t i = ((size_t)blockIdx.x * 256 + threadIdx.x) * 8;
    int row = (int)(i >> 11);
    int col = (int)(i & 2047);
    float4 a = make_float4(0.f,0.f,0.f,0.f), b = a;
    if (row < 12) {
        const float* s = lw + (size_t)row * HID + col;
        a = *(const float4*)s; b = *(const float4*)(s + 4);
    }
    __half2 q0 = __floats2half2_rn(a.x, a.y), q1 = __floats2half2_rn(a.z, a.w);
    __half2 q2 = __floats2half2_rn(b.x, b.y), q3 = __floats2half2_rn(b.z, b.w);
    uint4 u;
    u.x = *(uint32_t*)&q0; u.y = *(uint32_t*)&q1; u.z = *(uint32_t*)&q2; u.w = *(uint32_t*)&q3;
    *(uint4*)(dst + i) = u;
}

__global__ void __launch_bounds__(256) f2hw02(const float* __restrict__ w0, const float* __restrict__ w2,
                                              __half* __restrict__ dst)
{
    size_t i = ((size_t)blockIdx.x * 256 + threadIdx.x) * 8;
    int h = (int)(i >> 19);
    int r = (int)((i >> 9) & 1023);
    int c = (int)(i & 511);
    const float* src = (r < 512 ? w0 + ((size_t)h * FD + r) * FD
                                : w2 + ((size_t)h * FD + (r - 512)) * FD) + c;
    float4 a = *(const float4*)src, b = *(const float4*)(src + 4);
    __half2 q0 = __floats2half2_rn(a.x, a.y), q1 = __floats2half2_rn(a.z, a.w);
    __half2 q2 = __floats2half2_rn(b.x, b.y), q3 = __floats2half2_rn(b.z, b.w);
    uint4 u;
    u.x = *(uint32_t*)&q0; u.y = *(uint32_t*)&q1; u.z = *(uint32_t*)&q2; u.w = *(uint32_t*)&q3;
    *(uint4*)(dst + i) = u;
}

__global__ void __launch_bounds__(256) transpose_wh(const float* __restrict__ src, __half* __restrict__ dst)
{
    __shared__ float t[32][33];
    int h = blockIdx.z;
    int i0 = blockIdx.x * 32, j0 = blockIdx.y * 32;
    int x = threadIdx.x, y = threadIdx.y;
    const float* s = src + (size_t)h * FDFD;
    __half* d = dst + (size_t)h * FDFD;
    #pragma unroll
    for (int i = 0; i < 4; i++) t[y + i * 8][x] = s[(size_t)(j0 + y + i * 8) * FD + i0 + x];
    __syncthreads();
    #pragma unroll
    for (int i = 0; i < 4; i++) d[(size_t)(i0 + y + i * 8) * FD + j0 + x] = __float2half(t[x][y + i * 8]);
}

// ---------------- RoPE table (one-time) ----------------
__global__ void __launch_bounds__(256) rope_tab()
{
    int idx = blockIdx.x * 256 + threadIdx.x;
    int t = idx >> 6, i = idx & 63;
    float freq = (float)exp(-(double)i * (13.122363377404328 / 64.0));
    float sn, cs;
    sincosf((float)t * freq, &sn, &cs);
    g_rope[(size_t)t * 128 + i] = cs;
    g_rope[(size_t)t * 128 + 64 + i] = sn;
}

// ---------------- utils ----------------
__device__ __forceinline__ float blockReduceSum256(float v)
{
    __shared__ float red[8];
    #pragma unroll
    for (int o = 16; o > 0; o >>= 1) v += __shfl_xor_sync(0xffffffffu, v, o);
    if ((threadIdx.x & 31) == 0) red[threadIdx.x >> 5] = v;
    __syncthreads();
    if (threadIdx.x < 32) {
        float x = (threadIdx.x < 8) ? red[threadIdx.x] : 0.f;
        #pragma unroll
        for (int o = 4; o > 0; o >>= 1) x += __shfl_xor_sync(0xffffffffu, x, o);
        if (threadIdx.x == 0) red[0] = x;
    }
    __syncthreads();
    float r = red[0];
    __syncthreads();
    return r;
}
__device__ __forceinline__ float siluf(float x) { return x / (1.f + expf(-x)); }
// single-MUFU silu: x * sigmoid(x) = 0.5x*tanh(x/2) + 0.5x
__device__ __forceinline__ float siluf_fast(float x)
{
    float h = 0.5f * x, t;
    asm("tanh.approx.f32 %0, %1;" : "=f"(t) : "f"(h));
    return fmaf(h, t, h);
}

// ---------------- per-token preprocess ----------------
__global__ void __launch_bounds__(256) preprocess_kernel(
    const float* __restrict__ qnw, const float* __restrict__ knw,
    const float* __restrict__ qksc, const float* __restrict__ qkof,
    const float* __restrict__ lrb)
{
    __shared__ float sq[HID];
    __shared__ float sk[HID];
    __shared__ float gsum[8];
    int t = blockIdx.x, tid = threadIdx.x;

    if (tid < 8) gsum[tid] = 0.f;

    const float* qrow = g_qkv + (size_t)t * QKV3;
    const float* krow = qrow + HID;
    const float* vrow = qrow + 2 * HID;

    float ssq = 0.f, ssk = 0.f;
    for (int d = tid; d < HID; d += 256) {
        float a = qrow[d]; sq[d] = a; ssq += a * a;
        float b = krow[d]; sk[d] = b; ssk += b * b;
    }
    ssq = blockReduceSum256(ssq);
    ssk = blockReduceSum256(ssk);
    float rsq = rsqrtf(ssq * (1.f / HID) + 1e-6f);
    float rsk = rsqrtf(ssk * (1.f / HID) + 1e-6f);
    for (int d = tid; d < HID; d += 256) {
        sq[d] = sq[d] * rsq * qnw[d];
        sk[d] = sk[d] * rsk * knw[d];
    }
    __syncthreads();
    const float* rp = g_rope + (size_t)t * 128;
    for (int idx = tid; idx < NHEADS * 64; idx += 256) {
        int hh = idx >> 6, i = idx & 63;
        float cs = rp[i], sn = rp[64 + i];
        int d1 = hh * HDIM + i, d2 = d1 + 64;
        float q1 = sq[d1], q2 = sq[d2], k1 = sk[d1], k2 = sk[d2];
        size_t base = (size_t)t * HID;
        g_rq[base + d1] = q1 * cs - q2 * sn;
        g_rq[base + d2] = q2 * cs + q1 * sn;
        g_rk[base + d1] = k1 * cs - k2 * sn;
        g_rk[base + d2] = k2 * cs + k1 * sn;
    }
    __syncthreads();
    for (int d = tid; d < HID; d += 256) {
        float xq = sq[d] * qksc[2 * d]     + qkof[2 * d];
        float xk = sk[d] * qksc[2 * d + 1] + qkof[2 * d + 1];
        float a = siluf_fast(xq), b = siluf_fast(xk);
        sq[d] = a; sk[d] = b;
        int g = d >> 9;
        atomicAdd(&gsum[g],     a * a);
        atomicAdd(&gsum[4 + g], b * b);
        float sv = siluf_fast(vrow[d]);
        size_t o = ((size_t)g * S_LEN + t) * FD + (d & 511);
        g_fv[o] = sv;
        h_fv[o] = __float2half(sv);
    }
    __syncthreads();
    for (int d = tid; d < HID; d += 256) {
        int g = d >> 9;
        float nq = fmaxf(sqrtf(gsum[g]),     1e-12f);
        float nk = fmaxf(sqrtf(gsum[4 + g]), 1e-12f);
        size_t o = ((size_t)g * S_LEN + t) * FD + (d & 511);
        h_fq[o] = __float2half(sq[d] / nq);
        h_fk[o] = __float2half(sk[d] / nk);
    }
    if (tid < 12) {
        float z = g_lrraw[(size_t)t * 128 + tid] + lrb[tid] - 6.90725523731f;
        float sp = (z > 0.f) ? z + log1pf(expf(-z)) : log1pf(expf(z));
        g_lr[(size_t)t * 12 + tid] = sp;
    }
}

// ---------------- sliding-window attention (bank-conflict-free) ----------------
#define AR 132
#define ASM_FLOATS (3*32*AR + 32*36)    // 13824
__global__ void __launch_bounds__(256) attn_kernel()
{
    extern __shared__ float sh[];
    float* sQ = sh;
    float* sK = sh + 32 * AR;
    float* sV = sh + 64 * AR;
    float* sP = sh + 96 * AR;
    int head = blockIdx.y;
    int q0 = blockIdx.x * 32;
    int tid = threadIdx.x;
    int row = tid >> 3, sub = tid & 7;
    const float qs = 0.08838834764831845f;

    for (int i = tid; i < 32 * 32; i += 256) {
        int r = i >> 5, c4 = (i & 31) << 2;
        float4 v = *(const float4*)(g_rq + (size_t)(q0 + r) * HID + head * HDIM + c4);
        v.x *= qs; v.y *= qs; v.z *= qs; v.w *= qs;
        *(float4*)(sQ + r * AR + c4) = v;
    }

    float oacc[16];
    #pragma unroll
    for (int j = 0; j < 16; j++) oacc[j] = 0.f;
    float m = -1e30f, l = 0.f;
    int qpos = q0 + row;

    for (int it = 0; it < 9; it++) {
        int kb = q0 - 256 + it * 32;
        if (kb + 32 <= 0) continue;
        __syncthreads();
        for (int i = tid; i < 32 * 32; i += 256) {
            int r = i >> 5, c4 = (i & 31) << 2;
            int kpos = kb + r;
            float4 kv = make_float4(0.f,0.f,0.f,0.f), vv = kv;
            if (kpos >= 0) {
                kv = *(const float4*)(g_rk  + (size_t)kpos * HID  + head * HDIM + c4);
                vv = *(const float4*)(g_qkv + (size_t)kpos * QKV3 + 2 * HID + head * HDIM + c4);
            }
            *(float4*)(sK + r * AR + c4) = kv;
            *(float4*)(sV + r * AR + c4) = vv;
        }
        __syncthreads();
        float s[4];
        bool ok[4];
        #pragma unroll
        for (int j = 0; j < 4; j++) {
            int kpos = kb + sub + 8 * j;
            ok[j] = (kpos >= 0) && (kpos <= qpos) && (kpos >= qpos - 255);
            s[j] = 0.f;
        }
        const float4* qp = (const float4*)(sQ + row * AR);
        #pragma unroll 8
        for (int d4 = 0; d4 < 32; d4++) {
            float4 a = qp[d4];
            #pragma unroll
            for (int j = 0; j < 4; j++) {
                float4 b = *(const float4*)(sK + (sub + 8 * j) * AR + d4 * 4);
                s[j] += a.x*b.x + a.y*b.y + a.z*b.z + a.w*b.w;
            }
        }
        float tmax = -1e30f;
        #pragma unroll
        for (int j = 0; j < 4; j++) { if (!ok[j]) s[j] = -1e30f; tmax = fmaxf(tmax, s[j]); }
        #pragma unroll
        for (int o = 4; o > 0; o >>= 1) tmax = fmaxf(tmax, __shfl_xor_sync(0xffffffffu, tmax, o, 8));
        float mnew = fmaxf(m, tmax);
        float scale = expf(m - mnew);
        float p[4], ps = 0.f;
        #pragma unroll
        for (int j = 0; j < 4; j++) { p[j] = ok[j] ? expf(s[j] - mnew) : 0.f; ps += p[j]; }
        #pragma unroll
        for (int o = 4; o > 0; o >>= 1) ps += __shfl_xor_sync(0xffffffffu, ps, o, 8);
        l = l * scale + ps;
        m = mnew;
        #pragma unroll
        for (int j = 0; j < 16; j++) oacc[j] *= scale;
        #pragma unroll
        for (int j = 0; j < 4; j++) sP[row * 36 + sub + 8 * j] = p[j];
        __syncwarp();
        #pragma unroll 4
        for (int k = 0; k < 32; k++) {
            float pk = sP[row * 36 + k];
            #pragma unroll
            for (int jj = 0; jj < 4; jj++) {
                float4 v = *(const float4*)(sV + k * AR + sub * 4 + 32 * jj);
                oacc[jj*4+0] += pk*v.x; oacc[jj*4+1] += pk*v.y;
                oacc[jj*4+2] += pk*v.z; oacc[jj*4+3] += pk*v.w;
            }
        }
    }
    float inv = 1.f / l;
    #pragma unroll
    for (int jj = 0; jj < 4; jj++) {
        float4 v;
        v.x = oacc[jj*4+0]*inv; v.y = oacc[jj*4+1]*inv;
        v.z = oacc[jj*4+2]*inv; v.w = oacc[jj*4+3]*inv;
        *(float4*)(g_attn + (size_t)qpos * HID + head * HDIM + sub * 4 + 32 * jj) = v;
    }
}

// ---------------- TTT elementwise + transposes ----------------
__global__ void __launch_bounds__(256) ttt_elem_t(int c0)
{
    __shared__ float t0[32][33], t1[32][33], t2[32][33], t3[32][33], t4[32][33];
    int h = blockIdx.z;
    int cb = blockIdx.x * 32, db = blockIdx.y * 32;
    int x = threadIdx.x, y = threadIdx.y;
    size_t base  = (size_t)h * CHUNK * FD;
    size_t baseP = (size_t)h * CHUNK * 1024;
    #pragma unroll
    for (int i = 0; i < 4; i++) {
        int cy = y + i * 8;
        int c = cb + cy, d = db + x;
        size_t idx  = base  + (size_t)c * FD + d;
        size_t idxP = baseP + (size_t)c * 1024 + d;
        int t = c0 + c;
        float lr0 = g_lr[(size_t)t * 12 + h];
        float lr1 = g_lr[(size_t)t * 12 + 4 + h];
        float lr2 = g_lr[(size_t)t * 12 + 8 + h];
        float gq = g_pq[idxP], hmq = g_pq[idxP + 512];
        h_gq[idx] = __float2half(siluf(gq) * hmq);
        float gk = g_pk[idxP], hmk = g_pk[idxP + 512], dh = g_dhid[idx];
        float sg = 1.f / (1.f + expf(-gk));
        float silug = gk * sg;
        t0[cy][x] = dh * hmk * (sg * (1.f + gk * (1.f - sg))) * lr0;
        t1[cy][x] = dh * silug * lr2;
        t2[cy][x] = silug * hmk;
        t3[cy][x] = g_fv[((size_t)h * S_LEN + t) * FD + d] * lr1;
        t4[cy][x] = __half2float(h_fk[((size_t)h * S_LEN + t) * FD + d]);
    }
    __syncthreads();
    size_t tb = ((size_t)h * FD + db) * CHUNK + cb;
    #pragma unroll
    for (int i = 0; i < 4; i++) {
        int dy = y + i * 8;
        size_t o = tb + (size_t)dy * CHUNK + x;
        h_t0[o] = __float2half(t0[x][dy]);
        h_t1[o] = __float2half(t1[x][dy]);
        h_t2[o] = __float2half(t2[x][dy]);
        h_t3[o] = __float2half(t3[x][dy]);
        h_t4[o] = __float2half(t4[x][dy]);
    }
}

// ---------------- rms_norm(o_fast) + attn add -> fp16 x ----------------
__global__ void __launch_bounds__(256) normadd_kernel(const float* __restrict__ tnw)
{
    __shared__ float ss[4];
    int t = blockIdx.x, tid = threadIdx.x;
    if (tid < 4) ss[tid] = 0.f;
    __syncthreads();
    float v[8];
    #pragma unroll
    for (int i = 0; i < 8; i++) {
        int d = i * 256 + tid;
        int h = d >> 9;
        float x = g_ofst[((size_t)h * S_LEN + t) * FD + (d & 511)];
        v[i] = x;
        float s = x * x;
        #pragma unroll
        for (int o = 16; o > 0; o >>= 1) s += __shfl_xor_sync(0xffffffffu, s, o);
        if ((tid & 31) == 0) atomicAdd(&ss[h], s);
    }
    __syncthreads();
    #pragma unroll
    for (int i = 0; i < 8; i++) {
        int d = i * 256 + tid;
        int h = d >> 9;
        float rn = rsqrtf(ss[h] * (1.f / FD) + 1e-6f);
        h_x[(size_t)t * HID + d] =
            __float2half(g_attn[(size_t)t * HID + d] + v[i] * rn * tnw[d & 511]);
    }
}

// ---------------- host ----------------
template<typename T>
static T* symaddr(const void* s)
{
    void* p = nullptr;
    cudaGetSymbolAddress(&p, s);
    return (T*)p;
}

extern "C" void kernel_launch(void* const* d_in, const int* in_sizes, int n_in,
                              void* d_out, int out_size)
{
    const float* hs    = (const float*)d_in[0];
    const float* qkv_w = (const float*)d_in[1];
    const float* qnw   = (const float*)d_in[2];
    const float* knw   = (const float*)d_in[3];
    const float* qksc  = (const float*)d_in[4];
    const float* qkof  = (const float*)d_in[5];
    const float* lrw   = (const float*)d_in[6];
    const float* lrb   = (const float*)d_in[7];
    const float* w0    = (const float*)d_in[8];
    const float* w1    = (const float*)d_in[9];
    const float* w2    = (const float*)d_in[10];
    const float* tnw   = (const float*)d_in[11];
    const float* opw   = (const float*)d_in[12];
    float* out = (float*)d_out;

    float*  p_qkv  = symaddr<float>(g_qkv);
    float*  p_lrr  = symaddr<float>(g_lrraw);
    float*  p_ofst = symaddr<float>(g_ofst);
    float*  p_w0   = symaddr<float>(g_w0);
    float*  p_w1   = symaddr<float>(g_w1);
    float*  p_w2   = symaddr<float>(g_w2);
    float*  p_pq   = symaddr<float>(g_pq);
    float*  p_pk   = symaddr<float>(g_pk);
    float*  p_dhid = symaddr<float>(g_dhid);
    float*  p_part = symaddr<float>(g_part);
    __half* ph_hs  = symaddr<__half>(h_hs);
    __half* ph_qw  = symaddr<__half>(h_qkvw);
    __half* ph_lw  = symaddr<__half>(h_lrw);
    __half* ph_ow  = symaddr<__half>(h_opw);
    __half* ph_x   = symaddr<__half>(h_x);
    __half* ph_fq  = symaddr<__half>(h_fq);
    __half* ph_fk  = symaddr<__half>(h_fk);
    __half* ph_fv  = symaddr<__half>(h_fv);
    __half* ph_gq  = symaddr<__half>(h_gq);
    __half* ph_t0  = symaddr<__half>(h_t0);
    __half* ph_t1  = symaddr<__half>(h_t1);
    __half* ph_t2  = symaddr<__half>(h_t2);
    __half* ph_t3  = symaddr<__half>(h_t3);
    __half* ph_t4  = symaddr<__half>(h_t4);
    __half* ph_w02 = symaddr<__half>(h_w02);
    __half* ph_w1  = symaddr<__half>(h_w1);
    __half* ph_w1T = symaddr<__half>(h_w1T);

    const size_t WB = sizeof(float) * NFW * FDFD;
    const size_t WE = (size_t)NFW * FDFD;

    cudaFuncSetAttribute(mm_gen,  cudaFuncAttributeMaxDynamicSharedMemorySize, GSMEM);
    cudaFuncSetAttribute(mm_fwd2, cudaFuncAttributeMaxDynamicSharedMemorySize, GSMEM);
    cudaFuncSetAttribute(mm_upd2, cudaFuncAttributeMaxDynamicSharedMemorySize, GSMEM);
    cudaFuncSetAttribute(attn_kernel, cudaFuncAttributeMaxDynamicSharedMemorySize, ASM_FLOATS * 4);

    cudaMemcpyAsync(p_w0, w0, WB, cudaMemcpyDeviceToDevice, 0);
    cudaMemcpyAsync(p_w1, w1, WB, cudaMemcpyDeviceToDevice, 0);
    cudaMemcpyAsync(p_w2, w2, WB, cudaMemcpyDeviceToDevice, 0);

    rope_tab<<<(S_LEN*64)/256, 256>>>();                                          // 0
    f2h<<<(S_LEN*HID)/2048, 256>>>(hs, ph_hs, (size_t)S_LEN*HID);                 // 1
    f2h<<<(QKV3*HID)/2048, 256>>>(qkv_w, ph_qw, (size_t)QKV3*HID);                // 2
    lrw_cvt<<<(128*HID)/2048, 256>>>(lrw, ph_lw);                                 // 3
    mm_gen<<<dim3(QKV3/128, S_LEN/128, 1), 256, GSMEM>>>(
        ph_hs, ph_qw, p_qkv, HID, HID, HID, QKV3, 0, 0, 0);                       // 4
    mm_gen<<<dim3(1, S_LEN/128, 1), 256, GSMEM>>>(
        ph_hs, ph_lw, p_lrr, HID, HID, HID, 128, 0, 0, 0);                        // 5
    preprocess_kernel<<<S_LEN, 256>>>(qnw, knw, qksc, qkof, lrb);                 // 6
    attn_kernel<<<dim3(S_LEN/32, NHEADS), 256, ASM_FLOATS * 4>>>();               // 7
    f2hw02<<<(NFW*1024*FD)/2048, 256>>>(p_w0, p_w2, ph_w02);                      // 8
    f2h<<<WE/2048, 256>>>(p_w1, ph_w1, WE);                                       // 9
    transpose_wh<<<dim3(16, 16, 4), dim3(32, 8)>>>(p_w1, ph_w1T);                 // 10
    f2h<<<(HID*HID)/2048, 256>>>(opw, ph_ow, (size_t)HID*HID);                    // 11

    // TTT scan (4 launches/chunk)
    for (int c = 0; c < 4; c++) {
        size_t co = (size_t)c * CHUNK * FD;
        int c0 = c * CHUNK;
        mm_fwd2<<<1280, 256, GSMEM>>>(ph_fq + co, ph_fk + co, ph_fv + co,
                                      ph_w02, ph_w1T, p_pq, p_pk, p_dhid);
        ttt_elem_t<<<dim3(CHUNK/32, FD/32, NFW), dim3(32, 8)>>>(c0);
        mm_upd2<<<1024, 256, GSMEM>>>(ph_t0, ph_t1, ph_t3, ph_t4, ph_t2,
                                      ph_gq, ph_w1, p_part, p_ofst + co);
        if (c < 3)
            wupdate<<<dim3(16, 16, 12), dim3(32, 8)>>>(
                p_w0, p_w1, p_w2, p_part, ph_w02, ph_w1, ph_w1T);
    }

    normadd_kernel<<<S_LEN, 256>>>(tnw);

    mm_gen<<<dim3(HID/128, S_LEN/128, 1), 256, GSMEM>>>(
        ph_x, ph_ow, out, HID, HID, HID, HID, 0, 0, 0);
}

// round 17
// speedup vs baseline: 3.3592x; 1.0006x over previous
#include <cuda_runtime.h>
#include <cuda_fp16.h>
#include <math.h>
#include <stdint.h>

#define S_LEN 8192
#define HID 2048
#define QKV3 (3*HID)
#define NHEADS 16
#define HDIM 128
#define NFW 4
#define FD 512
#define CHUNK 2048
#define FDFD (FD*FD)

// ---------------- fp32 scratch ----------------
static __device__ float g_qkv [(size_t)S_LEN*QKV3];
static __device__ float g_rq  [(size_t)S_LEN*HID];
static __device__ float g_rk  [(size_t)S_LEN*HID];
static __device__ float g_attn[(size_t)S_LEN*HID];
static __device__ float g_fv  [(size_t)NFW*S_LEN*FD];
static __device__ float g_ofst[(size_t)NFW*S_LEN*FD];
static __device__ float g_lr  [(size_t)S_LEN*12];
static __device__ float g_lrraw[(size_t)S_LEN*128];
static __device__ float g_rope[(size_t)S_LEN*128];
static __device__ float g_w0  [(size_t)NFW*FDFD];
static __device__ float g_w1  [(size_t)NFW*FDFD];
static __device__ float g_w2  [(size_t)NFW*FDFD];
static __device__ float g_pq  [(size_t)NFW*CHUNK*1024];   // [gq | hmq]
static __device__ float g_pk  [(size_t)NFW*CHUNK*1024];   // [gk | hmk]
static __device__ float g_dhid[(size_t)NFW*CHUNK*FD];
static __device__ float g_part[(size_t)48*FDFD];          // split-K partials
// ---------------- fp16 GEMM operands ----------------
static __device__ __half h_hs  [(size_t)S_LEN*HID];
static __device__ __half h_qkvw[(size_t)QKV3*HID];
static __device__ __half h_lrw [(size_t)128*HID];
static __device__ __half h_opw [(size_t)HID*HID];
static __device__ __half h_x   [(size_t)S_LEN*HID];
static __device__ __half h_fq  [(size_t)NFW*S_LEN*FD];
static __device__ __half h_fk  [(size_t)NFW*S_LEN*FD];
static __device__ __half h_fv  [(size_t)NFW*S_LEN*FD];
static __device__ __half h_gq  [(size_t)NFW*CHUNK*FD];
static __device__ __half h_t0 [(size_t)NFW*CHUNK*FD];
static __device__ __half h_t1 [(size_t)NFW*CHUNK*FD];
static __device__ __half h_t2 [(size_t)NFW*CHUNK*FD];
static __device__ __half h_t3 [(size_t)NFW*CHUNK*FD];
static __device__ __half h_t4 [(size_t)NFW*CHUNK*FD];
static __device__ __half h_w02[(size_t)NFW*1024*FD];      // [w0 rows ; w2 rows]
static __device__ __half h_w1 [(size_t)NFW*FDFD];
static __device__ __half h_w1T[(size_t)NFW*FDFD];

// ---------------- helpers ----------------
__device__ __forceinline__ void mma16(float* c, const uint32_t* a, const uint32_t* b)
{
    asm volatile(
        "mma.sync.aligned.m16n8k16.row.col.f32.f16.f16.f32 "
        "{%0,%1,%2,%3}, {%4,%5,%6,%7}, {%8,%9}, {%0,%1,%2,%3};"
        : "+f"(c[0]), "+f"(c[1]), "+f"(c[2]), "+f"(c[3])
        : "r"(a[0]), "r"(a[1]), "r"(a[2]), "r"(a[3]), "r"(b[0]), "r"(b[1]));
}
__device__ __forceinline__ void ldsm4(uint32_t* r, uint32_t addr)
{
    asm volatile("ldmatrix.sync.aligned.m8n8.x4.shared.b16 {%0,%1,%2,%3}, [%4];"
                 : "=r"(r[0]), "=r"(r[1]), "=r"(r[2]), "=r"(r[3]) : "r"(addr));
}
__device__ __forceinline__ uint32_t smem_u32(const void* p)
{
    uint32_t a;
    asm("{ .reg .u64 t; cvta.to.shared.u64 t, %1; cvt.u32.u64 %0, t; }" : "=r"(a) : "l"(p));
    return a;
}
__device__ __forceinline__ void cp16(uint32_t d, const void* g)
{
    asm volatile("cp.async.cg.shared.global [%0], [%1], 16;" :: "r"(d), "l"(g));
}
#define CP_COMMIT() asm volatile("cp.async.commit_group;" ::: "memory")
#define CP_WAIT1()  asm volatile("cp.async.wait_group 1;" ::: "memory")
#define CP_WAIT0()  asm volatile("cp.async.wait_group 0;" ::: "memory")

// ---- packed f32x2 (Blackwell) ----
__device__ __forceinline__ uint64_t pk2(float lo, float hi)
{
    uint64_t r;
    asm("mov.b64 %0, {%1, %2};" : "=l"(r) : "f"(lo), "f"(hi));
    return r;
}
__device__ __forceinline__ void unpk2(float& lo, float& hi, uint64_t v)
{
    asm("mov.b64 {%0, %1}, %2;" : "=f"(lo), "=f"(hi) : "l"(v));
}
__device__ __forceinline__ uint64_t fma2(uint64_t a, uint64_t b, uint64_t c)
{
    uint64_t d;
    asm("fma.rn.f32x2 %0, %1, %2, %3;" : "=l"(d) : "l"(a), "l"(b), "l"(c));
    return d;
}
__device__ __forceinline__ uint64_t mul2(uint64_t a, uint64_t b)
{
    uint64_t d;
    asm("mul.rn.f32x2 %0, %1, %2;" : "=l"(d) : "l"(a), "l"(b));
    return d;
}

// ---------------- fp16 tensor GEMM body ----------------
#define STGB 32768
#define GSMEM (3*STGB)

__device__ __forceinline__ void gemm_body(
    const __half* __restrict__ A, const __half* __restrict__ B, float* __restrict__ C,
    int m0, int n0, int Ks, int lda, int ldb, int ldc, __half* smh)
{
    const int tid = threadIdx.x, warp = tid >> 5, lane = tid & 31;
    const int wm = (warp >> 1) * 32, wn = (warp & 1) * 64;

    float acc[2][8][4];
    #pragma unroll
    for (int i = 0; i < 2; i++)
        #pragma unroll
        for (int j = 0; j < 8; j++)
            #pragma unroll
            for (int l = 0; l < 4; l++) acc[i][j][l] = 0.f;

    const int nst = Ks >> 6;
    const uint32_t smbase = smem_u32(smh);

    const int crow = tid >> 1;
    const int gb = (tid & 1) * 4;
    const __half* gA = A + (size_t)(m0 + crow) * lda + gb * 8;
    const __half* gB = B + (size_t)(n0 + crow) * ldb + gb * 8;
    const uint32_t wbase = (uint32_t)(crow * 128);
    const uint32_t wsw = (uint32_t)(crow & 7);

    #pragma unroll
    for (int s = 0; s < 2; s++) {
        uint32_t sa = smbase + s * STGB;
        #pragma unroll
        for (int i = 0; i < 4; i++) {
            uint32_t wo = wbase + (((uint32_t)(gb + i) ^ wsw) << 4);
            cp16(sa + wo,         gA + (s << 6) + i * 8);
            cp16(sa + 16384 + wo, gB + (s << 6) + i * 8);
        }
        CP_COMMIT();
    }

    const uint32_t sw = (uint32_t)(lane & 7);
    const uint32_t arowb = (uint32_t)((wm + (lane & 15)) * 128);
    const uint32_t browb = (uint32_t)((wn + ((lane >> 4) << 3) + (lane & 7)) * 128);
    const uint32_t agb = (uint32_t)(lane >> 4);
    const uint32_t bgb = (uint32_t)((lane >> 3) & 1);

    int st = 0;
    for (int s = 0; s < nst; s++) {
        if (s + 1 < nst) CP_WAIT1(); else CP_WAIT0();
        __syncthreads();
        if (s + 2 < nst) {
            uint32_t sa = smbase + ((s + 2) % 3) * STGB;
            #pragma unroll
            for (int i = 0; i < 4; i++) {
                uint32_t wo = wbase + (((uint32_t)(gb + i) ^ wsw) << 4);
                cp16(sa + wo,         gA + ((s + 2) << 6) + i * 8);
                cp16(sa + 16384 + wo, gB + ((s + 2) << 6) + i * 8);
            }
        }
        CP_COMMIT();
        const uint32_t sa = smbase + st * STGB;
        const uint32_t sb = sa + 16384;
        #pragma unroll
        for (int kt = 0; kt < 4; kt++) {
            const uint32_t axor = ((2 * kt + agb) ^ sw) << 4;
            const uint32_t bxor = ((2 * kt + bgb) ^ sw) << 4;
            uint32_t af[2][4];
            ldsm4(af[0], sa + arowb + axor);
            ldsm4(af[1], sa + arowb + 2048 + axor);
            #pragma unroll
            for (int p = 0; p < 4; p++) {
                uint32_t bf[4];
                ldsm4(bf, sb + browb + p * 2048 + bxor);
                mma16(acc[0][2 * p],     af[0], &bf[0]);
                mma16(acc[0][2 * p + 1], af[0], &bf[2]);
                mma16(acc[1][2 * p],     af[1], &bf[0]);
                mma16(acc[1][2 * p + 1], af[1], &bf[2]);
            }
        }
        st++; if (st == 3) st = 0;
    }

    const int gr = lane >> 2, gc = lane & 3;
    #pragma unroll
    for (int mt = 0; mt < 2; mt++) {
        #pragma unroll
        for (int nt = 0; nt < 8; nt++) {
            int row = m0 + wm + mt * 16 + gr;
            int col = n0 + wn + nt * 8 + 2 * gc;
            *(float2*)(C + (size_t)row * ldc + col) =
                make_float2(acc[mt][nt][0], acc[mt][nt][1]);
            *(float2*)(C + (size_t)(row + 8) * ldc + col) =
                make_float2(acc[mt][nt][2], acc[mt][nt][3]);
        }
    }
}

__global__ void __launch_bounds__(256, 2) mm_gen(
    const __half* __restrict__ A, const __half* __restrict__ B, float* __restrict__ C,
    int K, int lda, int ldb, int ldc, size_t sA, size_t sB, size_t sC)
{
    extern __shared__ __half smh[];
    int hh = blockIdx.z;
    gemm_body(A + sA * hh, B + sB * hh, C + sC * hh,
              blockIdx.y * 128, blockIdx.x * 128, K, lda, ldb, ldc, smh);
}

// qkv + lr fused: grid (49, 64). bx<48 -> qkv tile; bx==48 -> lr tile.
__global__ void __launch_bounds__(256, 2) mm_qkvlr(
    const __half* __restrict__ hs, const __half* __restrict__ qw,
    const __half* __restrict__ lw, float* __restrict__ qkv, float* __restrict__ lrr)
{
    extern __shared__ __half smh[];
    int bx = blockIdx.x, by = blockIdx.y;
    if (bx < 48)
        gemm_body(hs, qw, qkv, by * 128, bx * 128, HID, HID, HID, QKV3, smh);
    else
        gemm_body(hs, lw, lrr, by * 128, 0, HID, HID, HID, 128, smh);
}

// fused forward: 1280 blocks. t<1024: pq/pk fwd; t>=1024: dhid.
__global__ void __launch_bounds__(256, 2) mm_fwd2(
    const __half* __restrict__ fq, const __half* __restrict__ fk,
    const __half* __restrict__ fv, const __half* __restrict__ w02,
    const __half* __restrict__ w1T,
    float* __restrict__ pq, float* __restrict__ pk, float* __restrict__ dhid)
{
    extern __shared__ __half smh[];
    int t = blockIdx.x;
    if (t < 1024) {
        int z = t >> 7, rem = t & 127, by = rem >> 3, bx = rem & 7;
        int which = z >> 2, hh = z & 3;
        const __half* A = (which ? fk : fq) + (size_t)hh * ((size_t)S_LEN * FD);
        const __half* B = w02 + (size_t)hh * (1024 * FD);
        float* C = (which ? pk : pq) + (size_t)hh * ((size_t)CHUNK * 1024);
        gemm_body(A, B, C, by * 128, bx * 128, FD, FD, FD, 1024, smh);
    } else {
        int u = t - 1024, z = u >> 6, rem = u & 63, by = rem >> 2, bx = rem & 3;
        const __half* A = fv + (size_t)z * ((size_t)S_LEN * FD);
        const __half* B = w1T + (size_t)z * FDFD;
        float* C = dhid + (size_t)z * ((size_t)CHUNK * FD);
        gemm_body(A, B, C, by * 128, bx * 128, FD, FD, FD, FD, smh);
    }
}

// fused updates + ofst: 1024 blocks. t<768: partials; t>=768: ofst (gq @ old w1).
__global__ void __launch_bounds__(256, 2) mm_upd2(
    const __half* __restrict__ t0, const __half* __restrict__ t1,
    const __half* __restrict__ t3, const __half* __restrict__ t4,
    const __half* __restrict__ t2, const __half* __restrict__ gq,
    const __half* __restrict__ w1, float* __restrict__ part, float* __restrict__ ofst)
{
    extern __shared__ __half smh[];
    int t = blockIdx.x;
    if (t < 768) {
        int z = t >> 4, rem = t & 15, by = rem >> 2, bx = rem & 3;
        int mat = z >> 4, r = z & 15, sl = r >> 2, hh = r & 3;
        const size_t sT = (size_t)FD * CHUNK;
        const __half* A = (mat == 0 ? t0 : mat == 1 ? t1 : t3)
                          + (size_t)hh * sT + sl * (CHUNK / 4);
        const __half* B = (mat < 2 ? t4 : t2)
                          + (size_t)hh * sT + sl * (CHUNK / 4);
        float* C = part + (size_t)z * FDFD;
        gemm_body(A, B, C, by * 128, bx * 128, CHUNK / 4, CHUNK, CHUNK, FD, smh);
    } else {
        int u = t - 768, z = u >> 6, rem = u & 63, by = rem >> 2, bx = rem & 3;
        const __half* A = gq + (size_t)z * ((size_t)CHUNK * FD);
        const __half* B = w1 + (size_t)z * FDFD;
        float* C = ofst + (size_t)z * ((size_t)S_LEN * FD);
        gemm_body(A, B, C, by * 128, bx * 128, FD, FD, FD, FD, smh);
    }
}

// ---------------- fused weight update + fp16 refresh ----------------
__global__ void __launch_bounds__(256) wupdate(
    float* __restrict__ w0, float* __restrict__ w1, float* __restrict__ w2,
    const float* __restrict__ part,
    __half* __restrict__ w02h, __half* __restrict__ w1h, __half* __restrict__ w1Th)
{
    __shared__ float t[32][33];
    int z = blockIdx.z, mat = z >> 2, h = z & 3;
    int c0 = blockIdx.x * 32, r0 = blockIdx.y * 32;
    int x = threadIdx.x, y = threadIdx.y;
    float* master = (mat == 0 ? w0 : mat == 1 ? w2 : w1) + (size_t)h * FDFD;
    const float* p = part + ((size_t)(mat * 16 + h)) * FDFD;
    #pragma unroll
    for (int i = 0; i < 4; i++) {
        int r = r0 + y + i * 8, c = c0 + x;
        size_t idx = (size_t)r * FD + c;
        float s = master[idx] + p[idx] + p[idx + (size_t)4 * FDFD]
                + p[idx + (size_t)8 * FDFD] + p[idx + (size_t)12 * FDFD];
        master[idx] = s;
        __half hv = __float2half(s);
        if (mat == 0)      w02h[(size_t)h * 1024 * FD + idx] = hv;
        else if (mat == 1) w02h[(size_t)h * 1024 * FD + (size_t)512 * FD + idx] = hv;
        else { w1h[(size_t)h * FDFD + idx] = hv; t[y + i * 8][x] = s; }
    }
    if (mat == 2) {
        __syncthreads();
        #pragma unroll
        for (int i = 0; i < 4; i++)
            w1Th[(size_t)h * FDFD + (size_t)(c0 + y + i * 8) * FD + r0 + x] =
                __float2half(t[x][y + i * 8]);
    }
}

// ---------------- converts ----------------
__global__ void __launch_bounds__(256) f2h(const float* __restrict__ s, __half* __restrict__ d, size_t n)
{
    size_t i = ((size_t)blockIdx.x * 256 + threadIdx.x) * 8;
    if (i >= n) return;
    float4 a = *(const float4*)(s + i), b = *(const float4*)(s + i + 4);
    __half2 q0 = __floats2half2_rn(a.x, a.y), q1 = __floats2half2_rn(a.z, a.w);
    __half2 q2 = __floats2half2_rn(b.x, b.y), q3 = __floats2half2_rn(b.z, b.w);
    uint4 u;
    u.x = *(uint32_t*)&q0; u.y = *(uint32_t*)&q1; u.z = *(uint32_t*)&q2; u.w = *(uint32_t*)&q3;
    *(uint4*)(d + i) = u;
}

__global__ void __launch_bounds__(256) lrw_cvt(const float* __restrict__ lw, __half* __restrict__ dst)
{
    size_t i = ((size_t)blockIdx.x * 256 + threadIdx.x) * 8;
    int row = (int)(i >> 11);
    int col = (int)(i & 2047);
    float4 a = make_float4(0.f,0.f,0.f,0.f), b = a;
    if (row < 12) {
        const float* s = lw + (size_t)row * HID + col;
        a = *(const float4*)s; b = *(const float4*)(s + 4);
    }
    __half2 q0 = __floats2half2_rn(a.x, a.y), q1 = __floats2half2_rn(a.z, a.w);
    __half2 q2 = __floats2half2_rn(b.x, b.y), q3 = __floats2half2_rn(b.z, b.w);
    uint4 u;
    u.x = *(uint32_t*)&q0; u.y = *(uint32_t*)&q1; u.z = *(uint32_t*)&q2; u.w = *(uint32_t*)&q3;
    *(uint4*)(dst + i) = u;
}

__global__ void __launch_bounds__(256) f2hw02(const float* __restrict__ w0, const float* __restrict__ w2,
                                              __half* __restrict__ dst)
{
    size_t i = ((size_t)blockIdx.x * 256 + threadIdx.x) * 8;
    int h = (int)(i >> 19);
    int r = (int)((i >> 9) & 1023);
    int c = (int)(i & 511);
    const float* src = (r < 512 ? w0 + ((size_t)h * FD + r) * FD
                                : w2 + ((size_t)h * FD + (r - 512)) * FD) + c;
    float4 a = *(const float4*)src, b = *(const float4*)(src + 4);
    __half2 q0 = __floats2half2_rn(a.x, a.y), q1 = __floats2half2_rn(a.z, a.w);
    __half2 q2 = __floats2half2_rn(b.x, b.y), q3 = __floats2half2_rn(b.z, b.w);
    uint4 u;
    u.x = *(uint32_t*)&q0; u.y = *(uint32_t*)&q1; u.z = *(uint32_t*)&q2; u.w = *(uint32_t*)&q3;
    *(uint4*)(dst + i) = u;
}

__global__ void __launch_bounds__(256) transpose_wh(const float* __restrict__ src, __half* __restrict__ dst)
{
    __shared__ float t[32][33];
    int h = blockIdx.z;
    int i0 = blockIdx.x * 32, j0 = blockIdx.y * 32;
    int x = threadIdx.x, y = threadIdx.y;
    const float* s = src + (size_t)h * FDFD;
    __half* d = dst + (size_t)h * FDFD;
    #pragma unroll
    for (int i = 0; i < 4; i++) t[y + i * 8][x] = s[(size_t)(j0 + y + i * 8) * FD + i0 + x];
    __syncthreads();
    #pragma unroll
    for (int i = 0; i < 4; i++) d[(size_t)(i0 + y + i * 8) * FD + j0 + x] = __float2half(t[x][y + i * 8]);
}

// ---------------- RoPE table (one-time) ----------------
__global__ void __launch_bounds__(256) rope_tab()
{
    int idx = blockIdx.x * 256 + threadIdx.x;
    int t = idx >> 6, i = idx & 63;
    float freq = (float)exp(-(double)i * (13.122363377404328 / 64.0));
    float sn, cs;
    sincosf((float)t * freq, &sn, &cs);
    g_rope[(size_t)t * 128 + i] = cs;
    g_rope[(size_t)t * 128 + 64 + i] = sn;
}

// ---------------- utils ----------------
__device__ __forceinline__ float blockReduceSum256(float v)
{
    __shared__ float red[8];
    #pragma unroll
    for (int o = 16; o > 0; o >>= 1) v += __shfl_xor_sync(0xffffffffu, v, o);
    if ((threadIdx.x & 31) == 0) red[threadIdx.x >> 5] = v;
    __syncthreads();
    if (threadIdx.x < 32) {
        float x = (threadIdx.x < 8) ? red[threadIdx.x] : 0.f;
        #pragma unroll
        for (int o = 4; o > 0; o >>= 1) x += __shfl_xor_sync(0xffffffffu, x, o);
        if (threadIdx.x == 0) red[0] = x;
    }
    __syncthreads();
    float r = red[0];
    __syncthreads();
    return r;
}
__device__ __forceinline__ float siluf(float x) { return x / (1.f + expf(-x)); }
__device__ __forceinline__ float siluf_fast(float x)
{
    float h = 0.5f * x, t;
    asm("tanh.approx.f32 %0, %1;" : "=f"(t) : "f"(h));
    return fmaf(h, t, h);
}

// ---------------- per-token preprocess ----------------
__global__ void __launch_bounds__(256) preprocess_kernel(
    const float* __restrict__ qnw, const float* __restrict__ knw,
    const float* __restrict__ qksc, const float* __restrict__ qkof,
    const float* __restrict__ lrb)
{
    __shared__ float sq[HID];
    __shared__ float sk[HID];
    __shared__ float gsum[8];
    int t = blockIdx.x, tid = threadIdx.x;

    if (tid < 8) gsum[tid] = 0.f;

    const float* qrow = g_qkv + (size_t)t * QKV3;
    const float* krow = qrow + HID;
    const float* vrow = qrow + 2 * HID;

    float ssq = 0.f, ssk = 0.f;
    for (int d = tid; d < HID; d += 256) {
        float a = qrow[d]; sq[d] = a; ssq += a * a;
        float b = krow[d]; sk[d] = b; ssk += b * b;
    }
    ssq = blockReduceSum256(ssq);
    ssk = blockReduceSum256(ssk);
    float rsq = rsqrtf(ssq * (1.f / HID) + 1e-6f);
    float rsk = rsqrtf(ssk * (1.f / HID) + 1e-6f);
    for (int d = tid; d < HID; d += 256) {
        sq[d] = sq[d] * rsq * qnw[d];
        sk[d] = sk[d] * rsk * knw[d];
    }
    __syncthreads();
    const float* rp = g_rope + (size_t)t * 128;
    for (int idx = tid; idx < NHEADS * 64; idx += 256) {
        int hh = idx >> 6, i = idx & 63;
        float cs = rp[i], sn = rp[64 + i];
        int d1 = hh * HDIM + i, d2 = d1 + 64;
        float q1 = sq[d1], q2 = sq[d2], k1 = sk[d1], k2 = sk[d2];
        size_t base = (size_t)t * HID;
        g_rq[base + d1] = q1 * cs - q2 * sn;
        g_rq[base + d2] = q2 * cs + q1 * sn;
        g_rk[base + d1] = k1 * cs - k2 * sn;
        g_rk[base + d2] = k2 * cs + k1 * sn;
    }
    __syncthreads();
    for (int d = tid; d < HID; d += 256) {
        float xq = sq[d] * qksc[2 * d]     + qkof[2 * d];
        float xk = sk[d] * qksc[2 * d + 1] + qkof[2 * d + 1];
        float a = siluf_fast(xq), b = siluf_fast(xk);
        sq[d] = a; sk[d] = b;
        int g = d >> 9;
        atomicAdd(&gsum[g],     a * a);
        atomicAdd(&gsum[4 + g], b * b);
        float sv = siluf_fast(vrow[d]);
        size_t o = ((size_t)g * S_LEN + t) * FD + (d & 511);
        g_fv[o] = sv;
        h_fv[o] = __float2half(sv);
    }
    __syncthreads();
    for (int d = tid; d < HID; d += 256) {
        int g = d >> 9;
        float nq = fmaxf(sqrtf(gsum[g]),     1e-12f);
        float nk = fmaxf(sqrtf(gsum[4 + g]), 1e-12f);
        size_t o = ((size_t)g * S_LEN + t) * FD + (d & 511);
        h_fq[o] = __float2half(sq[d] / nq);
        h_fk[o] = __float2half(sk[d] / nk);
    }
    if (tid < 12) {
        float z = g_lrraw[(size_t)t * 128 + tid] + lrb[tid] - 6.90725523731f;
        float sp = (z > 0.f) ? z + log1pf(expf(-z)) : log1pf(expf(z));
        g_lr[(size_t)t * 12 + tid] = sp;
    }
}

// ---------------- sliding-window attention (f32x2 packed math) ----------------
#define AR 132
#define ASM_FLOATS (3*32*AR + 32*36)    // 13824
__global__ void __launch_bounds__(256) attn_kernel()
{
    extern __shared__ float sh[];
    float* sQ = sh;
    float* sK = sh + 32 * AR;
    float* sV = sh + 64 * AR;
    float* sP = sh + 96 * AR;
    int head = blockIdx.y;
    int q0 = blockIdx.x * 32;
    int tid = threadIdx.x;
    int row = tid >> 3, sub = tid & 7;
    const float qs = 0.08838834764831845f;

    for (int i = tid; i < 32 * 32; i += 256) {
        int r = i >> 5, c4 = (i & 31) << 2;
        float4 v = *(const float4*)(g_rq + (size_t)(q0 + r) * HID + head * HDIM + c4);
        v.x *= qs; v.y *= qs; v.z *= qs; v.w *= qs;
        *(float4*)(sQ + r * AR + c4) = v;
    }

    uint64_t oacc2[8];
    #pragma unroll
    for (int j = 0; j < 8; j++) oacc2[j] = 0ull;
    float m = -1e30f, l = 0.f;
    int qpos = q0 + row;

    for (int it = 0; it < 9; it++) {
        int kb = q0 - 256 + it * 32;
        if (kb + 32 <= 0) continue;
        __syncthreads();
        for (int i = tid; i < 32 * 32; i += 256) {
            int r = i >> 5, c4 = (i & 31) << 2;
            int kpos = kb + r;
            float4 kv = make_float4(0.f,0.f,0.f,0.f), vv = kv;
            if (kpos >= 0) {
                kv = *(const float4*)(g_rk  + (size_t)kpos * HID  + head * HDIM + c4);
                vv = *(const float4*)(g_qkv + (size_t)kpos * QKV3 + 2 * HID + head * HDIM + c4);
            }
            *(float4*)(sK + r * AR + c4) = kv;
            *(float4*)(sV + r * AR + c4) = vv;
        }
        __syncthreads();
        uint64_t s2[4] = {0ull, 0ull, 0ull, 0ull};
        bool ok[4];
        #pragma unroll
        for (int j = 0; j < 4; j++) {
            int kpos = kb + sub + 8 * j;
            ok[j] = (kpos >= 0) && (kpos <= qpos) && (kpos >= qpos - 255);
        }
        const float4* qp = (const float4*)(sQ + row * AR);
        #pragma unroll 8
        for (int d4 = 0; d4 < 32; d4++) {
            float4 a = qp[d4];
            uint64_t a01 = pk2(a.x, a.y), a23 = pk2(a.z, a.w);
            #pragma unroll
            for (int j = 0; j < 4; j++) {
                float4 b = *(const float4*)(sK + (sub + 8 * j) * AR + d4 * 4);
                s2[j] = fma2(a01, pk2(b.x, b.y), s2[j]);
                s2[j] = fma2(a23, pk2(b.z, b.w), s2[j]);
            }
        }
        float s[4];
        #pragma unroll
        for (int j = 0; j < 4; j++) {
            float lo, hi;
            unpk2(lo, hi, s2[j]);
            s[j] = lo + hi;
        }
        float tmax = -1e30f;
        #pragma unroll
        for (int j = 0; j < 4; j++) { if (!ok[j]) s[j] = -1e30f; tmax = fmaxf(tmax, s[j]); }
        #pragma unroll
        for (int o = 4; o > 0; o >>= 1) tmax = fmaxf(tmax, __shfl_xor_sync(0xffffffffu, tmax, o, 8));
        float mnew = fmaxf(m, tmax);
        float scale = expf(m - mnew);
        float p[4], ps = 0.f;
        #pragma unroll
        for (int j = 0; j < 4; j++) { p[j] = ok[j] ? expf(s[j] - mnew) : 0.f; ps += p[j]; }
        #pragma unroll
        for (int o = 4; o > 0; o >>= 1) ps += __shfl_xor_sync(0xffffffffu, ps, o, 8);
        l = l * scale + ps;
        m = mnew;
        uint64_t sc2 = pk2(scale, scale);
        #pragma unroll
        for (int j = 0; j < 8; j++) oacc2[j] = mul2(oacc2[j], sc2);
        #pragma unroll
        for (int j = 0; j < 4; j++) sP[row * 36 + sub + 8 * j] = p[j];
        __syncwarp();
        #pragma unroll 4
        for (int k = 0; k < 32; k++) {
            uint64_t pkk = pk2(sP[row * 36 + k], sP[row * 36 + k]);
            #pragma unroll
            for (int jj = 0; jj < 4; jj++) {
                float4 v = *(const float4*)(sV + k * AR + sub * 4 + 32 * jj);
                oacc2[jj * 2]     = fma2(pkk, pk2(v.x, v.y), oacc2[jj * 2]);
                oacc2[jj * 2 + 1] = fma2(pkk, pk2(v.z, v.w), oacc2[jj * 2 + 1]);
            }
        }
    }
    float inv = 1.f / l;
    #pragma unroll
    for (int jj = 0; jj < 4; jj++) {
        float a0, a1, a2, a3;
        unpk2(a0, a1, oacc2[jj * 2]);
        unpk2(a2, a3, oacc2[jj * 2 + 1]);
        float4 v;
        v.x = a0 * inv; v.y = a1 * inv; v.z = a2 * inv; v.w = a3 * inv;
        *(float4*)(g_attn + (size_t)qpos * HID + head * HDIM + sub * 4 + 32 * jj) = v;
    }
}

// ---------------- TTT elementwise + transposes ----------------
__global__ void __launch_bounds__(256) ttt_elem_t(int c0)
{
    __shared__ float t0[32][33], t1[32][33], t2[32][33], t3[32][33], t4[32][33];
    int h = blockIdx.z;
    int cb = blockIdx.x * 32, db = blockIdx.y * 32;
    int x = threadIdx.x, y = threadIdx.y;
    size_t base  = (size_t)h * CHUNK * FD;
    size_t baseP = (size_t)h * CHUNK * 1024;
    #pragma unroll
    for (int i = 0; i < 4; i++) {
        int cy = y + i * 8;
        int c = cb + cy, d = db + x;
        size_t idx  = base  + (size_t)c * FD + d;
        size_t idxP = baseP + (size_t)c * 1024 + d;
        int t = c0 + c;
        float lr0 = g_lr[(size_t)t * 12 + h];
        float lr1 = g_lr[(size_t)t * 12 + 4 + h];
        float lr2 = g_lr[(size_t)t * 12 + 8 + h];
        float gq = g_pq[idxP], hmq = g_pq[idxP + 512];
        h_gq[idx] = __float2half(siluf(gq) * hmq);
        float gk = g_pk[idxP], hmk = g_pk[idxP + 512], dh = g_dhid[idx];
        float sg = 1.f / (1.f + expf(-gk));
        float silug = gk * sg;
        t0[cy][x] = dh * hmk * (sg * (1.f + gk * (1.f - sg))) * lr0;
        t1[cy][x] = dh * silug * lr2;
        t2[cy][x] = silug * hmk;
        t3[cy][x] = g_fv[((size_t)h * S_LEN + t) * FD + d] * lr1;
        t4[cy][x] = __half2float(h_fk[((size_t)h * S_LEN + t) * FD + d]);
    }
    __syncthreads();
    size_t tb = ((size_t)h * FD + db) * CHUNK + cb;
    #pragma unroll
    for (int i = 0; i < 4; i++) {
        int dy = y + i * 8;
        size_t o = tb + (size_t)dy * CHUNK + x;
        h_t0[o] = __float2half(t0[x][dy]);
        h_t1[o] = __float2half(t1[x][dy]);
        h_t2[o] = __float2half(t2[x][dy]);
        h_t3[o] = __float2half(t3[x][dy]);
        h_t4[o] = __float2half(t4[x][dy]);
    }
}

// ---------------- rms_norm(o_fast) + attn add -> fp16 x ----------------
__global__ void __launch_bounds__(256) normadd_kernel(const float* __restrict__ tnw)
{
    __shared__ float ss[4];
    int t = blockIdx.x, tid = threadIdx.x;
    if (tid < 4) ss[tid] = 0.f;
    __syncthreads();
    float v[8];
    #pragma unroll
    for (int i = 0; i < 8; i++) {
        int d = i * 256 + tid;
        int h = d >> 9;
        float x = g_ofst[((size_t)h * S_LEN + t) * FD + (d & 511)];
        v[i] = x;
        float s = x * x;
        #pragma unroll
        for (int o = 16; o > 0; o >>= 1) s += __shfl_xor_sync(0xffffffffu, s, o);
        if ((tid & 31) == 0) atomicAdd(&ss[h], s);
    }
    __syncthreads();
    #pragma unroll
    for (int i = 0; i < 8; i++) {
        int d = i * 256 + tid;
        int h = d >> 9;
        float rn = rsqrtf(ss[h] * (1.f / FD) + 1e-6f);
        h_x[(size_t)t * HID + d] =
            __float2half(g_attn[(size_t)t * HID + d] + v[i] * rn * tnw[d & 511]);
    }
}

// ---------------- host ----------------
template<typename T>
static T* symaddr(const void* s)
{
    void* p = nullptr;
    cudaGetSymbolAddress(&p, s);
    return (T*)p;
}

extern "C" void kernel_launch(void* const* d_in, const int* in_sizes, int n_in,
                              void* d_out, int out_size)
{
    const float* hs    = (const float*)d_in[0];
    const float* qkv_w = (const float*)d_in[1];
    const float* qnw   = (const float*)d_in[2];
    const float* knw   = (const float*)d_in[3];
    const float* qksc  = (const float*)d_in[4];
    const float* qkof  = (const float*)d_in[5];
    const float* lrw   = (const float*)d_in[6];
    const float* lrb   = (const float*)d_in[7];
    const float* w0    = (const float*)d_in[8];
    const float* w1    = (const float*)d_in[9];
    const float* w2    = (const float*)d_in[10];
    const float* tnw   = (const float*)d_in[11];
    const float* opw   = (const float*)d_in[12];
    float* out = (float*)d_out;

    float*  p_qkv  = symaddr<float>(g_qkv);
    float*  p_lrr  = symaddr<float>(g_lrraw);
    float*  p_ofst = symaddr<float>(g_ofst);
    float*  p_w0   = symaddr<float>(g_w0);
    float*  p_w1   = symaddr<float>(g_w1);
    float*  p_w2   = symaddr<float>(g_w2);
    float*  p_pq   = symaddr<float>(g_pq);
    float*  p_pk   = symaddr<float>(g_pk);
    float*  p_dhid = symaddr<float>(g_dhid);
    float*  p_part = symaddr<float>(g_part);
    __half* ph_hs  = symaddr<__half>(h_hs);
    __half* ph_qw  = symaddr<__half>(h_qkvw);
    __half* ph_lw  = symaddr<__half>(h_lrw);
    __half* ph_ow  = symaddr<__half>(h_opw);
    __half* ph_x   = symaddr<__half>(h_x);
    __half* ph_fq  = symaddr<__half>(h_fq);
    __half* ph_fk  = symaddr<__half>(h_fk);
    __half* ph_fv  = symaddr<__half>(h_fv);
    __half* ph_gq  = symaddr<__half>(h_gq);
    __half* ph_t0  = symaddr<__half>(h_t0);
    __half* ph_t1  = symaddr<__half>(h_t1);
    __half* ph_t2  = symaddr<__half>(h_t2);
    __half* ph_t3  = symaddr<__half>(h_t3);
    __half* ph_t4  = symaddr<__half>(h_t4);
    __half* ph_w02 = symaddr<__half>(h_w02);
    __half* ph_w1  = symaddr<__half>(h_w1);
    __half* ph_w1T = symaddr<__half>(h_w1T);

    const size_t WB = sizeof(float) * NFW * FDFD;
    const size_t WE = (size_t)NFW * FDFD;

    cudaFuncSetAttribute(mm_gen,   cudaFuncAttributeMaxDynamicSharedMemorySize, GSMEM);
    cudaFuncSetAttribute(mm_qkvlr, cudaFuncAttributeMaxDynamicSharedMemorySize, GSMEM);
    cudaFuncSetAttribute(mm_fwd2,  cudaFuncAttributeMaxDynamicSharedMemorySize, GSMEM);
    cudaFuncSetAttribute(mm_upd2,  cudaFuncAttributeMaxDynamicSharedMemorySize, GSMEM);
    cudaFuncSetAttribute(attn_kernel, cudaFuncAttributeMaxDynamicSharedMemorySize, ASM_FLOATS * 4);

    cudaMemcpyAsync(p_w0, w0, WB, cudaMemcpyDeviceToDevice, 0);
    cudaMemcpyAsync(p_w1, w1, WB, cudaMemcpyDeviceToDevice, 0);
    cudaMemcpyAsync(p_w2, w2, WB, cudaMemcpyDeviceToDevice, 0);

    rope_tab<<<(S_LEN*64)/256, 256>>>();                                          // 0
    f2h<<<(S_LEN*HID)/2048, 256>>>(hs, ph_hs, (size_t)S_LEN*HID);                 // 1
    f2h<<<(QKV3*HID)/2048, 256>>>(qkv_w, ph_qw, (size_t)QKV3*HID);                // 2
    lrw_cvt<<<(128*HID)/2048, 256>>>(lrw, ph_lw);                                 // 3
    mm_qkvlr<<<dim3(49, 64, 1), 256, GSMEM>>>(ph_hs, ph_qw, ph_lw, p_qkv, p_lrr); // 4
    preprocess_kernel<<<S_LEN, 256>>>(qnw, knw, qksc, qkof, lrb);                 // 5
    attn_kernel<<<dim3(S_LEN/32, NHEADS), 256, ASM_FLOATS * 4>>>();               // 6
    f2hw02<<<(NFW*1024*FD)/2048, 256>>>(p_w0, p_w2, ph_w02);                      // 7
    f2h<<<WE/2048, 256>>>(p_w1, ph_w1, WE);                                       // 8
    transpose_wh<<<dim3(16, 16, 4), dim3(32, 8)>>>(p_w1, ph_w1T);                 // 9
    f2h<<<(HID*HID)/2048, 256>>>(opw, ph_ow, (size_t)HID*HID);                    // 10

    // TTT scan (4 launches/chunk)
    for (int c = 0; c < 4; c++) {
        size_t co = (size_t)c * CHUNK * FD;
        int c0 = c * CHUNK;
        mm_fwd2<<<1280, 256, GSMEM>>>(ph_fq + co, ph_fk + co, ph_fv + co,
                                      ph_w02, ph_w1T, p_pq, p_pk, p_dhid);
        ttt_elem_t<<<dim3(CHUNK/32, FD/32, NFW), dim3(32, 8)>>>(c0);
        mm_upd2<<<1024, 256, GSMEM>>>(ph_t0, ph_t1, ph_t3, ph_t4, ph_t2,
                                      ph_gq, ph_w1, p_part, p_ofst + co);
        if (c < 3)
            wupdate<<<dim3(16, 16, 12), dim3(32, 8)>>>(
                p_w0, p_w1, p_w2, p_part, ph_w02, ph_w1, ph_w1T);
    }

    normadd_kernel<<<S_LEN, 256>>>(tnw);

    mm_gen<<<dim3(HID/128, S_LEN/128, 1), 256, GSMEM>>>(
        ph_x, ph_ow, out, HID, HID, HID, HID, 0, 0, 0);
}